// round 11
// baseline (speedup 1.0000x reference)
#include <cuda_runtime.h>
#include <cuda_bf16.h>
#include <cstdint>

// ---------------------------------------------------------------------------
// DGCNN segmentation. ALL GEMMs on tensor cores via mma.sync bf16x3 split
// precision (ldmatrix frags, cp.async.cg W streaming, 64-wide K chunks).
// Edges counting-sorted by dst. Register prefetch of next-chunk operands
// hides gather latency under the mma phase.
// ---------------------------------------------------------------------------

#define NMAX 30016
#define EMAX 480256
#define NBIN 30720   // 1024 * 30

__device__ float    g_AB[NMAX * 512];
__device__ unsigned g_agg[NMAX * 256];
__device__ float    g_hcat[NMAX * 448];
__device__ float    g_m1[NMAX * 512];
__device__ float    g_m2[NMAX * 256];
__device__ float    g_wc2[64 * 256];
__device__ float    g_wc3[128 * 512];
__device__ float    g_bc2[256];
__device__ float    g_bc3[512];
__device__ uint4    g_wh1[64 * 72 / 8],       g_wl1[64 * 72 / 8];
__device__ uint4    g_wh2[2 * 128 * 72 / 8],  g_wl2[2 * 128 * 72 / 8];
__device__ uint4    g_wh3[8 * 128 * 72 / 8],  g_wl3[8 * 128 * 72 / 8];
__device__ uint4    g_whn2[2304],  g_wln2[2304];
__device__ uint4    g_whn3[9216],  g_wln3[9216];
__device__ uint4    g_whm1[32256], g_wlm1[32256];
__device__ uint4    g_whm2[18432], g_wlm2[18432];
__device__ int      g_src[EMAX];
__device__ int      g_dst[EMAX];
__device__ int      g_srcS[EMAX];   // sorted by dst
__device__ int      g_dstS[EMAX];
__device__ int      g_cnt[NBIN];
__device__ int      g_c2[NBIN];
__device__ int      g_start[NBIN];

// ---- ordered-uint encoding for float max ------------------------------------
__device__ __forceinline__ unsigned f2ord(float f) {
    int i = __float_as_int(f);
    return (i >= 0) ? ((unsigned)i | 0x80000000u) : ~(unsigned)i;
}
__device__ __forceinline__ float ord2f(unsigned u) {
    int i = (u & 0x80000000u) ? (int)(u & 0x7fffffffu) : (int)(~u);
    return __int_as_float(i);
}

// ---- PTX helpers --------------------------------------------------------------
__device__ __forceinline__ uint32_t smem_u32(const void* p) {
    uint32_t a;
    asm("{ .reg .u64 t; cvta.to.shared.u64 t, %1; cvt.u32.u64 %0, t; }" : "=r"(a) : "l"(p));
    return a;
}
__device__ __forceinline__ void mma_bf16(float* d, const uint32_t* a,
                                         uint32_t b0, uint32_t b1) {
    asm volatile(
        "mma.sync.aligned.m16n8k16.row.col.f32.bf16.bf16.f32 "
        "{%0,%1,%2,%3},{%4,%5,%6,%7},{%8,%9},{%0,%1,%2,%3};"
        : "+f"(d[0]), "+f"(d[1]), "+f"(d[2]), "+f"(d[3])
        : "r"(a[0]), "r"(a[1]), "r"(a[2]), "r"(a[3]), "r"(b0), "r"(b1));
}
__device__ __forceinline__ void ldsm_x4(uint32_t* r, uint32_t addr) {
    asm volatile("ldmatrix.sync.aligned.m8n8.x4.shared.b16 {%0,%1,%2,%3},[%4];"
                 : "=r"(r[0]), "=r"(r[1]), "=r"(r[2]), "=r"(r[3]) : "r"(addr));
}
__device__ __forceinline__ void cp16(uint32_t s, const void* g) {
    asm volatile("cp.async.cg.shared.global [%0],[%1],16;" :: "r"(s), "l"(g));
}
__device__ __forceinline__ void split2(float m0, float m1, uint32_t& hi2, uint32_t& lo2) {
    asm("cvt.rn.bf16x2.f32 %0, %1, %2;" : "=r"(hi2) : "f"(m1), "f"(m0));
    float h0 = __uint_as_float(hi2 << 16);
    float h1 = __uint_as_float(hi2 & 0xffff0000u);
    float l0 = m0 - h0, l1 = m1 - h1;
    asm("cvt.rn.bf16x2.f32 %0, %1, %2;" : "=r"(lo2) : "f"(l1), "f"(l0));
}

// ---- edge index convert (+ zero sort bins) ------------------------------------
__global__ void convert_idx_kernel(const unsigned* __restrict__ raw, int E) {
    int n = (E < 256) ? E : 256;
    int is64 = 1;
    for (int i = 0; i < n; i++)
        if (raw[2 * i + 1] != 0u) { is64 = 0; break; }
    int i = blockIdx.x * blockDim.x + threadIdx.x;
    if (i < NBIN) { g_cnt[i] = 0; g_c2[i] = 0; }
    if (i >= E) return;
    if (is64) {
        const long long* p = (const long long*)raw;
        g_src[i] = (int)p[i];
        g_dst[i] = (int)p[E + i];
    } else {
        const int* p = (const int*)raw;
        g_src[i] = p[i];
        g_dst[i] = p[E + i];
    }
}
__global__ void hist_kernel(int E) {
    int i = blockIdx.x * blockDim.x + threadIdx.x;
    if (i < E) atomicAdd(&g_cnt[g_dst[i]], 1);
}
__global__ void scan_kernel() {   // 1 block, 1024 threads, 30 bins each
    __shared__ int part[1024];
    int t = threadIdx.x;
    int base = t * 30;
    int s = 0;
#pragma unroll
    for (int j = 0; j < 30; j++) s += g_cnt[base + j];
    part[t] = s;
    __syncthreads();
    for (int off = 1; off < 1024; off <<= 1) {
        int v = (t >= off) ? part[t - off] : 0;
        __syncthreads();
        part[t] += v;
        __syncthreads();
    }
    int run = part[t] - s;
#pragma unroll
    for (int j = 0; j < 30; j++) {
        g_start[base + j] = run;
        run += g_cnt[base + j];
    }
}
__global__ void scatter_kernel(int E) {
    int i = blockIdx.x * blockDim.x + threadIdx.x;
    if (i >= E) return;
    int d = g_dst[i];
    int pos = g_start[d] + atomicAdd(&g_c2[d], 1);
    g_srcS[pos] = g_src[i];
    g_dstS[pos] = d;
}

// ---- weight prep: wc = [Wtop - Wbot | Wbot], bc = [b | 0] ---------------------
__global__ void prep_kernel(const float* __restrict__ w, const float* __restrict__ b,
                            float* __restrict__ wc, float* __restrict__ bc,
                            int C, int H) {
    int stride = gridDim.x * blockDim.x;
    int i0 = blockIdx.x * blockDim.x + threadIdx.x;
    for (int t = i0; t < C * H; t += stride) {
        int k = t / H, j = t % H;
        float wd = w[(k + C) * H + j];
        wc[k * 2 * H + j]     = w[k * H + j] - wd;
        wc[k * 2 * H + H + j] = wd;
    }
    for (int t = i0; t < H; t += stride) { bc[t] = b[t]; bc[H + t] = 0.f; }
}

// ---- weight prep: W^T bf16 hi/lo chunked [(tile*NCH+c)*BN + n][72] ------------
__global__ void prep_wb_kernel(const float* __restrict__ W,
                               uint4* __restrict__ Whi, uint4* __restrict__ Wlo,
                               int H, int COUT, int BN) {
    int i = blockIdx.x * blockDim.x + threadIdx.x;
    if (i >= H * COUT) return;
    int k = i / COUT, n = i % COUT;
    float w = W[i];
    __nv_bfloat16 hb = __float2bfloat16(w);
    __nv_bfloat16 lb = __float2bfloat16(w - __bfloat162float(hb));
    int NCH = H >> 6;
    int tile = n / BN, nl = n % BN, c = k >> 6, kl = k & 63;
    size_t off = ((size_t)(tile * NCH + c) * BN + nl) * 72 + kl;
    ((unsigned short*)Whi)[off] = __bfloat16_as_ushort(hb);
    ((unsigned short*)Wlo)[off] = __bfloat16_as_ushort(lb);
}

// ---- layer-1 node precompute fused with wc1 prep + agg clear ------------------
__global__ void node1_fused_kernel(const float* __restrict__ x,
                                   const float* __restrict__ w1a,
                                   const float* __restrict__ b1a,
                                   float* __restrict__ AB,
                                   unsigned* __restrict__ agg, int M) {
    int idx = blockIdx.x * blockDim.x + threadIdx.x;
    if (idx >= M * 128) return;
    if (idx < M * 64) agg[idx] = 0u;
    int n = idx >> 7, j = idx & 127;
    float wk0, wk1, wk2, bb;
    if (j < 64) {
        wk0 = w1a[0 * 64 + j] - w1a[3 * 64 + j];
        wk1 = w1a[1 * 64 + j] - w1a[4 * 64 + j];
        wk2 = w1a[2 * 64 + j] - w1a[5 * 64 + j];
        bb  = b1a[j];
    } else {
        int jj = j - 64;
        wk0 = w1a[3 * 64 + jj];
        wk1 = w1a[4 * 64 + jj];
        wk2 = w1a[5 * 64 + jj];
        bb  = 0.f;
    }
    float x0 = x[n * 3 + 0], x1 = x[n * 3 + 1], x2 = x[n * 3 + 2];
    AB[idx] = fmaf(x0, wk0, fmaf(x1, wk1, fmaf(x2, wk2, bb)));
}

// ---- dense bf16x3 mma GEMM: C = act(A[M,K] @ W[K,N] + bias) -------------------
// Full register prefetch of the next A chunk overlaps gather latency with mma.
template <int K, int BN, bool RELU>
__global__ void __launch_bounds__(256, 2)
dense_mma_kernel(const float* __restrict__ A, int lda,
                 const uint4* __restrict__ Whi_g, const uint4* __restrict__ Wlo_g,
                 const float* __restrict__ bias,
                 float* __restrict__ C, int ldc, int M) {
    constexpr int NCH = K / 64;
    constexpr int NA  = BN / 16;
    constexpr int WSZ = BN * 144;
    constexpr int ASZ = 128 * 144;
    constexpr int OA  = 2 * WSZ;
    constexpr int WCNT = BN * 9;

    extern __shared__ char sm[];
    const uint32_t smb = smem_u32(sm);

    const int tid = threadIdx.x;
    const int wid = tid >> 5, lane = tid & 31;
    const int g = lane >> 2, tig = lane & 3;
    const int bm = blockIdx.x * 128;
    const int bn = blockIdx.y * BN;

    const int r  = tid >> 1;
    const int hf = tid & 1;
    const bool rv = (bm + r) < M;
    const float* Arow = A + (size_t)(bm + r) * lda + hf * 32;

    const int wm = wid >> 1, wn = wid & 1;
    const int m0 = wm * 32, n0 = wn * (BN / 2);

    const int lr = lane & 7;
    const uint32_t a_off =
        (uint32_t)(m0 + lr + ((lane >> 3) & 1) * 8) * 144u + (uint32_t)(lane >> 4) * 16u;
    const uint32_t w_off =
        (uint32_t)(n0 + lr + ((lane >> 4) & 1) * 8) * 144u + (uint32_t)((lane >> 3) & 1) * 16u;

    const uint32_t WhU = smb;
    const uint32_t WlU = WhU + WSZ;
    const uint32_t AhU = smb + OA;
    const uint32_t AlU = AhU + ASZ;
    char* Ah = sm + OA;
    char* Al = sm + OA + ASZ;

    float acc[2][NA][4];
#pragma unroll
    for (int ma = 0; ma < 2; ma++)
#pragma unroll
        for (int na = 0; na < NA; na++)
#pragma unroll
            for (int q = 0; q < 4; q++) acc[ma][na][q] = 0.f;

    // prefetch chunk 0 A operands into registers
    float4 preA[8];
    if (rv) {
#pragma unroll
        for (int q = 0; q < 8; q++) preA[q] = ((const float4*)Arow)[q];
    }

    for (int c = 0; c < NCH; c++) {
        if (c) __syncthreads();
        {
            const char* shp = (const char*)(Whi_g + (size_t)(blockIdx.y * NCH + c) * WCNT);
            const char* slp = (const char*)(Wlo_g + (size_t)(blockIdx.y * NCH + c) * WCNT);
            for (int i = tid; i < WCNT; i += 256) {
                cp16(WhU + i * 16, shp + i * 16);
                cp16(WlU + i * 16, slp + i * 16);
            }
            asm volatile("cp.async.commit_group;" ::: "memory");
        }
        {
            float v[32];
            if (rv) {
#pragma unroll
                for (int q = 0; q < 8; q++) {
                    float4 a = preA[q];
                    v[q * 4 + 0] = a.x; v[q * 4 + 1] = a.y;
                    v[q * 4 + 2] = a.z; v[q * 4 + 3] = a.w;
                }
                if (c + 1 < NCH) {     // prefetch next chunk during this mma phase
                    const float4* An = (const float4*)(Arow + (c + 1) * 64);
#pragma unroll
                    for (int q = 0; q < 8; q++) preA[q] = An[q];
                }
            } else {
#pragma unroll
                for (int q = 0; q < 32; q++) v[q] = 0.f;
            }
            char* ah = Ah + r * 144 + hf * 64;
            char* al = Al + r * 144 + hf * 64;
#pragma unroll
            for (int q8 = 0; q8 < 4; q8++) {
                uint32_t uh[4], ul[4];
#pragma unroll
                for (int p = 0; p < 4; p++)
                    split2(v[q8 * 8 + p * 2], v[q8 * 8 + p * 2 + 1], uh[p], ul[p]);
                *(uint4*)(ah + q8 * 16) = make_uint4(uh[0], uh[1], uh[2], uh[3]);
                *(uint4*)(al + q8 * 16) = make_uint4(ul[0], ul[1], ul[2], ul[3]);
            }
        }
        asm volatile("cp.async.wait_group 0;" ::: "memory");
        __syncthreads();

#pragma unroll
        for (int kq = 0; kq < 4; kq++) {
            uint32_t ah[2][4], al[2][4];
#pragma unroll
            for (int ma = 0; ma < 2; ma++) {
                ldsm_x4(ah[ma], AhU + a_off + (uint32_t)(ma * 16 * 144 + kq * 32));
                ldsm_x4(al[ma], AlU + a_off + (uint32_t)(ma * 16 * 144 + kq * 32));
            }
#pragma unroll
            for (int n2 = 0; n2 < NA / 2; n2++) {
                uint32_t wh[4], wl[4];
                ldsm_x4(wh, WhU + w_off + (uint32_t)(n2 * 16 * 144 + kq * 32));
                ldsm_x4(wl, WlU + w_off + (uint32_t)(n2 * 16 * 144 + kq * 32));
#pragma unroll
                for (int j = 0; j < 2; j++) {
                    const int na = n2 * 2 + j;
                    mma_bf16(acc[0][na], ah[0], wh[2 * j], wh[2 * j + 1]);
                    mma_bf16(acc[1][na], ah[1], wh[2 * j], wh[2 * j + 1]);
                    mma_bf16(acc[0][na], al[0], wh[2 * j], wh[2 * j + 1]);
                    mma_bf16(acc[1][na], al[1], wh[2 * j], wh[2 * j + 1]);
                    mma_bf16(acc[0][na], ah[0], wl[2 * j], wl[2 * j + 1]);
                    mma_bf16(acc[1][na], ah[1], wl[2 * j], wl[2 * j + 1]);
                }
            }
        }
    }

#pragma unroll
    for (int ma = 0; ma < 2; ma++) {
#pragma unroll
        for (int rr = 0; rr < 2; rr++) {
            const int rg = bm + m0 + ma * 16 + g + rr * 8;
            if (rg >= M) continue;
            float* crow = C + (size_t)rg * ldc + bn;
#pragma unroll
            for (int na = 0; na < NA; na++) {
                const int j = n0 + na * 8 + 2 * tig;
                float v0 = acc[ma][na][rr * 2 + 0] + bias[bn + j];
                float v1 = acc[ma][na][rr * 2 + 1] + bias[bn + j + 1];
                if (RELU) { v0 = fmaxf(v0, 0.f); v1 = fmaxf(v1, 0.f); }
                *(float2*)(crow + j) = make_float2(v0, v1);
            }
        }
    }
}

// ---- mma.sync edge kernel: sorted edges, A+B register prefetch ----------------
template <int H, int BN, int MINB>
__global__ void __launch_bounds__(256, MINB)
edge_mma_kernel(const float* __restrict__ AB,
                const uint4* __restrict__ Whi_g, const uint4* __restrict__ Wlo_g,
                const float* __restrict__ bias,
                unsigned* __restrict__ agg, int E, int COUT) {
    constexpr int NCH = H / 64;
    constexpr int NA  = BN / 16;
    constexpr int WSZ = BN * 144;
    constexpr int ASZ = 128 * 144;
    constexpr int OW  = 1024;
    constexpr int OA  = OW + 2 * WSZ;
    constexpr int WCNT = BN * 9;

    extern __shared__ char sm[];
    const uint32_t smb = smem_u32(sm);
    int* sdst = (int*)sm;
    int* ssrc = (int*)(sm + 512);

    const int tid = threadIdx.x;
    const int wid = tid >> 5, lane = tid & 31;
    const int g = lane >> 2, tig = lane & 3;
    const int e0 = blockIdx.x * 128;
    const int bn = blockIdx.y * BN;

    if (tid < 128) { int e = e0 + tid; ssrc[tid] = (e < E) ? g_srcS[e] : 0; }
    else           { int e = e0 + tid - 128; sdst[tid - 128] = (e < E) ? g_dstS[e] : 0; }
    __syncthreads();

    const int r  = tid >> 1;
    const int hf = tid & 1;
    const float* Arow = AB + (size_t)sdst[r] * (2 * H) + hf * 32;
    const float* Brow = AB + (size_t)ssrc[r] * (2 * H) + H + hf * 32;

    const int wm = wid >> 1, wn = wid & 1;
    const int m0 = wm * 32, n0 = wn * (BN / 2);

    const int lr = lane & 7;
    const uint32_t a_off =
        (uint32_t)(m0 + lr + ((lane >> 3) & 1) * 8) * 144u + (uint32_t)(lane >> 4) * 16u;
    const uint32_t w_off =
        (uint32_t)(n0 + lr + ((lane >> 4) & 1) * 8) * 144u + (uint32_t)((lane >> 3) & 1) * 16u;

    const uint32_t WhU = smb + OW;
    const uint32_t WlU = WhU + WSZ;
    const uint32_t AhU = smb + OA;
    const uint32_t AlU = AhU + ASZ;
    char* Ah = sm + OA;
    char* Al = sm + OA + ASZ;

    float acc[2][NA][4];
#pragma unroll
    for (int ma = 0; ma < 2; ma++)
#pragma unroll
        for (int na = 0; na < NA; na++)
#pragma unroll
            for (int q = 0; q < 4; q++) acc[ma][na][q] = 0.f;

    // prefetch chunk-0 first halves of both gather operands
    float4 preA[4], preB[4];
#pragma unroll
    for (int q = 0; q < 4; q++) {
        preA[q] = ((const float4*)Arow)[q];
        preB[q] = ((const float4*)Brow)[q];
    }

    for (int c = 0; c < NCH; c++) {
        if (c) __syncthreads();
        {
            const char* shp = (const char*)(Whi_g + (size_t)(blockIdx.y * NCH + c) * WCNT);
            const char* slp = (const char*)(Wlo_g + (size_t)(blockIdx.y * NCH + c) * WCNT);
            for (int i = tid; i < WCNT; i += 256) {
                cp16(WhU + i * 16, shp + i * 16);
                cp16(WlU + i * 16, slp + i * 16);
            }
            asm volatile("cp.async.commit_group;" ::: "memory");
        }
        {
            const float4* Ap = (const float4*)(Arow + c * 64);
            const float4* Bp = (const float4*)(Brow + c * 64);
            float v[32];
#pragma unroll
            for (int q = 0; q < 4; q++) {          // first halves from prefetch regs
                float4 a = preA[q], b = preB[q];
                v[q * 4 + 0] = fmaxf(a.x + b.x, 0.f);
                v[q * 4 + 1] = fmaxf(a.y + b.y, 0.f);
                v[q * 4 + 2] = fmaxf(a.z + b.z, 0.f);
                v[q * 4 + 3] = fmaxf(a.w + b.w, 0.f);
            }
#pragma unroll
            for (int q = 4; q < 8; q++) {          // second halves direct
                float4 a = Ap[q], b = Bp[q];
                v[q * 4 + 0] = fmaxf(a.x + b.x, 0.f);
                v[q * 4 + 1] = fmaxf(a.y + b.y, 0.f);
                v[q * 4 + 2] = fmaxf(a.z + b.z, 0.f);
                v[q * 4 + 3] = fmaxf(a.w + b.w, 0.f);
            }
            if (c + 1 < NCH) {                     // prefetch next chunk first halves
                const float4* An = (const float4*)(Arow + (c + 1) * 64);
                const float4* Bn = (const float4*)(Brow + (c + 1) * 64);
#pragma unroll
                for (int q = 0; q < 4; q++) { preA[q] = An[q]; preB[q] = Bn[q]; }
            }
            char* ah = Ah + r * 144 + hf * 64;
            char* al = Al + r * 144 + hf * 64;
#pragma unroll
            for (int q8 = 0; q8 < 4; q8++) {
                uint32_t uh[4], ul[4];
#pragma unroll
                for (int p = 0; p < 4; p++)
                    split2(v[q8 * 8 + p * 2], v[q8 * 8 + p * 2 + 1], uh[p], ul[p]);
                *(uint4*)(ah + q8 * 16) = make_uint4(uh[0], uh[1], uh[2], uh[3]);
                *(uint4*)(al + q8 * 16) = make_uint4(ul[0], ul[1], ul[2], ul[3]);
            }
        }
        asm volatile("cp.async.wait_group 0;" ::: "memory");
        __syncthreads();

#pragma unroll
        for (int kq = 0; kq < 4; kq++) {
            uint32_t ah[2][4], al[2][4];
#pragma unroll
            for (int ma = 0; ma < 2; ma++) {
                ldsm_x4(ah[ma], AhU + a_off + (uint32_t)(ma * 16 * 144 + kq * 32));
                ldsm_x4(al[ma], AlU + a_off + (uint32_t)(ma * 16 * 144 + kq * 32));
            }
#pragma unroll
            for (int n2 = 0; n2 < NA / 2; n2++) {
                uint32_t wh[4], wl[4];
                ldsm_x4(wh, WhU + w_off + (uint32_t)(n2 * 16 * 144 + kq * 32));
                ldsm_x4(wl, WlU + w_off + (uint32_t)(n2 * 16 * 144 + kq * 32));
#pragma unroll
                for (int j = 0; j < 2; j++) {
                    const int na = n2 * 2 + j;
                    mma_bf16(acc[0][na], ah[0], wh[2 * j], wh[2 * j + 1]);
                    mma_bf16(acc[1][na], ah[1], wh[2 * j], wh[2 * j + 1]);
                    mma_bf16(acc[0][na], al[0], wh[2 * j], wh[2 * j + 1]);
                    mma_bf16(acc[1][na], al[1], wh[2 * j], wh[2 * j + 1]);
                    mma_bf16(acc[0][na], ah[0], wl[2 * j], wl[2 * j + 1]);
                    mma_bf16(acc[1][na], ah[1], wl[2 * j], wl[2 * j + 1]);
                }
            }
        }
    }

    // ---- epilogue: bias + stale-safe guard + atomicMax ----
#pragma unroll
    for (int ma = 0; ma < 2; ma++) {
#pragma unroll
        for (int rr = 0; rr < 2; rr++) {
            const int rloc = m0 + ma * 16 + g + rr * 8;
            if (e0 + rloc >= E) continue;
            const int d = sdst[rloc];
            unsigned* arow = agg + (size_t)d * COUT + bn;
#pragma unroll
            for (int na = 0; na < NA; na++) {
                const int j = n0 + na * 8 + 2 * tig;
                float v0 = acc[ma][na][rr * 2 + 0] + bias[bn + j];
                float v1 = acc[ma][na][rr * 2 + 1] + bias[bn + j + 1];
                unsigned k0 = f2ord(v0);
                unsigned k1 = f2ord(v1);
                uint2 cur = *(const uint2*)(arow + j);
                if (k0 > cur.x) atomicMax(arow + j, k0);
                if (k1 > cur.y) atomicMax(arow + j + 1, k1);
            }
        }
    }
}

// ---- decode agg -> float, optionally clearing agg for the next layer ----------
__global__ void decode_clear_kernel(const unsigned* __restrict__ agg,
                                    float* __restrict__ dsth, int total, int C, int ldc,
                                    unsigned* __restrict__ clr, int clrN) {
    int i = blockIdx.x * blockDim.x + threadIdx.x;
    if (i < total) {
        int n = i / C, c = i % C;
        unsigned u = agg[i];
        dsth[(size_t)n * ldc + c] = (u == 0u) ? 0.f : ord2f(u);
    }
    if (i < clrN) clr[i] = 0u;
}

// ---- final 256 -> 4 linear ------------------------------------------------------
__global__ void mlp3_kernel(const float* __restrict__ A, const float* __restrict__ W,
                            const float* __restrict__ b, float* __restrict__ out, int M) {
    int gw = (blockIdx.x * blockDim.x + threadIdx.x) >> 5;
    int lane = threadIdx.x & 31;
    if (gw >= M) return;
    const float* a = A + (size_t)gw * 256;
    float acc0 = 0.f, acc1 = 0.f, acc2 = 0.f, acc3 = 0.f;
    for (int k = lane; k < 256; k += 32) {
        float av = a[k];
        const float* wr = W + k * 4;
        acc0 = fmaf(av, wr[0], acc0);
        acc1 = fmaf(av, wr[1], acc1);
        acc2 = fmaf(av, wr[2], acc2);
        acc3 = fmaf(av, wr[3], acc3);
    }
#pragma unroll
    for (int off = 16; off > 0; off >>= 1) {
        acc0 += __shfl_down_sync(0xffffffffu, acc0, off);
        acc1 += __shfl_down_sync(0xffffffffu, acc1, off);
        acc2 += __shfl_down_sync(0xffffffffu, acc2, off);
        acc3 += __shfl_down_sync(0xffffffffu, acc3, off);
    }
    if (lane == 0) {
        out[gw * 4 + 0] = acc0 + b[0];
        out[gw * 4 + 1] = acc1 + b[1];
        out[gw * 4 + 2] = acc2 + b[2];
        out[gw * 4 + 3] = acc3 + b[3];
    }
}

// ---------------------------------------------------------------------------
extern "C" void kernel_launch(void* const* d_in, const int* in_sizes, int n_in,
                              void* d_out, int out_size) {
    const float* x   = (const float*)d_in[0];
    const void*  ei  = d_in[1];
    const float* w1a = (const float*)d_in[3];
    const float* b1a = (const float*)d_in[4];
    const float* w1b = (const float*)d_in[5];
    const float* b1b = (const float*)d_in[6];
    const float* w2a = (const float*)d_in[7];
    const float* b2a = (const float*)d_in[8];
    const float* w2b = (const float*)d_in[9];
    const float* b2b = (const float*)d_in[10];
    const float* w3a = (const float*)d_in[11];
    const float* b3a = (const float*)d_in[12];
    const float* w3b = (const float*)d_in[13];
    const float* b3b = (const float*)d_in[14];
    const float* wm1 = (const float*)d_in[15];
    const float* bm1 = (const float*)d_in[16];
    const float* wm2 = (const float*)d_in[17];
    const float* bm2 = (const float*)d_in[18];
    const float* wm3 = (const float*)d_in[19];
    const float* bm3 = (const float*)d_in[20];

    const int Nn = in_sizes[0] / 3;
    const int E  = in_sizes[1] / 2;
    float* out = (float*)d_out;

    float *AB, *hcat, *m1, *m2, *wc2, *wc3, *bc2, *bc3;
    unsigned* agg;
    uint4 *wh1, *wl1, *wh2, *wl2, *wh3, *wl3;
    uint4 *whn2, *wln2, *whn3, *wln3, *whm1, *wlm1, *whm2, *wlm2;
    cudaGetSymbolAddress((void**)&AB,   g_AB);
    cudaGetSymbolAddress((void**)&agg,  g_agg);
    cudaGetSymbolAddress((void**)&hcat, g_hcat);
    cudaGetSymbolAddress((void**)&m1,   g_m1);
    cudaGetSymbolAddress((void**)&m2,   g_m2);
    cudaGetSymbolAddress((void**)&wc2,  g_wc2);
    cudaGetSymbolAddress((void**)&wc3,  g_wc3);
    cudaGetSymbolAddress((void**)&bc2,  g_bc2);
    cudaGetSymbolAddress((void**)&bc3,  g_bc3);
    cudaGetSymbolAddress((void**)&wh1,  g_wh1);
    cudaGetSymbolAddress((void**)&wl1,  g_wl1);
    cudaGetSymbolAddress((void**)&wh2,  g_wh2);
    cudaGetSymbolAddress((void**)&wl2,  g_wl2);
    cudaGetSymbolAddress((void**)&wh3,  g_wh3);
    cudaGetSymbolAddress((void**)&wl3,  g_wl3);
    cudaGetSymbolAddress((void**)&whn2, g_whn2);
    cudaGetSymbolAddress((void**)&wln2, g_wln2);
    cudaGetSymbolAddress((void**)&whn3, g_whn3);
    cudaGetSymbolAddress((void**)&wln3, g_wln3);
    cudaGetSymbolAddress((void**)&whm1, g_whm1);
    cudaGetSymbolAddress((void**)&wlm1, g_wlm1);
    cudaGetSymbolAddress((void**)&whm2, g_whm2);
    cudaGetSymbolAddress((void**)&wlm2, g_wlm2);

    const int SM1 = 1024 + 2 * (64  * 144) + 2 * 18432;  // 56320
    const int SM2 = 1024 + 2 * (128 * 144) + 2 * 18432;  // 74752
    const int SMD = 2 * (128 * 144) + 2 * 18432;         // 73728
    cudaFuncSetAttribute(edge_mma_kernel<64, 64, 3>,   cudaFuncAttributeMaxDynamicSharedMemorySize, SM1);
    cudaFuncSetAttribute(edge_mma_kernel<128, 128, 2>, cudaFuncAttributeMaxDynamicSharedMemorySize, SM2);
    cudaFuncSetAttribute(edge_mma_kernel<256, 128, 2>, cudaFuncAttributeMaxDynamicSharedMemorySize, SM2);
    cudaFuncSetAttribute(dense_mma_kernel<64,  128, false>, cudaFuncAttributeMaxDynamicSharedMemorySize, SMD);
    cudaFuncSetAttribute(dense_mma_kernel<128, 128, false>, cudaFuncAttributeMaxDynamicSharedMemorySize, SMD);
    cudaFuncSetAttribute(dense_mma_kernel<448, 128, true>,  cudaFuncAttributeMaxDynamicSharedMemorySize, SMD);
    cudaFuncSetAttribute(dense_mma_kernel<512, 128, true>,  cudaFuncAttributeMaxDynamicSharedMemorySize, SMD);

    const int TB = 256;
    dim3 blk(TB);
    const int gx  = (Nn + 127) / 128;
    const int egx = (E + 127) / 128;

    // ---- edge sort by dst (counting sort; segment-max is order-invariant) ----
    convert_idx_kernel<<<(E + TB - 1) / TB, blk>>>((const unsigned*)ei, E);
    hist_kernel<<<(E + TB - 1) / TB, blk>>>(E);
    scan_kernel<<<1, 1024>>>();
    scatter_kernel<<<(E + TB - 1) / TB, blk>>>(E);

    // ---- EdgeConv 1: 3 -> 64 ----
    prep_wb_kernel<<<(64 * 64 + TB - 1) / TB, blk>>>(w1b, wh1, wl1, 64, 64, 64);
    node1_fused_kernel<<<(Nn * 128 + TB - 1) / TB, blk>>>(x, w1a, b1a, AB, agg, Nn);
    edge_mma_kernel<64, 64, 3><<<dim3(egx, 1), blk, SM1>>>(AB, wh1, wl1, b1b, agg, E, 64);

    // ---- EdgeConv 2: 64 -> 128 ----
    prep_kernel<<<64, blk>>>(w2a, b2a, wc2, bc2, 64, 128);
    prep_wb_kernel<<<(64 * 256 + TB - 1) / TB, blk>>>(wc2, whn2, wln2, 64, 256, 128);
    prep_wb_kernel<<<(128 * 128 + TB - 1) / TB, blk>>>(w2b, wh2, wl2, 128, 128, 128);
    decode_clear_kernel<<<(Nn * 64 + TB - 1) / TB, blk>>>(agg, hcat + 0, Nn * 64, 64, 448, nullptr, 0);
    dense_mma_kernel<64, 128, false><<<dim3(gx, 2), blk, SMD>>>(hcat, 448, whn2, wln2, bc2, AB, 256, Nn);
    decode_clear_kernel<<<(Nn * 128 + TB - 1) / TB, blk>>>(agg, hcat, 0, 64, 448, agg, Nn * 128);
    edge_mma_kernel<128, 128, 2><<<dim3(egx, 1), blk, SM2>>>(AB, wh2, wl2, b2b, agg, E, 128);

    // ---- EdgeConv 3: 128 -> 256 ----
    prep_kernel<<<256, blk>>>(w3a, b3a, wc3, bc3, 128, 256);
    prep_wb_kernel<<<(128 * 512 + TB - 1) / TB, blk>>>(wc3, whn3, wln3, 128, 512, 128);
    prep_wb_kernel<<<(256 * 256 + TB - 1) / TB, blk>>>(w3b, wh3, wl3, 256, 256, 128);
    decode_clear_kernel<<<(Nn * 128 + TB - 1) / TB, blk>>>(agg, hcat + 64, Nn * 128, 128, 448, nullptr, 0);
    dense_mma_kernel<128, 128, false><<<dim3(gx, 4), blk, SMD>>>(hcat + 64, 448, whn3, wln3, bc3, AB, 512, Nn);
    decode_clear_kernel<<<(Nn * 256 + TB - 1) / TB, blk>>>(agg, hcat, 0, 128, 448, agg, Nn * 256);
    edge_mma_kernel<256, 128, 2><<<dim3(egx, 2), blk, SM2>>>(AB, wh3, wl3, b3b, agg, E, 256);
    decode_clear_kernel<<<(Nn * 256 + TB - 1) / TB, blk>>>(agg, hcat + 192, Nn * 256, 256, 448, nullptr, 0);

    // ---- MLP head ----
    prep_wb_kernel<<<(448 * 512 + TB - 1) / TB, blk>>>(wm1, whm1, wlm1, 448, 512, 128);
    dense_mma_kernel<448, 128, true><<<dim3(gx, 4), blk, SMD>>>(hcat, 448, whm1, wlm1, bm1, m1, 512, Nn);
    prep_wb_kernel<<<(512 * 256 + TB - 1) / TB, blk>>>(wm2, whm2, wlm2, 512, 256, 128);
    dense_mma_kernel<512, 128, true><<<dim3(gx, 2), blk, SMD>>>(m1, 512, whm2, wlm2, bm2, m2, 256, Nn);
    mlp3_kernel<<<(Nn * 32 + TB - 1) / TB, blk>>>(m2, wm3, bm3, out, Nn);
}

// round 12
// speedup vs baseline: 1.0576x; 1.0576x over previous
#include <cuda_runtime.h>
#include <cuda_bf16.h>
#include <cstdint>

// ---------------------------------------------------------------------------
// DGCNN segmentation. ALL GEMMs on tensor cores via mma.sync bf16x3 split
// precision (ldmatrix frags, cp.async.cg W streaming, 64-wide K chunks).
// Edges counting-sorted by dst. Bias applied after segment-max (exact).
// ---------------------------------------------------------------------------

#define NMAX 30016
#define EMAX 480256
#define NBIN 30720   // 1024 * 30

__device__ float    g_AB[NMAX * 512];
__device__ unsigned g_agg[NMAX * 256];
__device__ float    g_hcat[NMAX * 448];
__device__ float    g_m1[NMAX * 512];
__device__ float    g_m2[NMAX * 256];
__device__ float    g_wc2[64 * 256];
__device__ float    g_wc3[128 * 512];
__device__ float    g_bc2[256];
__device__ float    g_bc3[512];
__device__ uint4    g_wh1[64 * 72 / 8],       g_wl1[64 * 72 / 8];
__device__ uint4    g_wh2[2 * 128 * 72 / 8],  g_wl2[2 * 128 * 72 / 8];
__device__ uint4    g_wh3[8 * 128 * 72 / 8],  g_wl3[8 * 128 * 72 / 8];
__device__ uint4    g_whn2[2304],  g_wln2[2304];
__device__ uint4    g_whn3[9216],  g_wln3[9216];
__device__ uint4    g_whm1[32256], g_wlm1[32256];
__device__ uint4    g_whm2[18432], g_wlm2[18432];
__device__ int      g_src[EMAX];
__device__ int      g_dst[EMAX];
__device__ int      g_srcS[EMAX];   // sorted by dst
__device__ int      g_dstS[EMAX];
__device__ int      g_cnt[NBIN];
__device__ int      g_c2[NBIN];
__device__ int      g_start[NBIN];

// ---- ordered-uint encoding for float max ------------------------------------
__device__ __forceinline__ unsigned f2ord(float f) {
    int i = __float_as_int(f);
    return (i >= 0) ? ((unsigned)i | 0x80000000u) : ~(unsigned)i;
}
__device__ __forceinline__ float ord2f(unsigned u) {
    int i = (u & 0x80000000u) ? (int)(u & 0x7fffffffu) : (int)(~u);
    return __int_as_float(i);
}

// ---- PTX helpers --------------------------------------------------------------
__device__ __forceinline__ uint32_t smem_u32(const void* p) {
    uint32_t a;
    asm("{ .reg .u64 t; cvta.to.shared.u64 t, %1; cvt.u32.u64 %0, t; }" : "=r"(a) : "l"(p));
    return a;
}
__device__ __forceinline__ void mma_bf16(float* d, const uint32_t* a,
                                         uint32_t b0, uint32_t b1) {
    asm volatile(
        "mma.sync.aligned.m16n8k16.row.col.f32.bf16.bf16.f32 "
        "{%0,%1,%2,%3},{%4,%5,%6,%7},{%8,%9},{%0,%1,%2,%3};"
        : "+f"(d[0]), "+f"(d[1]), "+f"(d[2]), "+f"(d[3])
        : "r"(a[0]), "r"(a[1]), "r"(a[2]), "r"(a[3]), "r"(b0), "r"(b1));
}
__device__ __forceinline__ void ldsm_x4(uint32_t* r, uint32_t addr) {
    asm volatile("ldmatrix.sync.aligned.m8n8.x4.shared.b16 {%0,%1,%2,%3},[%4];"
                 : "=r"(r[0]), "=r"(r[1]), "=r"(r[2]), "=r"(r[3]) : "r"(addr));
}
__device__ __forceinline__ void cp16(uint32_t s, const void* g) {
    asm volatile("cp.async.cg.shared.global [%0],[%1],16;" :: "r"(s), "l"(g));
}
__device__ __forceinline__ void split2(float m0, float m1, uint32_t& hi2, uint32_t& lo2) {
    asm("cvt.rn.bf16x2.f32 %0, %1, %2;" : "=r"(hi2) : "f"(m1), "f"(m0));
    float h0 = __uint_as_float(hi2 << 16);
    float h1 = __uint_as_float(hi2 & 0xffff0000u);
    float l0 = m0 - h0, l1 = m1 - h1;
    asm("cvt.rn.bf16x2.f32 %0, %1, %2;" : "=r"(lo2) : "f"(l1), "f"(l0));
}

// ---- edge index convert (+ zero sort bins) ------------------------------------
__global__ void convert_idx_kernel(const unsigned* __restrict__ raw, int E) {
    int n = (E < 256) ? E : 256;
    int is64 = 1;
    for (int i = 0; i < n; i++)
        if (raw[2 * i + 1] != 0u) { is64 = 0; break; }
    int i = blockIdx.x * blockDim.x + threadIdx.x;
    if (i < NBIN) { g_cnt[i] = 0; g_c2[i] = 0; }
    if (i >= E) return;
    if (is64) {
        const long long* p = (const long long*)raw;
        g_src[i] = (int)p[i];
        g_dst[i] = (int)p[E + i];
    } else {
        const int* p = (const int*)raw;
        g_src[i] = p[i];
        g_dst[i] = p[E + i];
    }
}
__global__ void hist_kernel(int E) {
    int i = blockIdx.x * blockDim.x + threadIdx.x;
    if (i < E) atomicAdd(&g_cnt[g_dst[i]], 1);
}
__global__ void scan_kernel() {   // 1 block, 1024 threads, 30 bins each
    __shared__ int part[1024];
    int t = threadIdx.x;
    int base = t * 30;
    int s = 0;
#pragma unroll
    for (int j = 0; j < 30; j++) s += g_cnt[base + j];
    part[t] = s;
    __syncthreads();
    for (int off = 1; off < 1024; off <<= 1) {
        int v = (t >= off) ? part[t - off] : 0;
        __syncthreads();
        part[t] += v;
        __syncthreads();
    }
    int run = part[t] - s;
#pragma unroll
    for (int j = 0; j < 30; j++) {
        g_start[base + j] = run;
        run += g_cnt[base + j];
    }
}
__global__ void scatter_kernel(int E) {
    int i = blockIdx.x * blockDim.x + threadIdx.x;
    if (i >= E) return;
    int d = g_dst[i];
    int pos = g_start[d] + atomicAdd(&g_c2[d], 1);
    g_srcS[pos] = g_src[i];
    g_dstS[pos] = d;
}

// ---- weight prep: wc = [Wtop - Wbot | Wbot], bc = [b | 0] ---------------------
__global__ void prep_kernel(const float* __restrict__ w, const float* __restrict__ b,
                            float* __restrict__ wc, float* __restrict__ bc,
                            int C, int H) {
    int stride = gridDim.x * blockDim.x;
    int i0 = blockIdx.x * blockDim.x + threadIdx.x;
    for (int t = i0; t < C * H; t += stride) {
        int k = t / H, j = t % H;
        float wd = w[(k + C) * H + j];
        wc[k * 2 * H + j]     = w[k * H + j] - wd;
        wc[k * 2 * H + H + j] = wd;
    }
    for (int t = i0; t < H; t += stride) { bc[t] = b[t]; bc[H + t] = 0.f; }
}

// ---- weight prep: W^T bf16 hi/lo chunked [(tile*NCH+c)*BN + n][72] ------------
__global__ void prep_wb_kernel(const float* __restrict__ W,
                               uint4* __restrict__ Whi, uint4* __restrict__ Wlo,
                               int H, int COUT, int BN) {
    int i = blockIdx.x * blockDim.x + threadIdx.x;
    if (i >= H * COUT) return;
    int k = i / COUT, n = i % COUT;
    float w = W[i];
    __nv_bfloat16 hb = __float2bfloat16(w);
    __nv_bfloat16 lb = __float2bfloat16(w - __bfloat162float(hb));
    int NCH = H >> 6;
    int tile = n / BN, nl = n % BN, c = k >> 6, kl = k & 63;
    size_t off = ((size_t)(tile * NCH + c) * BN + nl) * 72 + kl;
    ((unsigned short*)Whi)[off] = __bfloat16_as_ushort(hb);
    ((unsigned short*)Wlo)[off] = __bfloat16_as_ushort(lb);
}

// ---- layer-1 node precompute fused with wc1 prep + agg clear ------------------
__global__ void node1_fused_kernel(const float* __restrict__ x,
                                   const float* __restrict__ w1a,
                                   const float* __restrict__ b1a,
                                   float* __restrict__ AB,
                                   unsigned* __restrict__ agg, int M) {
    int idx = blockIdx.x * blockDim.x + threadIdx.x;
    if (idx >= M * 128) return;
    if (idx < M * 64) agg[idx] = 0u;
    int n = idx >> 7, j = idx & 127;
    float wk0, wk1, wk2, bb;
    if (j < 64) {
        wk0 = w1a[0 * 64 + j] - w1a[3 * 64 + j];
        wk1 = w1a[1 * 64 + j] - w1a[4 * 64 + j];
        wk2 = w1a[2 * 64 + j] - w1a[5 * 64 + j];
        bb  = b1a[j];
    } else {
        int jj = j - 64;
        wk0 = w1a[3 * 64 + jj];
        wk1 = w1a[4 * 64 + jj];
        wk2 = w1a[5 * 64 + jj];
        bb  = 0.f;
    }
    float x0 = x[n * 3 + 0], x1 = x[n * 3 + 1], x2 = x[n * 3 + 2];
    AB[idx] = fmaf(x0, wk0, fmaf(x1, wk1, fmaf(x2, wk2, bb)));
}

// ---- dense bf16x3 mma GEMM: C = act(A[M,K] @ W[K,N] + bias) -------------------
template <int K, int BN, bool RELU>
__global__ void __launch_bounds__(256, 2)
dense_mma_kernel(const float* __restrict__ A, int lda,
                 const uint4* __restrict__ Whi_g, const uint4* __restrict__ Wlo_g,
                 const float* __restrict__ bias,
                 float* __restrict__ C, int ldc, int M) {
    constexpr int NCH = K / 64;
    constexpr int NA  = BN / 16;
    constexpr int WSZ = BN * 144;
    constexpr int ASZ = 128 * 144;
    constexpr int OA  = 2 * WSZ;
    constexpr int WCNT = BN * 9;

    extern __shared__ char sm[];
    const uint32_t smb = smem_u32(sm);

    const int tid = threadIdx.x;
    const int wid = tid >> 5, lane = tid & 31;
    const int g = lane >> 2, tig = lane & 3;
    const int bm = blockIdx.x * 128;
    const int bn = blockIdx.y * BN;

    const int r  = tid >> 1;
    const int hf = tid & 1;
    const bool rv = (bm + r) < M;
    const float* Arow = A + (size_t)(bm + r) * lda + hf * 32;

    const int wm = wid >> 1, wn = wid & 1;
    const int m0 = wm * 32, n0 = wn * (BN / 2);

    const int lr = lane & 7;
    const uint32_t a_off =
        (uint32_t)(m0 + lr + ((lane >> 3) & 1) * 8) * 144u + (uint32_t)(lane >> 4) * 16u;
    const uint32_t w_off =
        (uint32_t)(n0 + lr + ((lane >> 4) & 1) * 8) * 144u + (uint32_t)((lane >> 3) & 1) * 16u;

    const uint32_t WhU = smb;
    const uint32_t WlU = WhU + WSZ;
    const uint32_t AhU = smb + OA;
    const uint32_t AlU = AhU + ASZ;
    char* Ah = sm + OA;
    char* Al = sm + OA + ASZ;

    float acc[2][NA][4];
#pragma unroll
    for (int ma = 0; ma < 2; ma++)
#pragma unroll
        for (int na = 0; na < NA; na++)
#pragma unroll
            for (int q = 0; q < 4; q++) acc[ma][na][q] = 0.f;

    for (int c = 0; c < NCH; c++) {
        if (c) __syncthreads();
        {
            const char* shp = (const char*)(Whi_g + (size_t)(blockIdx.y * NCH + c) * WCNT);
            const char* slp = (const char*)(Wlo_g + (size_t)(blockIdx.y * NCH + c) * WCNT);
            for (int i = tid; i < WCNT; i += 256) {
                cp16(WhU + i * 16, shp + i * 16);
                cp16(WlU + i * 16, slp + i * 16);
            }
            asm volatile("cp.async.commit_group;" ::: "memory");
        }
        {
            const float4* Ap = (const float4*)(Arow + c * 64);
            float v[32];
            if (rv) {
#pragma unroll
                for (int q = 0; q < 8; q++) {
                    float4 a = Ap[q];
                    v[q * 4 + 0] = a.x; v[q * 4 + 1] = a.y;
                    v[q * 4 + 2] = a.z; v[q * 4 + 3] = a.w;
                }
            } else {
#pragma unroll
                for (int q = 0; q < 32; q++) v[q] = 0.f;
            }
            char* ah = Ah + r * 144 + hf * 64;
            char* al = Al + r * 144 + hf * 64;
#pragma unroll
            for (int q8 = 0; q8 < 4; q8++) {
                uint32_t uh[4], ul[4];
#pragma unroll
                for (int p = 0; p < 4; p++)
                    split2(v[q8 * 8 + p * 2], v[q8 * 8 + p * 2 + 1], uh[p], ul[p]);
                *(uint4*)(ah + q8 * 16) = make_uint4(uh[0], uh[1], uh[2], uh[3]);
                *(uint4*)(al + q8 * 16) = make_uint4(ul[0], ul[1], ul[2], ul[3]);
            }
        }
        asm volatile("cp.async.wait_group 0;" ::: "memory");
        __syncthreads();

#pragma unroll
        for (int kq = 0; kq < 4; kq++) {
            uint32_t ah[2][4], al[2][4];
#pragma unroll
            for (int ma = 0; ma < 2; ma++) {
                ldsm_x4(ah[ma], AhU + a_off + (uint32_t)(ma * 16 * 144 + kq * 32));
                ldsm_x4(al[ma], AlU + a_off + (uint32_t)(ma * 16 * 144 + kq * 32));
            }
#pragma unroll
            for (int n2 = 0; n2 < NA / 2; n2++) {
                uint32_t wh[4], wl[4];
                ldsm_x4(wh, WhU + w_off + (uint32_t)(n2 * 16 * 144 + kq * 32));
                ldsm_x4(wl, WlU + w_off + (uint32_t)(n2 * 16 * 144 + kq * 32));
#pragma unroll
                for (int j = 0; j < 2; j++) {
                    const int na = n2 * 2 + j;
                    mma_bf16(acc[0][na], ah[0], wh[2 * j], wh[2 * j + 1]);
                    mma_bf16(acc[1][na], ah[1], wh[2 * j], wh[2 * j + 1]);
                    mma_bf16(acc[0][na], al[0], wh[2 * j], wh[2 * j + 1]);
                    mma_bf16(acc[1][na], al[1], wh[2 * j], wh[2 * j + 1]);
                    mma_bf16(acc[0][na], ah[0], wl[2 * j], wl[2 * j + 1]);
                    mma_bf16(acc[1][na], ah[1], wl[2 * j], wl[2 * j + 1]);
                }
            }
        }
    }

#pragma unroll
    for (int ma = 0; ma < 2; ma++) {
#pragma unroll
        for (int rr = 0; rr < 2; rr++) {
            const int rg = bm + m0 + ma * 16 + g + rr * 8;
            if (rg >= M) continue;
            float* crow = C + (size_t)rg * ldc + bn;
#pragma unroll
            for (int na = 0; na < NA; na++) {
                const int j = n0 + na * 8 + 2 * tig;
                float v0 = acc[ma][na][rr * 2 + 0] + bias[bn + j];
                float v1 = acc[ma][na][rr * 2 + 1] + bias[bn + j + 1];
                if (RELU) { v0 = fmaxf(v0, 0.f); v1 = fmaxf(v1, 0.f); }
                *(float2*)(crow + j) = make_float2(v0, v1);
            }
        }
    }
}

// ---- mma.sync edge kernel: sorted edges, no bias (applied post-max) -----------
template <int H, int BN, int MINB>
__global__ void __launch_bounds__(256, MINB)
edge_mma_kernel(const float* __restrict__ AB,
                const uint4* __restrict__ Whi_g, const uint4* __restrict__ Wlo_g,
                unsigned* __restrict__ agg, int E, int COUT) {
    constexpr int NCH = H / 64;
    constexpr int NA  = BN / 16;
    constexpr int WSZ = BN * 144;
    constexpr int ASZ = 128 * 144;
    constexpr int OW  = 1024;
    constexpr int OA  = OW + 2 * WSZ;
    constexpr int WCNT = BN * 9;

    extern __shared__ char sm[];
    const uint32_t smb = smem_u32(sm);
    int* sdst = (int*)sm;
    int* ssrc = (int*)(sm + 512);

    const int tid = threadIdx.x;
    const int wid = tid >> 5, lane = tid & 31;
    const int g = lane >> 2, tig = lane & 3;
    const int e0 = blockIdx.x * 128;
    const int bn = blockIdx.y * BN;

    if (tid < 128) { int e = e0 + tid; ssrc[tid] = (e < E) ? g_srcS[e] : 0; }
    else           { int e = e0 + tid - 128; sdst[tid - 128] = (e < E) ? g_dstS[e] : 0; }
    __syncthreads();

    const int r  = tid >> 1;
    const int hf = tid & 1;
    const float* Arow = AB + (size_t)sdst[r] * (2 * H) + hf * 32;
    const float* Brow = AB + (size_t)ssrc[r] * (2 * H) + H + hf * 32;

    const int wm = wid >> 1, wn = wid & 1;
    const int m0 = wm * 32, n0 = wn * (BN / 2);

    const int lr = lane & 7;
    const uint32_t a_off =
        (uint32_t)(m0 + lr + ((lane >> 3) & 1) * 8) * 144u + (uint32_t)(lane >> 4) * 16u;
    const uint32_t w_off =
        (uint32_t)(n0 + lr + ((lane >> 4) & 1) * 8) * 144u + (uint32_t)((lane >> 3) & 1) * 16u;

    const uint32_t WhU = smb + OW;
    const uint32_t WlU = WhU + WSZ;
    const uint32_t AhU = smb + OA;
    const uint32_t AlU = AhU + ASZ;
    char* Ah = sm + OA;
    char* Al = sm + OA + ASZ;

    float acc[2][NA][4];
#pragma unroll
    for (int ma = 0; ma < 2; ma++)
#pragma unroll
        for (int na = 0; na < NA; na++)
#pragma unroll
            for (int q = 0; q < 4; q++) acc[ma][na][q] = 0.f;

    // prefetch B-side (random src gather) first half for chunk 0
    float4 pre[4];
#pragma unroll
    for (int q = 0; q < 4; q++) pre[q] = ((const float4*)Brow)[q];

    for (int c = 0; c < NCH; c++) {
        if (c) __syncthreads();
        {
            const char* shp = (const char*)(Whi_g + (size_t)(blockIdx.y * NCH + c) * WCNT);
            const char* slp = (const char*)(Wlo_g + (size_t)(blockIdx.y * NCH + c) * WCNT);
            for (int i = tid; i < WCNT; i += 256) {
                cp16(WhU + i * 16, shp + i * 16);
                cp16(WlU + i * 16, slp + i * 16);
            }
            asm volatile("cp.async.commit_group;" ::: "memory");
        }
        {
            const float4* Ap = (const float4*)(Arow + c * 64);
            const float4* Bp = (const float4*)(Brow + c * 64);
            float v[32];
#pragma unroll
            for (int q = 0; q < 4; q++) {
                float4 a = Ap[q], b = pre[q];
                v[q * 4 + 0] = fmaxf(a.x + b.x, 0.f);
                v[q * 4 + 1] = fmaxf(a.y + b.y, 0.f);
                v[q * 4 + 2] = fmaxf(a.z + b.z, 0.f);
                v[q * 4 + 3] = fmaxf(a.w + b.w, 0.f);
            }
#pragma unroll
            for (int q = 4; q < 8; q++) {
                float4 a = Ap[q], b = Bp[q];
                v[q * 4 + 0] = fmaxf(a.x + b.x, 0.f);
                v[q * 4 + 1] = fmaxf(a.y + b.y, 0.f);
                v[q * 4 + 2] = fmaxf(a.z + b.z, 0.f);
                v[q * 4 + 3] = fmaxf(a.w + b.w, 0.f);
            }
            if (c + 1 < NCH) {
                const float4* Bn = (const float4*)(Brow + (c + 1) * 64);
#pragma unroll
                for (int q = 0; q < 4; q++) pre[q] = Bn[q];
            }
            char* ah = Ah + r * 144 + hf * 64;
            char* al = Al + r * 144 + hf * 64;
#pragma unroll
            for (int q8 = 0; q8 < 4; q8++) {
                uint32_t uh[4], ul[4];
#pragma unroll
                for (int p = 0; p < 4; p++)
                    split2(v[q8 * 8 + p * 2], v[q8 * 8 + p * 2 + 1], uh[p], ul[p]);
                *(uint4*)(ah + q8 * 16) = make_uint4(uh[0], uh[1], uh[2], uh[3]);
                *(uint4*)(al + q8 * 16) = make_uint4(ul[0], ul[1], ul[2], ul[3]);
            }
        }
        asm volatile("cp.async.wait_group 0;" ::: "memory");
        __syncthreads();

#pragma unroll
        for (int kq = 0; kq < 4; kq++) {
            uint32_t ah[2][4], al[2][4];
#pragma unroll
            for (int ma = 0; ma < 2; ma++) {
                ldsm_x4(ah[ma], AhU + a_off + (uint32_t)(ma * 16 * 144 + kq * 32));
                ldsm_x4(al[ma], AlU + a_off + (uint32_t)(ma * 16 * 144 + kq * 32));
            }
#pragma unroll
            for (int n2 = 0; n2 < NA / 2; n2++) {
                uint32_t wh[4], wl[4];
                ldsm_x4(wh, WhU + w_off + (uint32_t)(n2 * 16 * 144 + kq * 32));
                ldsm_x4(wl, WlU + w_off + (uint32_t)(n2 * 16 * 144 + kq * 32));
#pragma unroll
                for (int j = 0; j < 2; j++) {
                    const int na = n2 * 2 + j;
                    mma_bf16(acc[0][na], ah[0], wh[2 * j], wh[2 * j + 1]);
                    mma_bf16(acc[1][na], ah[1], wh[2 * j], wh[2 * j + 1]);
                    mma_bf16(acc[0][na], al[0], wh[2 * j], wh[2 * j + 1]);
                    mma_bf16(acc[1][na], al[1], wh[2 * j], wh[2 * j + 1]);
                    mma_bf16(acc[0][na], ah[0], wl[2 * j], wl[2 * j + 1]);
                    mma_bf16(acc[1][na], ah[1], wl[2 * j], wl[2 * j + 1]);
                }
            }
        }
    }

    // ---- epilogue: stale-safe guard + atomicMax (bias deferred to decode) ----
#pragma unroll
    for (int ma = 0; ma < 2; ma++) {
#pragma unroll
        for (int rr = 0; rr < 2; rr++) {
            const int rloc = m0 + ma * 16 + g + rr * 8;
            if (e0 + rloc >= E) continue;
            const int d = sdst[rloc];
            unsigned* arow = agg + (size_t)d * COUT + bn;
#pragma unroll
            for (int na = 0; na < NA; na++) {
                const int j = n0 + na * 8 + 2 * tig;
                unsigned k0 = f2ord(acc[ma][na][rr * 2 + 0]);
                unsigned k1 = f2ord(acc[ma][na][rr * 2 + 1]);
                uint2 cur = *(const uint2*)(arow + j);
                if (k0 > cur.x) atomicMax(arow + j, k0);
                if (k1 > cur.y) atomicMax(arow + j + 1, k1);
            }
        }
    }
}

// ---- decode agg (+bias post-max, exact) -> float; optional clear --------------
__global__ void decode_clear_kernel(const unsigned* __restrict__ agg,
                                    const float* __restrict__ bias,
                                    float* __restrict__ dsth, int total, int C, int ldc,
                                    unsigned* __restrict__ clr, int clrN) {
    int i = blockIdx.x * blockDim.x + threadIdx.x;
    if (i < total) {
        int n = i / C, c = i % C;
        unsigned u = agg[i];
        dsth[(size_t)n * ldc + c] = (u == 0u) ? 0.f : (ord2f(u) + bias[c]);
    }
    if (i < clrN) clr[i] = 0u;
}

// ---- final 256 -> 4 linear ------------------------------------------------------
__global__ void mlp3_kernel(const float* __restrict__ A, const float* __restrict__ W,
                            const float* __restrict__ b, float* __restrict__ out, int M) {
    int gw = (blockIdx.x * blockDim.x + threadIdx.x) >> 5;
    int lane = threadIdx.x & 31;
    if (gw >= M) return;
    const float* a = A + (size_t)gw * 256;
    float acc0 = 0.f, acc1 = 0.f, acc2 = 0.f, acc3 = 0.f;
    for (int k = lane; k < 256; k += 32) {
        float av = a[k];
        const float* wr = W + k * 4;
        acc0 = fmaf(av, wr[0], acc0);
        acc1 = fmaf(av, wr[1], acc1);
        acc2 = fmaf(av, wr[2], acc2);
        acc3 = fmaf(av, wr[3], acc3);
    }
#pragma unroll
    for (int off = 16; off > 0; off >>= 1) {
        acc0 += __shfl_down_sync(0xffffffffu, acc0, off);
        acc1 += __shfl_down_sync(0xffffffffu, acc1, off);
        acc2 += __shfl_down_sync(0xffffffffu, acc2, off);
        acc3 += __shfl_down_sync(0xffffffffu, acc3, off);
    }
    if (lane == 0) {
        out[gw * 4 + 0] = acc0 + b[0];
        out[gw * 4 + 1] = acc1 + b[1];
        out[gw * 4 + 2] = acc2 + b[2];
        out[gw * 4 + 3] = acc3 + b[3];
    }
}

// ---------------------------------------------------------------------------
extern "C" void kernel_launch(void* const* d_in, const int* in_sizes, int n_in,
                              void* d_out, int out_size) {
    const float* x   = (const float*)d_in[0];
    const void*  ei  = d_in[1];
    const float* w1a = (const float*)d_in[3];
    const float* b1a = (const float*)d_in[4];
    const float* w1b = (const float*)d_in[5];
    const float* b1b = (const float*)d_in[6];
    const float* w2a = (const float*)d_in[7];
    const float* b2a = (const float*)d_in[8];
    const float* w2b = (const float*)d_in[9];
    const float* b2b = (const float*)d_in[10];
    const float* w3a = (const float*)d_in[11];
    const float* b3a = (const float*)d_in[12];
    const float* w3b = (const float*)d_in[13];
    const float* b3b = (const float*)d_in[14];
    const float* wm1 = (const float*)d_in[15];
    const float* bm1 = (const float*)d_in[16];
    const float* wm2 = (const float*)d_in[17];
    const float* bm2 = (const float*)d_in[18];
    const float* wm3 = (const float*)d_in[19];
    const float* bm3 = (const float*)d_in[20];

    const int Nn = in_sizes[0] / 3;
    const int E  = in_sizes[1] / 2;
    float* out = (float*)d_out;

    float *AB, *hcat, *m1, *m2, *wc2, *wc3, *bc2, *bc3;
    unsigned* agg;
    uint4 *wh1, *wl1, *wh2, *wl2, *wh3, *wl3;
    uint4 *whn2, *wln2, *whn3, *wln3, *whm1, *wlm1, *whm2, *wlm2;
    cudaGetSymbolAddress((void**)&AB,   g_AB);
    cudaGetSymbolAddress((void**)&agg,  g_agg);
    cudaGetSymbolAddress((void**)&hcat, g_hcat);
    cudaGetSymbolAddress((void**)&m1,   g_m1);
    cudaGetSymbolAddress((void**)&m2,   g_m2);
    cudaGetSymbolAddress((void**)&wc2,  g_wc2);
    cudaGetSymbolAddress((void**)&wc3,  g_wc3);
    cudaGetSymbolAddress((void**)&bc2,  g_bc2);
    cudaGetSymbolAddress((void**)&bc3,  g_bc3);
    cudaGetSymbolAddress((void**)&wh1,  g_wh1);
    cudaGetSymbolAddress((void**)&wl1,  g_wl1);
    cudaGetSymbolAddress((void**)&wh2,  g_wh2);
    cudaGetSymbolAddress((void**)&wl2,  g_wl2);
    cudaGetSymbolAddress((void**)&wh3,  g_wh3);
    cudaGetSymbolAddress((void**)&wl3,  g_wl3);
    cudaGetSymbolAddress((void**)&whn2, g_whn2);
    cudaGetSymbolAddress((void**)&wln2, g_wln2);
    cudaGetSymbolAddress((void**)&whn3, g_whn3);
    cudaGetSymbolAddress((void**)&wln3, g_wln3);
    cudaGetSymbolAddress((void**)&whm1, g_whm1);
    cudaGetSymbolAddress((void**)&wlm1, g_wlm1);
    cudaGetSymbolAddress((void**)&whm2, g_whm2);
    cudaGetSymbolAddress((void**)&wlm2, g_wlm2);

    const int SM1 = 1024 + 2 * (64  * 144) + 2 * 18432;  // 56320
    const int SM2 = 1024 + 2 * (128 * 144) + 2 * 18432;  // 74752
    const int SMD = 2 * (128 * 144) + 2 * 18432;         // 73728
    cudaFuncSetAttribute(edge_mma_kernel<64, 64, 3>,   cudaFuncAttributeMaxDynamicSharedMemorySize, SM1);
    cudaFuncSetAttribute(edge_mma_kernel<128, 128, 2>, cudaFuncAttributeMaxDynamicSharedMemorySize, SM2);
    cudaFuncSetAttribute(edge_mma_kernel<256, 128, 2>, cudaFuncAttributeMaxDynamicSharedMemorySize, SM2);
    cudaFuncSetAttribute(dense_mma_kernel<64,  128, false>, cudaFuncAttributeMaxDynamicSharedMemorySize, SMD);
    cudaFuncSetAttribute(dense_mma_kernel<128, 128, false>, cudaFuncAttributeMaxDynamicSharedMemorySize, SMD);
    cudaFuncSetAttribute(dense_mma_kernel<448, 128, true>,  cudaFuncAttributeMaxDynamicSharedMemorySize, SMD);
    cudaFuncSetAttribute(dense_mma_kernel<512, 128, true>,  cudaFuncAttributeMaxDynamicSharedMemorySize, SMD);

    const int TB = 256;
    dim3 blk(TB);
    const int gx  = (Nn + 127) / 128;
    const int egx = (E + 127) / 128;

    // ---- edge sort by dst (counting sort; segment-max is order-invariant) ----
    convert_idx_kernel<<<(E + TB - 1) / TB, blk>>>((const unsigned*)ei, E);
    hist_kernel<<<(E + TB - 1) / TB, blk>>>(E);
    scan_kernel<<<1, 1024>>>();
    scatter_kernel<<<(E + TB - 1) / TB, blk>>>(E);

    // ---- EdgeConv 1: 3 -> 64 ----
    prep_wb_kernel<<<(64 * 64 + TB - 1) / TB, blk>>>(w1b, wh1, wl1, 64, 64, 64);
    node1_fused_kernel<<<(Nn * 128 + TB - 1) / TB, blk>>>(x, w1a, b1a, AB, agg, Nn);
    edge_mma_kernel<64, 64, 3><<<dim3(egx, 1), blk, SM1>>>(AB, wh1, wl1, agg, E, 64);

    // ---- EdgeConv 2: 64 -> 128 ----
    prep_kernel<<<64, blk>>>(w2a, b2a, wc2, bc2, 64, 128);
    prep_wb_kernel<<<(64 * 256 + TB - 1) / TB, blk>>>(wc2, whn2, wln2, 64, 256, 128);
    prep_wb_kernel<<<(128 * 128 + TB - 1) / TB, blk>>>(w2b, wh2, wl2, 128, 128, 128);
    decode_clear_kernel<<<(Nn * 64 + TB - 1) / TB, blk>>>(agg, b1b, hcat + 0, Nn * 64, 64, 448, nullptr, 0);
    dense_mma_kernel<64, 128, false><<<dim3(gx, 2), blk, SMD>>>(hcat, 448, whn2, wln2, bc2, AB, 256, Nn);
    decode_clear_kernel<<<(Nn * 128 + TB - 1) / TB, blk>>>(agg, b1b, hcat, 0, 64, 448, agg, Nn * 128);
    edge_mma_kernel<128, 128, 2><<<dim3(egx, 1), blk, SM2>>>(AB, wh2, wl2, agg, E, 128);

    // ---- EdgeConv 3: 128 -> 256 ----
    prep_kernel<<<256, blk>>>(w3a, b3a, wc3, bc3, 128, 256);
    prep_wb_kernel<<<(128 * 512 + TB - 1) / TB, blk>>>(wc3, whn3, wln3, 128, 512, 128);
    prep_wb_kernel<<<(256 * 256 + TB - 1) / TB, blk>>>(w3b, wh3, wl3, 256, 256, 128);
    decode_clear_kernel<<<(Nn * 128 + TB - 1) / TB, blk>>>(agg, b2b, hcat + 64, Nn * 128, 128, 448, nullptr, 0);
    dense_mma_kernel<128, 128, false><<<dim3(gx, 4), blk, SMD>>>(hcat + 64, 448, whn3, wln3, bc3, AB, 512, Nn);
    decode_clear_kernel<<<(Nn * 256 + TB - 1) / TB, blk>>>(agg, b2b, hcat, 0, 128, 448, agg, Nn * 256);
    edge_mma_kernel<256, 128, 2><<<dim3(egx, 2), blk, SM2>>>(AB, wh3, wl3, agg, E, 256);
    decode_clear_kernel<<<(Nn * 256 + TB - 1) / TB, blk>>>(agg, b3b, hcat + 192, Nn * 256, 256, 448, nullptr, 0);

    // ---- MLP head ----
    prep_wb_kernel<<<(448 * 512 + TB - 1) / TB, blk>>>(wm1, whm1, wlm1, 448, 512, 128);
    dense_mma_kernel<448, 128, true><<<dim3(gx, 4), blk, SMD>>>(hcat, 448, whm1, wlm1, bm1, m1, 512, Nn);
    prep_wb_kernel<<<(512 * 256 + TB - 1) / TB, blk>>>(wm2, whm2, wlm2, 512, 256, 128);
    dense_mma_kernel<512, 128, true><<<dim3(gx, 2), blk, SMD>>>(m1, 512, whm2, wlm2, bm2, m2, 256, Nn);
    mlp3_kernel<<<(Nn * 32 + TB - 1) / TB, blk>>>(m2, wm3, bm3, out, Nn);
}

// round 13
// speedup vs baseline: 1.0585x; 1.0008x over previous
#include <cuda_runtime.h>
#include <cuda_bf16.h>
#include <cstdint>

// ---------------------------------------------------------------------------
// DGCNN segmentation. ALL GEMMs on tensor cores via mma.sync bf16x3 split
// precision (ldmatrix frags, cp.async.cg W streaming, 64-wide K chunks).
// Edges counting-sorted by dst. Bias applied after segment-max (exact).
// NCH==1 kernels batch MT=2 m-tiles per block to amortize the W copy.
// ---------------------------------------------------------------------------

#define NMAX 30016
#define EMAX 480256
#define NBIN 30720   // 1024 * 30

__device__ float    g_AB[NMAX * 512];
__device__ unsigned g_agg[NMAX * 256];
__device__ float    g_hcat[NMAX * 448];
__device__ float    g_m1[NMAX * 512];
__device__ float    g_m2[NMAX * 256];
__device__ float    g_wc2[64 * 256];
__device__ float    g_wc3[128 * 512];
__device__ float    g_bc2[256];
__device__ float    g_bc3[512];
__device__ uint4    g_wh1[64 * 72 / 8],       g_wl1[64 * 72 / 8];
__device__ uint4    g_wh2[2 * 128 * 72 / 8],  g_wl2[2 * 128 * 72 / 8];
__device__ uint4    g_wh3[8 * 128 * 72 / 8],  g_wl3[8 * 128 * 72 / 8];
__device__ uint4    g_whn2[2304],  g_wln2[2304];
__device__ uint4    g_whn3[9216],  g_wln3[9216];
__device__ uint4    g_whm1[32256], g_wlm1[32256];
__device__ uint4    g_whm2[18432], g_wlm2[18432];
__device__ int      g_src[EMAX];
__device__ int      g_dst[EMAX];
__device__ int      g_srcS[EMAX];   // sorted by dst
__device__ int      g_dstS[EMAX];
__device__ int      g_cnt[NBIN];
__device__ int      g_c2[NBIN];
__device__ int      g_start[NBIN];

// ---- ordered-uint encoding for float max ------------------------------------
__device__ __forceinline__ unsigned f2ord(float f) {
    int i = __float_as_int(f);
    return (i >= 0) ? ((unsigned)i | 0x80000000u) : ~(unsigned)i;
}
__device__ __forceinline__ float ord2f(unsigned u) {
    int i = (u & 0x80000000u) ? (int)(u & 0x7fffffffu) : (int)(~u);
    return __int_as_float(i);
}

// ---- PTX helpers --------------------------------------------------------------
__device__ __forceinline__ uint32_t smem_u32(const void* p) {
    uint32_t a;
    asm("{ .reg .u64 t; cvta.to.shared.u64 t, %1; cvt.u32.u64 %0, t; }" : "=r"(a) : "l"(p));
    return a;
}
__device__ __forceinline__ void mma_bf16(float* d, const uint32_t* a,
                                         uint32_t b0, uint32_t b1) {
    asm volatile(
        "mma.sync.aligned.m16n8k16.row.col.f32.bf16.bf16.f32 "
        "{%0,%1,%2,%3},{%4,%5,%6,%7},{%8,%9},{%0,%1,%2,%3};"
        : "+f"(d[0]), "+f"(d[1]), "+f"(d[2]), "+f"(d[3])
        : "r"(a[0]), "r"(a[1]), "r"(a[2]), "r"(a[3]), "r"(b0), "r"(b1));
}
__device__ __forceinline__ void ldsm_x4(uint32_t* r, uint32_t addr) {
    asm volatile("ldmatrix.sync.aligned.m8n8.x4.shared.b16 {%0,%1,%2,%3},[%4];"
                 : "=r"(r[0]), "=r"(r[1]), "=r"(r[2]), "=r"(r[3]) : "r"(addr));
}
__device__ __forceinline__ void cp16(uint32_t s, const void* g) {
    asm volatile("cp.async.cg.shared.global [%0],[%1],16;" :: "r"(s), "l"(g));
}
__device__ __forceinline__ void split2(float m0, float m1, uint32_t& hi2, uint32_t& lo2) {
    asm("cvt.rn.bf16x2.f32 %0, %1, %2;" : "=r"(hi2) : "f"(m1), "f"(m0));
    float h0 = __uint_as_float(hi2 << 16);
    float h1 = __uint_as_float(hi2 & 0xffff0000u);
    float l0 = m0 - h0, l1 = m1 - h1;
    asm("cvt.rn.bf16x2.f32 %0, %1, %2;" : "=r"(lo2) : "f"(l1), "f"(l0));
}

// ---- edge index convert (+ zero sort bins) ------------------------------------
__global__ void convert_idx_kernel(const unsigned* __restrict__ raw, int E) {
    int n = (E < 256) ? E : 256;
    int is64 = 1;
    for (int i = 0; i < n; i++)
        if (raw[2 * i + 1] != 0u) { is64 = 0; break; }
    int i = blockIdx.x * blockDim.x + threadIdx.x;
    if (i < NBIN) { g_cnt[i] = 0; g_c2[i] = 0; }
    if (i >= E) return;
    if (is64) {
        const long long* p = (const long long*)raw;
        g_src[i] = (int)p[i];
        g_dst[i] = (int)p[E + i];
    } else {
        const int* p = (const int*)raw;
        g_src[i] = p[i];
        g_dst[i] = p[E + i];
    }
}
__global__ void hist_kernel(int E) {
    int i = blockIdx.x * blockDim.x + threadIdx.x;
    if (i < E) atomicAdd(&g_cnt[g_dst[i]], 1);
}
__global__ void scan_kernel() {   // 1 block, 1024 threads, 30 bins each
    __shared__ int part[1024];
    int t = threadIdx.x;
    int base = t * 30;
    int s = 0;
#pragma unroll
    for (int j = 0; j < 30; j++) s += g_cnt[base + j];
    part[t] = s;
    __syncthreads();
    for (int off = 1; off < 1024; off <<= 1) {
        int v = (t >= off) ? part[t - off] : 0;
        __syncthreads();
        part[t] += v;
        __syncthreads();
    }
    int run = part[t] - s;
#pragma unroll
    for (int j = 0; j < 30; j++) {
        g_start[base + j] = run;
        run += g_cnt[base + j];
    }
}
__global__ void scatter_kernel(int E) {
    int i = blockIdx.x * blockDim.x + threadIdx.x;
    if (i >= E) return;
    int d = g_dst[i];
    int pos = g_start[d] + atomicAdd(&g_c2[d], 1);
    g_srcS[pos] = g_src[i];
    g_dstS[pos] = d;
}

// ---- weight prep: wc = [Wtop - Wbot | Wbot], bc = [b | 0] ---------------------
__global__ void prep_kernel(const float* __restrict__ w, const float* __restrict__ b,
                            float* __restrict__ wc, float* __restrict__ bc,
                            int C, int H) {
    int stride = gridDim.x * blockDim.x;
    int i0 = blockIdx.x * blockDim.x + threadIdx.x;
    for (int t = i0; t < C * H; t += stride) {
        int k = t / H, j = t % H;
        float wd = w[(k + C) * H + j];
        wc[k * 2 * H + j]     = w[k * H + j] - wd;
        wc[k * 2 * H + H + j] = wd;
    }
    for (int t = i0; t < H; t += stride) { bc[t] = b[t]; bc[H + t] = 0.f; }
}

// ---- weight prep: W^T bf16 hi/lo chunked [(tile*NCH+c)*BN + n][72] ------------
__global__ void prep_wb_kernel(const float* __restrict__ W,
                               uint4* __restrict__ Whi, uint4* __restrict__ Wlo,
                               int H, int COUT, int BN) {
    int i = blockIdx.x * blockDim.x + threadIdx.x;
    if (i >= H * COUT) return;
    int k = i / COUT, n = i % COUT;
    float w = W[i];
    __nv_bfloat16 hb = __float2bfloat16(w);
    __nv_bfloat16 lb = __float2bfloat16(w - __bfloat162float(hb));
    int NCH = H >> 6;
    int tile = n / BN, nl = n % BN, c = k >> 6, kl = k & 63;
    size_t off = ((size_t)(tile * NCH + c) * BN + nl) * 72 + kl;
    ((unsigned short*)Whi)[off] = __bfloat16_as_ushort(hb);
    ((unsigned short*)Wlo)[off] = __bfloat16_as_ushort(lb);
}

// ---- layer-1 node precompute fused with wc1 prep + agg clear ------------------
__global__ void node1_fused_kernel(const float* __restrict__ x,
                                   const float* __restrict__ w1a,
                                   const float* __restrict__ b1a,
                                   float* __restrict__ AB,
                                   unsigned* __restrict__ agg, int M) {
    int idx = blockIdx.x * blockDim.x + threadIdx.x;
    if (idx >= M * 128) return;
    if (idx < M * 64) agg[idx] = 0u;
    int n = idx >> 7, j = idx & 127;
    float wk0, wk1, wk2, bb;
    if (j < 64) {
        wk0 = w1a[0 * 64 + j] - w1a[3 * 64 + j];
        wk1 = w1a[1 * 64 + j] - w1a[4 * 64 + j];
        wk2 = w1a[2 * 64 + j] - w1a[5 * 64 + j];
        bb  = b1a[j];
    } else {
        int jj = j - 64;
        wk0 = w1a[3 * 64 + jj];
        wk1 = w1a[4 * 64 + jj];
        wk2 = w1a[5 * 64 + jj];
        bb  = 0.f;
    }
    float x0 = x[n * 3 + 0], x1 = x[n * 3 + 1], x2 = x[n * 3 + 2];
    AB[idx] = fmaf(x0, wk0, fmaf(x1, wk1, fmaf(x2, wk2, bb)));
}

// ---- dense bf16x3 mma GEMM: C = act(A[M,K] @ W[K,N] + bias) -------------------
// MT m-tiles per block; W copied once per chunk (reused across m-tiles, NCH==1).
template <int K, int BN, bool RELU, int MT>
__global__ void __launch_bounds__(256, 2)
dense_mma_kernel(const float* __restrict__ A, int lda,
                 const uint4* __restrict__ Whi_g, const uint4* __restrict__ Wlo_g,
                 const float* __restrict__ bias,
                 float* __restrict__ C, int ldc, int M) {
    constexpr int NCH = K / 64;
    static_assert(MT == 1 || NCH == 1, "MT>1 requires single-chunk K");
    constexpr int NA  = BN / 16;
    constexpr int WSZ = BN * 144;
    constexpr int ASZ = 128 * 144;
    constexpr int OA  = 2 * WSZ;
    constexpr int WCNT = BN * 9;

    extern __shared__ char sm[];
    const uint32_t smb = smem_u32(sm);

    const int tid = threadIdx.x;
    const int wid = tid >> 5, lane = tid & 31;
    const int g = lane >> 2, tig = lane & 3;
    const int bmb = blockIdx.x * (128 * MT);
    const int bn = blockIdx.y * BN;

    const int r  = tid >> 1;
    const int hf = tid & 1;

    const int wm = wid >> 1, wn = wid & 1;
    const int m0 = wm * 32, n0 = wn * (BN / 2);

    const int lr = lane & 7;
    const uint32_t a_off =
        (uint32_t)(m0 + lr + ((lane >> 3) & 1) * 8) * 144u + (uint32_t)(lane >> 4) * 16u;
    const uint32_t w_off =
        (uint32_t)(n0 + lr + ((lane >> 4) & 1) * 8) * 144u + (uint32_t)((lane >> 3) & 1) * 16u;

    const uint32_t WhU = smb;
    const uint32_t WlU = WhU + WSZ;
    const uint32_t AhU = smb + OA;
    const uint32_t AlU = AhU + ASZ;
    char* Ah = sm + OA;
    char* Al = sm + OA + ASZ;

    for (int mt = 0; mt < MT; mt++) {
        const int bm = bmb + mt * 128;
        const bool rv = (bm + r) < M;
        const float* Arow = A + (size_t)(bm + r) * lda + hf * 32;

        float acc[2][NA][4];
#pragma unroll
        for (int ma = 0; ma < 2; ma++)
#pragma unroll
            for (int na = 0; na < NA; na++)
#pragma unroll
                for (int q = 0; q < 4; q++) acc[ma][na][q] = 0.f;

        for (int c = 0; c < NCH; c++) {
            if (c || mt) __syncthreads();
            if (mt == 0) {
                const char* shp = (const char*)(Whi_g + (size_t)(blockIdx.y * NCH + c) * WCNT);
                const char* slp = (const char*)(Wlo_g + (size_t)(blockIdx.y * NCH + c) * WCNT);
                for (int i = tid; i < WCNT; i += 256) {
                    cp16(WhU + i * 16, shp + i * 16);
                    cp16(WlU + i * 16, slp + i * 16);
                }
                asm volatile("cp.async.commit_group;" ::: "memory");
            }
            {
                const float4* Ap = (const float4*)(Arow + c * 64);
                float v[32];
                if (rv) {
#pragma unroll
                    for (int q = 0; q < 8; q++) {
                        float4 a = Ap[q];
                        v[q * 4 + 0] = a.x; v[q * 4 + 1] = a.y;
                        v[q * 4 + 2] = a.z; v[q * 4 + 3] = a.w;
                    }
                } else {
#pragma unroll
                    for (int q = 0; q < 32; q++) v[q] = 0.f;
                }
                char* ah = Ah + r * 144 + hf * 64;
                char* al = Al + r * 144 + hf * 64;
#pragma unroll
                for (int q8 = 0; q8 < 4; q8++) {
                    uint32_t uh[4], ul[4];
#pragma unroll
                    for (int p = 0; p < 4; p++)
                        split2(v[q8 * 8 + p * 2], v[q8 * 8 + p * 2 + 1], uh[p], ul[p]);
                    *(uint4*)(ah + q8 * 16) = make_uint4(uh[0], uh[1], uh[2], uh[3]);
                    *(uint4*)(al + q8 * 16) = make_uint4(ul[0], ul[1], ul[2], ul[3]);
                }
            }
            asm volatile("cp.async.wait_group 0;" ::: "memory");
            __syncthreads();

#pragma unroll
            for (int kq = 0; kq < 4; kq++) {
                uint32_t ah[2][4], al[2][4];
#pragma unroll
                for (int ma = 0; ma < 2; ma++) {
                    ldsm_x4(ah[ma], AhU + a_off + (uint32_t)(ma * 16 * 144 + kq * 32));
                    ldsm_x4(al[ma], AlU + a_off + (uint32_t)(ma * 16 * 144 + kq * 32));
                }
#pragma unroll
                for (int n2 = 0; n2 < NA / 2; n2++) {
                    uint32_t wh[4], wl[4];
                    ldsm_x4(wh, WhU + w_off + (uint32_t)(n2 * 16 * 144 + kq * 32));
                    ldsm_x4(wl, WlU + w_off + (uint32_t)(n2 * 16 * 144 + kq * 32));
#pragma unroll
                    for (int j = 0; j < 2; j++) {
                        const int na = n2 * 2 + j;
                        mma_bf16(acc[0][na], ah[0], wh[2 * j], wh[2 * j + 1]);
                        mma_bf16(acc[1][na], ah[1], wh[2 * j], wh[2 * j + 1]);
                        mma_bf16(acc[0][na], al[0], wh[2 * j], wh[2 * j + 1]);
                        mma_bf16(acc[1][na], al[1], wh[2 * j], wh[2 * j + 1]);
                        mma_bf16(acc[0][na], ah[0], wl[2 * j], wl[2 * j + 1]);
                        mma_bf16(acc[1][na], ah[1], wl[2 * j], wl[2 * j + 1]);
                    }
                }
            }
        }

#pragma unroll
        for (int ma = 0; ma < 2; ma++) {
#pragma unroll
            for (int rr = 0; rr < 2; rr++) {
                const int rg = bm + m0 + ma * 16 + g + rr * 8;
                if (rg >= M) continue;
                float* crow = C + (size_t)rg * ldc + bn;
#pragma unroll
                for (int na = 0; na < NA; na++) {
                    const int j = n0 + na * 8 + 2 * tig;
                    float v0 = acc[ma][na][rr * 2 + 0] + bias[bn + j];
                    float v1 = acc[ma][na][rr * 2 + 1] + bias[bn + j + 1];
                    if (RELU) { v0 = fmaxf(v0, 0.f); v1 = fmaxf(v1, 0.f); }
                    *(float2*)(crow + j) = make_float2(v0, v1);
                }
            }
        }
    }
}

// ---- mma.sync edge kernel: sorted edges, MT m-tiles, bias post-max ------------
template <int H, int BN, int MINB, int MT>
__global__ void __launch_bounds__(256, MINB)
edge_mma_kernel(const float* __restrict__ AB,
                const uint4* __restrict__ Whi_g, const uint4* __restrict__ Wlo_g,
                unsigned* __restrict__ agg, int E, int COUT) {
    constexpr int NCH = H / 64;
    static_assert(MT == 1 || NCH == 1, "MT>1 requires single-chunk K");
    constexpr int NA  = BN / 16;
    constexpr int WSZ = BN * 144;
    constexpr int ASZ = 128 * 144;
    constexpr int OW  = 2048;
    constexpr int OA  = OW + 2 * WSZ;
    constexpr int WCNT = BN * 9;

    extern __shared__ char sm[];
    const uint32_t smb = smem_u32(sm);
    int* sdst = (int*)sm;            // MT*128 ints
    int* ssrc = (int*)(sm + 1024);   // MT*128 ints

    const int tid = threadIdx.x;
    const int wid = tid >> 5, lane = tid & 31;
    const int g = lane >> 2, tig = lane & 3;
    const int e0b = blockIdx.x * (128 * MT);
    const int bn = blockIdx.y * BN;

    for (int i = tid; i < 128 * MT; i += 256) {
        int e = e0b + i;
        ssrc[i] = (e < E) ? g_srcS[e] : 0;
        sdst[i] = (e < E) ? g_dstS[e] : 0;
    }
    __syncthreads();

    const int r  = tid >> 1;
    const int hf = tid & 1;

    const int wm = wid >> 1, wn = wid & 1;
    const int m0 = wm * 32, n0 = wn * (BN / 2);

    const int lr = lane & 7;
    const uint32_t a_off =
        (uint32_t)(m0 + lr + ((lane >> 3) & 1) * 8) * 144u + (uint32_t)(lane >> 4) * 16u;
    const uint32_t w_off =
        (uint32_t)(n0 + lr + ((lane >> 4) & 1) * 8) * 144u + (uint32_t)((lane >> 3) & 1) * 16u;

    const uint32_t WhU = smb + OW;
    const uint32_t WlU = WhU + WSZ;
    const uint32_t AhU = smb + OA;
    const uint32_t AlU = AhU + ASZ;
    char* Ah = sm + OA;
    char* Al = sm + OA + ASZ;

    for (int mt = 0; mt < MT; mt++) {
        const int rb = mt * 128;
        const float* Arow = AB + (size_t)sdst[rb + r] * (2 * H) + hf * 32;
        const float* Brow = AB + (size_t)ssrc[rb + r] * (2 * H) + H + hf * 32;

        float acc[2][NA][4];
#pragma unroll
        for (int ma = 0; ma < 2; ma++)
#pragma unroll
            for (int na = 0; na < NA; na++)
#pragma unroll
                for (int q = 0; q < 4; q++) acc[ma][na][q] = 0.f;

        // prefetch B-side (random src gather) first half for chunk 0
        float4 pre[4];
#pragma unroll
        for (int q = 0; q < 4; q++) pre[q] = ((const float4*)Brow)[q];

        for (int c = 0; c < NCH; c++) {
            if (c || mt) __syncthreads();
            if (mt == 0) {
                const char* shp = (const char*)(Whi_g + (size_t)(blockIdx.y * NCH + c) * WCNT);
                const char* slp = (const char*)(Wlo_g + (size_t)(blockIdx.y * NCH + c) * WCNT);
                for (int i = tid; i < WCNT; i += 256) {
                    cp16(WhU + i * 16, shp + i * 16);
                    cp16(WlU + i * 16, slp + i * 16);
                }
                asm volatile("cp.async.commit_group;" ::: "memory");
            }
            {
                const float4* Ap = (const float4*)(Arow + c * 64);
                const float4* Bp = (const float4*)(Brow + c * 64);
                float v[32];
#pragma unroll
                for (int q = 0; q < 4; q++) {
                    float4 a = Ap[q], b = pre[q];
                    v[q * 4 + 0] = fmaxf(a.x + b.x, 0.f);
                    v[q * 4 + 1] = fmaxf(a.y + b.y, 0.f);
                    v[q * 4 + 2] = fmaxf(a.z + b.z, 0.f);
                    v[q * 4 + 3] = fmaxf(a.w + b.w, 0.f);
                }
#pragma unroll
                for (int q = 4; q < 8; q++) {
                    float4 a = Ap[q], b = Bp[q];
                    v[q * 4 + 0] = fmaxf(a.x + b.x, 0.f);
                    v[q * 4 + 1] = fmaxf(a.y + b.y, 0.f);
                    v[q * 4 + 2] = fmaxf(a.z + b.z, 0.f);
                    v[q * 4 + 3] = fmaxf(a.w + b.w, 0.f);
                }
                if (c + 1 < NCH) {
                    const float4* Bn = (const float4*)(Brow + (c + 1) * 64);
#pragma unroll
                    for (int q = 0; q < 4; q++) pre[q] = Bn[q];
                }
                char* ah = Ah + r * 144 + hf * 64;
                char* al = Al + r * 144 + hf * 64;
#pragma unroll
                for (int q8 = 0; q8 < 4; q8++) {
                    uint32_t uh[4], ul[4];
#pragma unroll
                    for (int p = 0; p < 4; p++)
                        split2(v[q8 * 8 + p * 2], v[q8 * 8 + p * 2 + 1], uh[p], ul[p]);
                    *(uint4*)(ah + q8 * 16) = make_uint4(uh[0], uh[1], uh[2], uh[3]);
                    *(uint4*)(al + q8 * 16) = make_uint4(ul[0], ul[1], ul[2], ul[3]);
                }
            }
            asm volatile("cp.async.wait_group 0;" ::: "memory");
            __syncthreads();

#pragma unroll
            for (int kq = 0; kq < 4; kq++) {
                uint32_t ah[2][4], al[2][4];
#pragma unroll
                for (int ma = 0; ma < 2; ma++) {
                    ldsm_x4(ah[ma], AhU + a_off + (uint32_t)(ma * 16 * 144 + kq * 32));
                    ldsm_x4(al[ma], AlU + a_off + (uint32_t)(ma * 16 * 144 + kq * 32));
                }
#pragma unroll
                for (int n2 = 0; n2 < NA / 2; n2++) {
                    uint32_t wh[4], wl[4];
                    ldsm_x4(wh, WhU + w_off + (uint32_t)(n2 * 16 * 144 + kq * 32));
                    ldsm_x4(wl, WlU + w_off + (uint32_t)(n2 * 16 * 144 + kq * 32));
#pragma unroll
                    for (int j = 0; j < 2; j++) {
                        const int na = n2 * 2 + j;
                        mma_bf16(acc[0][na], ah[0], wh[2 * j], wh[2 * j + 1]);
                        mma_bf16(acc[1][na], ah[1], wh[2 * j], wh[2 * j + 1]);
                        mma_bf16(acc[0][na], al[0], wh[2 * j], wh[2 * j + 1]);
                        mma_bf16(acc[1][na], al[1], wh[2 * j], wh[2 * j + 1]);
                        mma_bf16(acc[0][na], ah[0], wl[2 * j], wl[2 * j + 1]);
                        mma_bf16(acc[1][na], ah[1], wl[2 * j], wl[2 * j + 1]);
                    }
                }
            }
        }

        // ---- epilogue: stale-safe guard + atomicMax (bias deferred) ----
#pragma unroll
        for (int ma = 0; ma < 2; ma++) {
#pragma unroll
            for (int rr = 0; rr < 2; rr++) {
                const int rloc = m0 + ma * 16 + g + rr * 8;
                if (e0b + rb + rloc >= E) continue;
                const int d = sdst[rb + rloc];
                unsigned* arow = agg + (size_t)d * COUT + bn;
#pragma unroll
                for (int na = 0; na < NA; na++) {
                    const int j = n0 + na * 8 + 2 * tig;
                    unsigned k0 = f2ord(acc[ma][na][rr * 2 + 0]);
                    unsigned k1 = f2ord(acc[ma][na][rr * 2 + 1]);
                    uint2 cur = *(const uint2*)(arow + j);
                    if (k0 > cur.x) atomicMax(arow + j, k0);
                    if (k1 > cur.y) atomicMax(arow + j + 1, k1);
                }
            }
        }
    }
}

// ---- decode agg (+bias post-max, exact) -> float; optional clear --------------
__global__ void decode_clear_kernel(const unsigned* __restrict__ agg,
                                    const float* __restrict__ bias,
                                    float* __restrict__ dsth, int total, int C, int ldc,
                                    unsigned* __restrict__ clr, int clrN) {
    int i = blockIdx.x * blockDim.x + threadIdx.x;
    if (i < total) {
        int n = i / C, c = i % C;
        unsigned u = agg[i];
        dsth[(size_t)n * ldc + c] = (u == 0u) ? 0.f : (ord2f(u) + bias[c]);
    }
    if (i < clrN) clr[i] = 0u;
}

// ---- final 256 -> 4 linear ------------------------------------------------------
__global__ void mlp3_kernel(const float* __restrict__ A, const float* __restrict__ W,
                            const float* __restrict__ b, float* __restrict__ out, int M) {
    int gw = (blockIdx.x * blockDim.x + threadIdx.x) >> 5;
    int lane = threadIdx.x & 31;
    if (gw >= M) return;
    const float* a = A + (size_t)gw * 256;
    float acc0 = 0.f, acc1 = 0.f, acc2 = 0.f, acc3 = 0.f;
    for (int k = lane; k < 256; k += 32) {
        float av = a[k];
        const float* wr = W + k * 4;
        acc0 = fmaf(av, wr[0], acc0);
        acc1 = fmaf(av, wr[1], acc1);
        acc2 = fmaf(av, wr[2], acc2);
        acc3 = fmaf(av, wr[3], acc3);
    }
#pragma unroll
    for (int off = 16; off > 0; off >>= 1) {
        acc0 += __shfl_down_sync(0xffffffffu, acc0, off);
        acc1 += __shfl_down_sync(0xffffffffu, acc1, off);
        acc2 += __shfl_down_sync(0xffffffffu, acc2, off);
        acc3 += __shfl_down_sync(0xffffffffu, acc3, off);
    }
    if (lane == 0) {
        out[gw * 4 + 0] = acc0 + b[0];
        out[gw * 4 + 1] = acc1 + b[1];
        out[gw * 4 + 2] = acc2 + b[2];
        out[gw * 4 + 3] = acc3 + b[3];
    }
}

// ---------------------------------------------------------------------------
extern "C" void kernel_launch(void* const* d_in, const int* in_sizes, int n_in,
                              void* d_out, int out_size) {
    const float* x   = (const float*)d_in[0];
    const void*  ei  = d_in[1];
    const float* w1a = (const float*)d_in[3];
    const float* b1a = (const float*)d_in[4];
    const float* w1b = (const float*)d_in[5];
    const float* b1b = (const float*)d_in[6];
    const float* w2a = (const float*)d_in[7];
    const float* b2a = (const float*)d_in[8];
    const float* w2b = (const float*)d_in[9];
    const float* b2b = (const float*)d_in[10];
    const float* w3a = (const float*)d_in[11];
    const float* b3a = (const float*)d_in[12];
    const float* w3b = (const float*)d_in[13];
    const float* b3b = (const float*)d_in[14];
    const float* wm1 = (const float*)d_in[15];
    const float* bm1 = (const float*)d_in[16];
    const float* wm2 = (const float*)d_in[17];
    const float* bm2 = (const float*)d_in[18];
    const float* wm3 = (const float*)d_in[19];
    const float* bm3 = (const float*)d_in[20];

    const int Nn = in_sizes[0] / 3;
    const int E  = in_sizes[1] / 2;
    float* out = (float*)d_out;

    float *AB, *hcat, *m1, *m2, *wc2, *wc3, *bc2, *bc3;
    unsigned* agg;
    uint4 *wh1, *wl1, *wh2, *wl2, *wh3, *wl3;
    uint4 *whn2, *wln2, *whn3, *wln3, *whm1, *wlm1, *whm2, *wlm2;
    cudaGetSymbolAddress((void**)&AB,   g_AB);
    cudaGetSymbolAddress((void**)&agg,  g_agg);
    cudaGetSymbolAddress((void**)&hcat, g_hcat);
    cudaGetSymbolAddress((void**)&m1,   g_m1);
    cudaGetSymbolAddress((void**)&m2,   g_m2);
    cudaGetSymbolAddress((void**)&wc2,  g_wc2);
    cudaGetSymbolAddress((void**)&wc3,  g_wc3);
    cudaGetSymbolAddress((void**)&bc2,  g_bc2);
    cudaGetSymbolAddress((void**)&bc3,  g_bc3);
    cudaGetSymbolAddress((void**)&wh1,  g_wh1);
    cudaGetSymbolAddress((void**)&wl1,  g_wl1);
    cudaGetSymbolAddress((void**)&wh2,  g_wh2);
    cudaGetSymbolAddress((void**)&wl2,  g_wl2);
    cudaGetSymbolAddress((void**)&wh3,  g_wh3);
    cudaGetSymbolAddress((void**)&wl3,  g_wl3);
    cudaGetSymbolAddress((void**)&whn2, g_whn2);
    cudaGetSymbolAddress((void**)&wln2, g_wln2);
    cudaGetSymbolAddress((void**)&whn3, g_whn3);
    cudaGetSymbolAddress((void**)&wln3, g_wln3);
    cudaGetSymbolAddress((void**)&whm1, g_whm1);
    cudaGetSymbolAddress((void**)&wlm1, g_wlm1);
    cudaGetSymbolAddress((void**)&whm2, g_whm2);
    cudaGetSymbolAddress((void**)&wlm2, g_wlm2);

    const int SM1 = 2048 + 2 * (64  * 144) + 2 * 18432;  // 57344
    const int SM2 = 2048 + 2 * (128 * 144) + 2 * 18432;  // 75776
    const int SMD = 2 * (128 * 144) + 2 * 18432;         // 73728
    cudaFuncSetAttribute(edge_mma_kernel<64, 64, 3, 2>,   cudaFuncAttributeMaxDynamicSharedMemorySize, SM1);
    cudaFuncSetAttribute(edge_mma_kernel<128, 128, 2, 1>, cudaFuncAttributeMaxDynamicSharedMemorySize, SM2);
    cudaFuncSetAttribute(edge_mma_kernel<256, 128, 2, 1>, cudaFuncAttributeMaxDynamicSharedMemorySize, SM2);
    cudaFuncSetAttribute(dense_mma_kernel<64,  128, false, 2>, cudaFuncAttributeMaxDynamicSharedMemorySize, SMD);
    cudaFuncSetAttribute(dense_mma_kernel<128, 128, false, 1>, cudaFuncAttributeMaxDynamicSharedMemorySize, SMD);
    cudaFuncSetAttribute(dense_mma_kernel<448, 128, true, 1>,  cudaFuncAttributeMaxDynamicSharedMemorySize, SMD);
    cudaFuncSetAttribute(dense_mma_kernel<512, 128, true, 1>,  cudaFuncAttributeMaxDynamicSharedMemorySize, SMD);

    const int TB = 256;
    dim3 blk(TB);
    const int gx   = (Nn + 127) / 128;
    const int gx2  = (Nn + 255) / 256;
    const int egx  = (E + 127) / 128;
    const int egx2 = (E + 255) / 256;

    // ---- edge sort by dst (counting sort; segment-max is order-invariant) ----
    convert_idx_kernel<<<(E + TB - 1) / TB, blk>>>((const unsigned*)ei, E);
    hist_kernel<<<(E + TB - 1) / TB, blk>>>(E);
    scan_kernel<<<1, 1024>>>();
    scatter_kernel<<<(E + TB - 1) / TB, blk>>>(E);

    // ---- EdgeConv 1: 3 -> 64 ----
    prep_wb_kernel<<<(64 * 64 + TB - 1) / TB, blk>>>(w1b, wh1, wl1, 64, 64, 64);
    node1_fused_kernel<<<(Nn * 128 + TB - 1) / TB, blk>>>(x, w1a, b1a, AB, agg, Nn);
    edge_mma_kernel<64, 64, 3, 2><<<dim3(egx2, 1), blk, SM1>>>(AB, wh1, wl1, agg, E, 64);

    // ---- EdgeConv 2: 64 -> 128 ----
    prep_kernel<<<64, blk>>>(w2a, b2a, wc2, bc2, 64, 128);
    prep_wb_kernel<<<(64 * 256 + TB - 1) / TB, blk>>>(wc2, whn2, wln2, 64, 256, 128);
    prep_wb_kernel<<<(128 * 128 + TB - 1) / TB, blk>>>(w2b, wh2, wl2, 128, 128, 128);
    decode_clear_kernel<<<(Nn * 64 + TB - 1) / TB, blk>>>(agg, b1b, hcat + 0, Nn * 64, 64, 448, nullptr, 0);
    dense_mma_kernel<64, 128, false, 2><<<dim3(gx2, 2), blk, SMD>>>(hcat, 448, whn2, wln2, bc2, AB, 256, Nn);
    decode_clear_kernel<<<(Nn * 128 + TB - 1) / TB, blk>>>(agg, b1b, hcat, 0, 64, 448, agg, Nn * 128);
    edge_mma_kernel<128, 128, 2, 1><<<dim3(egx, 1), blk, SM2>>>(AB, wh2, wl2, agg, E, 128);

    // ---- EdgeConv 3: 128 -> 256 ----
    prep_kernel<<<256, blk>>>(w3a, b3a, wc3, bc3, 128, 256);
    prep_wb_kernel<<<(128 * 512 + TB - 1) / TB, blk>>>(wc3, whn3, wln3, 128, 512, 128);
    prep_wb_kernel<<<(256 * 256 + TB - 1) / TB, blk>>>(w3b, wh3, wl3, 256, 256, 128);
    decode_clear_kernel<<<(Nn * 128 + TB - 1) / TB, blk>>>(agg, b2b, hcat + 64, Nn * 128, 128, 448, nullptr, 0);
    dense_mma_kernel<128, 128, false, 1><<<dim3(gx, 4), blk, SMD>>>(hcat + 64, 448, whn3, wln3, bc3, AB, 512, Nn);
    decode_clear_kernel<<<(Nn * 256 + TB - 1) / TB, blk>>>(agg, b2b, hcat, 0, 128, 448, agg, Nn * 256);
    edge_mma_kernel<256, 128, 2, 1><<<dim3(egx, 2), blk, SM2>>>(AB, wh3, wl3, agg, E, 256);
    decode_clear_kernel<<<(Nn * 256 + TB - 1) / TB, blk>>>(agg, b3b, hcat + 192, Nn * 256, 256, 448, nullptr, 0);

    // ---- MLP head ----
    prep_wb_kernel<<<(448 * 512 + TB - 1) / TB, blk>>>(wm1, whm1, wlm1, 448, 512, 128);
    dense_mma_kernel<448, 128, true, 1><<<dim3(gx, 4), blk, SMD>>>(hcat, 448, whm1, wlm1, bm1, m1, 512, Nn);
    prep_wb_kernel<<<(512 * 256 + TB - 1) / TB, blk>>>(wm2, whm2, wlm2, 512, 256, 128);
    dense_mma_kernel<512, 128, true, 1><<<dim3(gx, 2), blk, SMD>>>(m1, 512, whm2, wlm2, bm2, m2, 256, Nn);
    mlp3_kernel<<<(Nn * 32 + TB - 1) / TB, blk>>>(m2, wm3, bm3, out, Nn);
}

// round 14
// speedup vs baseline: 1.0717x; 1.0125x over previous
#include <cuda_runtime.h>
#include <cuda_bf16.h>
#include <cstdint>

// ---------------------------------------------------------------------------
// DGCNN segmentation. ALL GEMMs on tensor cores via mma.sync bf16x3 split
// precision (ldmatrix frags, cp.async.cg W streaming, 64-wide K chunks).
// Edges counting-sorted by dst. Bias applied after segment-max (exact).
// Launch-compressed: inline node-weight combine, fused decode+clear.
// ---------------------------------------------------------------------------

#define NMAX 30016
#define EMAX 480256
#define NBIN 30720   // 1024 * 30

__device__ float    g_AB[NMAX * 512];
__device__ unsigned g_agg[NMAX * 256];
__device__ float    g_hcat[NMAX * 448];
__device__ float    g_m1[NMAX * 512];
__device__ float    g_m2[NMAX * 256];
__device__ uint4    g_wh1[64 * 72 / 8],       g_wl1[64 * 72 / 8];
__device__ uint4    g_wh2[2 * 128 * 72 / 8],  g_wl2[2 * 128 * 72 / 8];
__device__ uint4    g_wh3[8 * 128 * 72 / 8],  g_wl3[8 * 128 * 72 / 8];
__device__ uint4    g_whn2[2304],  g_wln2[2304];
__device__ uint4    g_whn3[9216],  g_wln3[9216];
__device__ uint4    g_whm1[32256], g_wlm1[32256];
__device__ uint4    g_whm2[18432], g_wlm2[18432];
__device__ int      g_src[EMAX];
__device__ int      g_dst[EMAX];
__device__ int      g_srcS[EMAX];   // sorted by dst
__device__ int      g_dstS[EMAX];
__device__ int      g_cnt[NBIN];
__device__ int      g_c2[NBIN];
__device__ int      g_start[NBIN];

// ---- ordered-uint encoding for float max ------------------------------------
__device__ __forceinline__ unsigned f2ord(float f) {
    int i = __float_as_int(f);
    return (i >= 0) ? ((unsigned)i | 0x80000000u) : ~(unsigned)i;
}
__device__ __forceinline__ float ord2f(unsigned u) {
    int i = (u & 0x80000000u) ? (int)(u & 0x7fffffffu) : (int)(~u);
    return __int_as_float(i);
}

// ---- PTX helpers --------------------------------------------------------------
__device__ __forceinline__ uint32_t smem_u32(const void* p) {
    uint32_t a;
    asm("{ .reg .u64 t; cvta.to.shared.u64 t, %1; cvt.u32.u64 %0, t; }" : "=r"(a) : "l"(p));
    return a;
}
__device__ __forceinline__ void mma_bf16(float* d, const uint32_t* a,
                                         uint32_t b0, uint32_t b1) {
    asm volatile(
        "mma.sync.aligned.m16n8k16.row.col.f32.bf16.bf16.f32 "
        "{%0,%1,%2,%3},{%4,%5,%6,%7},{%8,%9},{%0,%1,%2,%3};"
        : "+f"(d[0]), "+f"(d[1]), "+f"(d[2]), "+f"(d[3])
        : "r"(a[0]), "r"(a[1]), "r"(a[2]), "r"(a[3]), "r"(b0), "r"(b1));
}
__device__ __forceinline__ void ldsm_x4(uint32_t* r, uint32_t addr) {
    asm volatile("ldmatrix.sync.aligned.m8n8.x4.shared.b16 {%0,%1,%2,%3},[%4];"
                 : "=r"(r[0]), "=r"(r[1]), "=r"(r[2]), "=r"(r[3]) : "r"(addr));
}
__device__ __forceinline__ void cp16(uint32_t s, const void* g) {
    asm volatile("cp.async.cg.shared.global [%0],[%1],16;" :: "r"(s), "l"(g));
}
__device__ __forceinline__ void split2(float m0, float m1, uint32_t& hi2, uint32_t& lo2) {
    asm("cvt.rn.bf16x2.f32 %0, %1, %2;" : "=r"(hi2) : "f"(m1), "f"(m0));
    float h0 = __uint_as_float(hi2 << 16);
    float h1 = __uint_as_float(hi2 & 0xffff0000u);
    float l0 = m0 - h0, l1 = m1 - h1;
    asm("cvt.rn.bf16x2.f32 %0, %1, %2;" : "=r"(lo2) : "f"(l1), "f"(l0));
}

// ---- edge index convert (+ zero sort bins) ------------------------------------
__global__ void convert_idx_kernel(const unsigned* __restrict__ raw, int E) {
    int n = (E < 256) ? E : 256;
    int is64 = 1;
    for (int i = 0; i < n; i++)
        if (raw[2 * i + 1] != 0u) { is64 = 0; break; }
    int i = blockIdx.x * blockDim.x + threadIdx.x;
    if (i < NBIN) { g_cnt[i] = 0; g_c2[i] = 0; }
    if (i >= E) return;
    if (is64) {
        const long long* p = (const long long*)raw;
        g_src[i] = (int)p[i];
        g_dst[i] = (int)p[E + i];
    } else {
        const int* p = (const int*)raw;
        g_src[i] = p[i];
        g_dst[i] = p[E + i];
    }
}
__global__ void hist_kernel(int E) {
    int i = blockIdx.x * blockDim.x + threadIdx.x;
    if (i < E) atomicAdd(&g_cnt[g_dst[i]], 1);
}
__global__ void scan_kernel() {   // 1 block, 1024 threads, 30 bins each
    __shared__ int part[1024];
    int t = threadIdx.x;
    int base = t * 30;
    int s = 0;
#pragma unroll
    for (int j = 0; j < 30; j++) s += g_cnt[base + j];
    part[t] = s;
    __syncthreads();
    for (int off = 1; off < 1024; off <<= 1) {
        int v = (t >= off) ? part[t - off] : 0;
        __syncthreads();
        part[t] += v;
        __syncthreads();
    }
    int run = part[t] - s;
#pragma unroll
    for (int j = 0; j < 30; j++) {
        g_start[base + j] = run;
        run += g_cnt[base + j];
    }
}
__global__ void scatter_kernel(int E) {
    int i = blockIdx.x * blockDim.x + threadIdx.x;
    if (i >= E) return;
    int d = g_dst[i];
    int pos = g_start[d] + atomicAdd(&g_c2[d], 1);
    g_srcS[pos] = g_src[i];
    g_dstS[pos] = d;
}

// ---- weight prep: W^T bf16 hi/lo chunked [(tile*NCH+c)*BN + n][72] ------------
__global__ void prep_wb_kernel(const float* __restrict__ W,
                               uint4* __restrict__ Whi, uint4* __restrict__ Wlo,
                               int H, int COUT, int BN) {
    int i = blockIdx.x * blockDim.x + threadIdx.x;
    if (i >= H * COUT) return;
    int k = i / COUT, n = i % COUT;
    float w = W[i];
    __nv_bfloat16 hb = __float2bfloat16(w);
    __nv_bfloat16 lb = __float2bfloat16(w - __bfloat162float(hb));
    int NCH = H >> 6;
    int tile = n / BN, nl = n % BN, c = k >> 6, kl = k & 63;
    size_t off = ((size_t)(tile * NCH + c) * BN + nl) * 72 + kl;
    ((unsigned short*)Whi)[off] = __bfloat16_as_ushort(hb);
    ((unsigned short*)Wlo)[off] = __bfloat16_as_ushort(lb);
}

// ---- node-GEMM weight prep: combined [Wtop-Wbot | Wbot] inline from raw w ------
// raw w: [2C, H] row-major.  Logical GEMM weight: [C rows, 2H cols].
__global__ void prep_wb_node_kernel(const float* __restrict__ w,
                                    uint4* __restrict__ Whi, uint4* __restrict__ Wlo,
                                    int C, int H, int BN) {
    int COUT = 2 * H;
    int i = blockIdx.x * blockDim.x + threadIdx.x;
    if (i >= C * COUT) return;
    int k = i / COUT, n = i % COUT;
    float val = (n < H) ? (w[k * H + n] - w[(k + C) * H + n])
                        : w[(k + C) * H + (n - H)];
    __nv_bfloat16 hb = __float2bfloat16(val);
    __nv_bfloat16 lb = __float2bfloat16(val - __bfloat162float(hb));
    int NCH = C >> 6;
    int tile = n / BN, nl = n % BN, c = k >> 6, kl = k & 63;
    size_t off = ((size_t)(tile * NCH + c) * BN + nl) * 72 + kl;
    ((unsigned short*)Whi)[off] = __bfloat16_as_ushort(hb);
    ((unsigned short*)Wlo)[off] = __bfloat16_as_ushort(lb);
}

// ---- layer-1 node precompute fused with wc1 prep + agg clear ------------------
__global__ void node1_fused_kernel(const float* __restrict__ x,
                                   const float* __restrict__ w1a,
                                   const float* __restrict__ b1a,
                                   float* __restrict__ AB,
                                   unsigned* __restrict__ agg, int M) {
    int idx = blockIdx.x * blockDim.x + threadIdx.x;
    if (idx >= M * 128) return;
    if (idx < M * 64) agg[idx] = 0u;
    int n = idx >> 7, j = idx & 127;
    float wk0, wk1, wk2, bb;
    if (j < 64) {
        wk0 = w1a[0 * 64 + j] - w1a[3 * 64 + j];
        wk1 = w1a[1 * 64 + j] - w1a[4 * 64 + j];
        wk2 = w1a[2 * 64 + j] - w1a[5 * 64 + j];
        bb  = b1a[j];
    } else {
        int jj = j - 64;
        wk0 = w1a[3 * 64 + jj];
        wk1 = w1a[4 * 64 + jj];
        wk2 = w1a[5 * 64 + jj];
        bb  = 0.f;
    }
    float x0 = x[n * 3 + 0], x1 = x[n * 3 + 1], x2 = x[n * 3 + 2];
    AB[idx] = fmaf(x0, wk0, fmaf(x1, wk1, fmaf(x2, wk2, bb)));
}

// ---- dense bf16x3 mma GEMM: C = act(A @ W + [bias|0]) --------------------------
// bias covers columns [0, HB); columns >= HB get 0 (node-GEMM [b|0] layout).
template <int K, int BN, bool RELU, int MT>
__global__ void __launch_bounds__(256, 2)
dense_mma_kernel(const float* __restrict__ A, int lda,
                 const uint4* __restrict__ Whi_g, const uint4* __restrict__ Wlo_g,
                 const float* __restrict__ bias, int HB,
                 float* __restrict__ C, int ldc, int M) {
    constexpr int NCH = K / 64;
    static_assert(MT == 1 || NCH == 1, "MT>1 requires single-chunk K");
    constexpr int NA  = BN / 16;
    constexpr int WSZ = BN * 144;
    constexpr int ASZ = 128 * 144;
    constexpr int OA  = 2 * WSZ;
    constexpr int WCNT = BN * 9;

    extern __shared__ char sm[];
    const uint32_t smb = smem_u32(sm);

    const int tid = threadIdx.x;
    const int wid = tid >> 5, lane = tid & 31;
    const int g = lane >> 2, tig = lane & 3;
    const int bmb = blockIdx.x * (128 * MT);
    const int bn = blockIdx.y * BN;

    const int r  = tid >> 1;
    const int hf = tid & 1;

    const int wm = wid >> 1, wn = wid & 1;
    const int m0 = wm * 32, n0 = wn * (BN / 2);

    const int lr = lane & 7;
    const uint32_t a_off =
        (uint32_t)(m0 + lr + ((lane >> 3) & 1) * 8) * 144u + (uint32_t)(lane >> 4) * 16u;
    const uint32_t w_off =
        (uint32_t)(n0 + lr + ((lane >> 4) & 1) * 8) * 144u + (uint32_t)((lane >> 3) & 1) * 16u;

    const uint32_t WhU = smb;
    const uint32_t WlU = WhU + WSZ;
    const uint32_t AhU = smb + OA;
    const uint32_t AlU = AhU + ASZ;
    char* Ah = sm + OA;
    char* Al = sm + OA + ASZ;

    for (int mt = 0; mt < MT; mt++) {
        const int bm = bmb + mt * 128;
        const bool rv = (bm + r) < M;
        const float* Arow = A + (size_t)(bm + r) * lda + hf * 32;

        float acc[2][NA][4];
#pragma unroll
        for (int ma = 0; ma < 2; ma++)
#pragma unroll
            for (int na = 0; na < NA; na++)
#pragma unroll
                for (int q = 0; q < 4; q++) acc[ma][na][q] = 0.f;

        for (int c = 0; c < NCH; c++) {
            if (c || mt) __syncthreads();
            if (mt == 0) {
                const char* shp = (const char*)(Whi_g + (size_t)(blockIdx.y * NCH + c) * WCNT);
                const char* slp = (const char*)(Wlo_g + (size_t)(blockIdx.y * NCH + c) * WCNT);
                for (int i = tid; i < WCNT; i += 256) {
                    cp16(WhU + i * 16, shp + i * 16);
                    cp16(WlU + i * 16, slp + i * 16);
                }
                asm volatile("cp.async.commit_group;" ::: "memory");
            }
            {
                const float4* Ap = (const float4*)(Arow + c * 64);
                float v[32];
                if (rv) {
#pragma unroll
                    for (int q = 0; q < 8; q++) {
                        float4 a = Ap[q];
                        v[q * 4 + 0] = a.x; v[q * 4 + 1] = a.y;
                        v[q * 4 + 2] = a.z; v[q * 4 + 3] = a.w;
                    }
                } else {
#pragma unroll
                    for (int q = 0; q < 32; q++) v[q] = 0.f;
                }
                char* ah = Ah + r * 144 + hf * 64;
                char* al = Al + r * 144 + hf * 64;
#pragma unroll
                for (int q8 = 0; q8 < 4; q8++) {
                    uint32_t uh[4], ul[4];
#pragma unroll
                    for (int p = 0; p < 4; p++)
                        split2(v[q8 * 8 + p * 2], v[q8 * 8 + p * 2 + 1], uh[p], ul[p]);
                    *(uint4*)(ah + q8 * 16) = make_uint4(uh[0], uh[1], uh[2], uh[3]);
                    *(uint4*)(al + q8 * 16) = make_uint4(ul[0], ul[1], ul[2], ul[3]);
                }
            }
            asm volatile("cp.async.wait_group 0;" ::: "memory");
            __syncthreads();

#pragma unroll
            for (int kq = 0; kq < 4; kq++) {
                uint32_t ah[2][4], al[2][4];
#pragma unroll
                for (int ma = 0; ma < 2; ma++) {
                    ldsm_x4(ah[ma], AhU + a_off + (uint32_t)(ma * 16 * 144 + kq * 32));
                    ldsm_x4(al[ma], AlU + a_off + (uint32_t)(ma * 16 * 144 + kq * 32));
                }
#pragma unroll
                for (int n2 = 0; n2 < NA / 2; n2++) {
                    uint32_t wh[4], wl[4];
                    ldsm_x4(wh, WhU + w_off + (uint32_t)(n2 * 16 * 144 + kq * 32));
                    ldsm_x4(wl, WlU + w_off + (uint32_t)(n2 * 16 * 144 + kq * 32));
#pragma unroll
                    for (int j = 0; j < 2; j++) {
                        const int na = n2 * 2 + j;
                        mma_bf16(acc[0][na], ah[0], wh[2 * j], wh[2 * j + 1]);
                        mma_bf16(acc[1][na], ah[1], wh[2 * j], wh[2 * j + 1]);
                        mma_bf16(acc[0][na], al[0], wh[2 * j], wh[2 * j + 1]);
                        mma_bf16(acc[1][na], al[1], wh[2 * j], wh[2 * j + 1]);
                        mma_bf16(acc[0][na], ah[0], wl[2 * j], wl[2 * j + 1]);
                        mma_bf16(acc[1][na], ah[1], wl[2 * j], wl[2 * j + 1]);
                    }
                }
            }
        }

#pragma unroll
        for (int ma = 0; ma < 2; ma++) {
#pragma unroll
            for (int rr = 0; rr < 2; rr++) {
                const int rg = bm + m0 + ma * 16 + g + rr * 8;
                if (rg >= M) continue;
                float* crow = C + (size_t)rg * ldc + bn;
#pragma unroll
                for (int na = 0; na < NA; na++) {
                    const int j = n0 + na * 8 + 2 * tig;
                    float b0 = (bn + j     < HB) ? bias[bn + j]     : 0.f;
                    float b1 = (bn + j + 1 < HB) ? bias[bn + j + 1] : 0.f;
                    float v0 = acc[ma][na][rr * 2 + 0] + b0;
                    float v1 = acc[ma][na][rr * 2 + 1] + b1;
                    if (RELU) { v0 = fmaxf(v0, 0.f); v1 = fmaxf(v1, 0.f); }
                    *(float2*)(crow + j) = make_float2(v0, v1);
                }
            }
        }
    }
}

// ---- mma.sync edge kernel: sorted edges, MT m-tiles, bias post-max ------------
template <int H, int BN, int MINB, int MT>
__global__ void __launch_bounds__(256, MINB)
edge_mma_kernel(const float* __restrict__ AB,
                const uint4* __restrict__ Whi_g, const uint4* __restrict__ Wlo_g,
                unsigned* __restrict__ agg, int E, int COUT) {
    constexpr int NCH = H / 64;
    static_assert(MT == 1 || NCH == 1, "MT>1 requires single-chunk K");
    constexpr int NA  = BN / 16;
    constexpr int WSZ = BN * 144;
    constexpr int ASZ = 128 * 144;
    constexpr int OW  = 2048;
    constexpr int OA  = OW + 2 * WSZ;
    constexpr int WCNT = BN * 9;

    extern __shared__ char sm[];
    const uint32_t smb = smem_u32(sm);
    int* sdst = (int*)sm;            // MT*128 ints
    int* ssrc = (int*)(sm + 1024);   // MT*128 ints

    const int tid = threadIdx.x;
    const int wid = tid >> 5, lane = tid & 31;
    const int g = lane >> 2, tig = lane & 3;
    const int e0b = blockIdx.x * (128 * MT);
    const int bn = blockIdx.y * BN;

    for (int i = tid; i < 128 * MT; i += 256) {
        int e = e0b + i;
        ssrc[i] = (e < E) ? g_srcS[e] : 0;
        sdst[i] = (e < E) ? g_dstS[e] : 0;
    }
    __syncthreads();

    const int r  = tid >> 1;
    const int hf = tid & 1;

    const int wm = wid >> 1, wn = wid & 1;
    const int m0 = wm * 32, n0 = wn * (BN / 2);

    const int lr = lane & 7;
    const uint32_t a_off =
        (uint32_t)(m0 + lr + ((lane >> 3) & 1) * 8) * 144u + (uint32_t)(lane >> 4) * 16u;
    const uint32_t w_off =
        (uint32_t)(n0 + lr + ((lane >> 4) & 1) * 8) * 144u + (uint32_t)((lane >> 3) & 1) * 16u;

    const uint32_t WhU = smb + OW;
    const uint32_t WlU = WhU + WSZ;
    const uint32_t AhU = smb + OA;
    const uint32_t AlU = AhU + ASZ;
    char* Ah = sm + OA;
    char* Al = sm + OA + ASZ;

    for (int mt = 0; mt < MT; mt++) {
        const int rb = mt * 128;
        const float* Arow = AB + (size_t)sdst[rb + r] * (2 * H) + hf * 32;
        const float* Brow = AB + (size_t)ssrc[rb + r] * (2 * H) + H + hf * 32;

        float acc[2][NA][4];
#pragma unroll
        for (int ma = 0; ma < 2; ma++)
#pragma unroll
            for (int na = 0; na < NA; na++)
#pragma unroll
                for (int q = 0; q < 4; q++) acc[ma][na][q] = 0.f;

        float4 pre[4];
#pragma unroll
        for (int q = 0; q < 4; q++) pre[q] = ((const float4*)Brow)[q];

        for (int c = 0; c < NCH; c++) {
            if (c || mt) __syncthreads();
            if (mt == 0) {
                const char* shp = (const char*)(Whi_g + (size_t)(blockIdx.y * NCH + c) * WCNT);
                const char* slp = (const char*)(Wlo_g + (size_t)(blockIdx.y * NCH + c) * WCNT);
                for (int i = tid; i < WCNT; i += 256) {
                    cp16(WhU + i * 16, shp + i * 16);
                    cp16(WlU + i * 16, slp + i * 16);
                }
                asm volatile("cp.async.commit_group;" ::: "memory");
            }
            {
                const float4* Ap = (const float4*)(Arow + c * 64);
                const float4* Bp = (const float4*)(Brow + c * 64);
                float v[32];
#pragma unroll
                for (int q = 0; q < 4; q++) {
                    float4 a = Ap[q], b = pre[q];
                    v[q * 4 + 0] = fmaxf(a.x + b.x, 0.f);
                    v[q * 4 + 1] = fmaxf(a.y + b.y, 0.f);
                    v[q * 4 + 2] = fmaxf(a.z + b.z, 0.f);
                    v[q * 4 + 3] = fmaxf(a.w + b.w, 0.f);
                }
#pragma unroll
                for (int q = 4; q < 8; q++) {
                    float4 a = Ap[q], b = Bp[q];
                    v[q * 4 + 0] = fmaxf(a.x + b.x, 0.f);
                    v[q * 4 + 1] = fmaxf(a.y + b.y, 0.f);
                    v[q * 4 + 2] = fmaxf(a.z + b.z, 0.f);
                    v[q * 4 + 3] = fmaxf(a.w + b.w, 0.f);
                }
                if (c + 1 < NCH) {
                    const float4* Bn = (const float4*)(Brow + (c + 1) * 64);
#pragma unroll
                    for (int q = 0; q < 4; q++) pre[q] = Bn[q];
                }
                char* ah = Ah + r * 144 + hf * 64;
                char* al = Al + r * 144 + hf * 64;
#pragma unroll
                for (int q8 = 0; q8 < 4; q8++) {
                    uint32_t uh[4], ul[4];
#pragma unroll
                    for (int p = 0; p < 4; p++)
                        split2(v[q8 * 8 + p * 2], v[q8 * 8 + p * 2 + 1], uh[p], ul[p]);
                    *(uint4*)(ah + q8 * 16) = make_uint4(uh[0], uh[1], uh[2], uh[3]);
                    *(uint4*)(al + q8 * 16) = make_uint4(ul[0], ul[1], ul[2], ul[3]);
                }
            }
            asm volatile("cp.async.wait_group 0;" ::: "memory");
            __syncthreads();

#pragma unroll
            for (int kq = 0; kq < 4; kq++) {
                uint32_t ah[2][4], al[2][4];
#pragma unroll
                for (int ma = 0; ma < 2; ma++) {
                    ldsm_x4(ah[ma], AhU + a_off + (uint32_t)(ma * 16 * 144 + kq * 32));
                    ldsm_x4(al[ma], AlU + a_off + (uint32_t)(ma * 16 * 144 + kq * 32));
                }
#pragma unroll
                for (int n2 = 0; n2 < NA / 2; n2++) {
                    uint32_t wh[4], wl[4];
                    ldsm_x4(wh, WhU + w_off + (uint32_t)(n2 * 16 * 144 + kq * 32));
                    ldsm_x4(wl, WlU + w_off + (uint32_t)(n2 * 16 * 144 + kq * 32));
#pragma unroll
                    for (int j = 0; j < 2; j++) {
                        const int na = n2 * 2 + j;
                        mma_bf16(acc[0][na], ah[0], wh[2 * j], wh[2 * j + 1]);
                        mma_bf16(acc[1][na], ah[1], wh[2 * j], wh[2 * j + 1]);
                        mma_bf16(acc[0][na], al[0], wh[2 * j], wh[2 * j + 1]);
                        mma_bf16(acc[1][na], al[1], wh[2 * j], wh[2 * j + 1]);
                        mma_bf16(acc[0][na], ah[0], wl[2 * j], wl[2 * j + 1]);
                        mma_bf16(acc[1][na], ah[1], wl[2 * j], wl[2 * j + 1]);
                    }
                }
            }
        }

#pragma unroll
        for (int ma = 0; ma < 2; ma++) {
#pragma unroll
            for (int rr = 0; rr < 2; rr++) {
                const int rloc = m0 + ma * 16 + g + rr * 8;
                if (e0b + rb + rloc >= E) continue;
                const int d = sdst[rb + rloc];
                unsigned* arow = agg + (size_t)d * COUT + bn;
#pragma unroll
                for (int na = 0; na < NA; na++) {
                    const int j = n0 + na * 8 + 2 * tig;
                    unsigned k0 = f2ord(acc[ma][na][rr * 2 + 0]);
                    unsigned k1 = f2ord(acc[ma][na][rr * 2 + 1]);
                    uint2 cur = *(const uint2*)(arow + j);
                    if (k0 > cur.x) atomicMax(arow + j, k0);
                    if (k1 > cur.y) atomicMax(arow + j + 1, k1);
                }
            }
        }
    }
}

// ---- decode agg (+bias post-max) -> float, then clear agg in-place ------------
// Each thread reads agg[i] (if decoding) before writing agg[i]=0 (if clearing):
// same index, program-ordered, race-free.
__global__ void decode_clear_kernel(unsigned* __restrict__ agg,
                                    const float* __restrict__ bias,
                                    float* __restrict__ dsth, int total, int C, int ldc,
                                    int clrN) {
    int i = blockIdx.x * blockDim.x + threadIdx.x;
    if (i < total) {
        int n = i / C, c = i % C;
        unsigned u = agg[i];
        dsth[(size_t)n * ldc + c] = (u == 0u) ? 0.f : (ord2f(u) + bias[c]);
    }
    if (i < clrN) agg[i] = 0u;
}

// ---- final 256 -> 4 linear ------------------------------------------------------
__global__ void mlp3_kernel(const float* __restrict__ A, const float* __restrict__ W,
                            const float* __restrict__ b, float* __restrict__ out, int M) {
    int gw = (blockIdx.x * blockDim.x + threadIdx.x) >> 5;
    int lane = threadIdx.x & 31;
    if (gw >= M) return;
    const float* a = A + (size_t)gw * 256;
    float acc0 = 0.f, acc1 = 0.f, acc2 = 0.f, acc3 = 0.f;
    for (int k = lane; k < 256; k += 32) {
        float av = a[k];
        const float* wr = W + k * 4;
        acc0 = fmaf(av, wr[0], acc0);
        acc1 = fmaf(av, wr[1], acc1);
        acc2 = fmaf(av, wr[2], acc2);
        acc3 = fmaf(av, wr[3], acc3);
    }
#pragma unroll
    for (int off = 16; off > 0; off >>= 1) {
        acc0 += __shfl_down_sync(0xffffffffu, acc0, off);
        acc1 += __shfl_down_sync(0xffffffffu, acc1, off);
        acc2 += __shfl_down_sync(0xffffffffu, acc2, off);
        acc3 += __shfl_down_sync(0xffffffffu, acc3, off);
    }
    if (lane == 0) {
        out[gw * 4 + 0] = acc0 + b[0];
        out[gw * 4 + 1] = acc1 + b[1];
        out[gw * 4 + 2] = acc2 + b[2];
        out[gw * 4 + 3] = acc3 + b[3];
    }
}

// ---------------------------------------------------------------------------
extern "C" void kernel_launch(void* const* d_in, const int* in_sizes, int n_in,
                              void* d_out, int out_size) {
    const float* x   = (const float*)d_in[0];
    const void*  ei  = d_in[1];
    const float* w1a = (const float*)d_in[3];
    const float* b1a = (const float*)d_in[4];
    const float* w1b = (const float*)d_in[5];
    const float* b1b = (const float*)d_in[6];
    const float* w2a = (const float*)d_in[7];
    const float* b2a = (const float*)d_in[8];
    const float* w2b = (const float*)d_in[9];
    const float* b2b = (const float*)d_in[10];
    const float* w3a = (const float*)d_in[11];
    const float* b3a = (const float*)d_in[12];
    const float* w3b = (const float*)d_in[13];
    const float* b3b = (const float*)d_in[14];
    const float* wm1 = (const float*)d_in[15];
    const float* bm1 = (const float*)d_in[16];
    const float* wm2 = (const float*)d_in[17];
    const float* bm2 = (const float*)d_in[18];
    const float* wm3 = (const float*)d_in[19];
    const float* bm3 = (const float*)d_in[20];

    const int Nn = in_sizes[0] / 3;
    const int E  = in_sizes[1] / 2;
    float* out = (float*)d_out;

    float *AB, *hcat, *m1, *m2;
    unsigned* agg;
    uint4 *wh1, *wl1, *wh2, *wl2, *wh3, *wl3;
    uint4 *whn2, *wln2, *whn3, *wln3, *whm1, *wlm1, *whm2, *wlm2;
    cudaGetSymbolAddress((void**)&AB,   g_AB);
    cudaGetSymbolAddress((void**)&agg,  g_agg);
    cudaGetSymbolAddress((void**)&hcat, g_hcat);
    cudaGetSymbolAddress((void**)&m1,   g_m1);
    cudaGetSymbolAddress((void**)&m2,   g_m2);
    cudaGetSymbolAddress((void**)&wh1,  g_wh1);
    cudaGetSymbolAddress((void**)&wl1,  g_wl1);
    cudaGetSymbolAddress((void**)&wh2,  g_wh2);
    cudaGetSymbolAddress((void**)&wl2,  g_wl2);
    cudaGetSymbolAddress((void**)&wh3,  g_wh3);
    cudaGetSymbolAddress((void**)&wl3,  g_wl3);
    cudaGetSymbolAddress((void**)&whn2, g_whn2);
    cudaGetSymbolAddress((void**)&wln2, g_wln2);
    cudaGetSymbolAddress((void**)&whn3, g_whn3);
    cudaGetSymbolAddress((void**)&wln3, g_wln3);
    cudaGetSymbolAddress((void**)&whm1, g_whm1);
    cudaGetSymbolAddress((void**)&wlm1, g_wlm1);
    cudaGetSymbolAddress((void**)&whm2, g_whm2);
    cudaGetSymbolAddress((void**)&wlm2, g_wlm2);

    const int SM1 = 2048 + 2 * (64  * 144) + 2 * 18432;  // 57344
    const int SM2 = 2048 + 2 * (128 * 144) + 2 * 18432;  // 75776
    const int SMD = 2 * (128 * 144) + 2 * 18432;         // 73728
    cudaFuncSetAttribute(edge_mma_kernel<64, 64, 3, 2>,   cudaFuncAttributeMaxDynamicSharedMemorySize, SM1);
    cudaFuncSetAttribute(edge_mma_kernel<128, 128, 2, 1>, cudaFuncAttributeMaxDynamicSharedMemorySize, SM2);
    cudaFuncSetAttribute(edge_mma_kernel<256, 128, 2, 1>, cudaFuncAttributeMaxDynamicSharedMemorySize, SM2);
    cudaFuncSetAttribute(dense_mma_kernel<64,  128, false, 2>, cudaFuncAttributeMaxDynamicSharedMemorySize, SMD);
    cudaFuncSetAttribute(dense_mma_kernel<128, 128, false, 1>, cudaFuncAttributeMaxDynamicSharedMemorySize, SMD);
    cudaFuncSetAttribute(dense_mma_kernel<448, 128, true, 1>,  cudaFuncAttributeMaxDynamicSharedMemorySize, SMD);
    cudaFuncSetAttribute(dense_mma_kernel<512, 128, true, 1>,  cudaFuncAttributeMaxDynamicSharedMemorySize, SMD);

    const int TB = 256;
    dim3 blk(TB);
    const int gx   = (Nn + 127) / 128;
    const int gx2  = (Nn + 255) / 256;
    const int egx  = (E + 127) / 128;
    const int egx2 = (E + 255) / 256;

    // ---- edge sort by dst (counting sort; segment-max is order-invariant) ----
    convert_idx_kernel<<<(E + TB - 1) / TB, blk>>>((const unsigned*)ei, E);
    hist_kernel<<<(E + TB - 1) / TB, blk>>>(E);
    scan_kernel<<<1, 1024>>>();
    scatter_kernel<<<(E + TB - 1) / TB, blk>>>(E);

    // ---- EdgeConv 1: 3 -> 64 ----
    prep_wb_kernel<<<(64 * 64 + TB - 1) / TB, blk>>>(w1b, wh1, wl1, 64, 64, 64);
    node1_fused_kernel<<<(Nn * 128 + TB - 1) / TB, blk>>>(x, w1a, b1a, AB, agg, Nn);
    edge_mma_kernel<64, 64, 3, 2><<<dim3(egx2, 1), blk, SM1>>>(AB, wh1, wl1, agg, E, 64);

    // ---- EdgeConv 2: 64 -> 128 ----
    prep_wb_node_kernel<<<(64 * 256 + TB - 1) / TB, blk>>>(w2a, whn2, wln2, 64, 128, 128);
    prep_wb_kernel<<<(128 * 128 + TB - 1) / TB, blk>>>(w2b, wh2, wl2, 128, 128, 128);
    decode_clear_kernel<<<(Nn * 128 + TB - 1) / TB, blk>>>(agg, b1b, hcat + 0, Nn * 64, 64, 448, Nn * 128);
    dense_mma_kernel<64, 128, false, 2><<<dim3(gx2, 2), blk, SMD>>>(hcat, 448, whn2, wln2, b2a, 128, AB, 256, Nn);
    edge_mma_kernel<128, 128, 2, 1><<<dim3(egx, 1), blk, SM2>>>(AB, wh2, wl2, agg, E, 128);

    // ---- EdgeConv 3: 128 -> 256 ----
    prep_wb_node_kernel<<<(128 * 512 + TB - 1) / TB, blk>>>(w3a, whn3, wln3, 128, 256, 128);
    prep_wb_kernel<<<(256 * 256 + TB - 1) / TB, blk>>>(w3b, wh3, wl3, 256, 256, 128);
    decode_clear_kernel<<<(Nn * 256 + TB - 1) / TB, blk>>>(agg, b2b, hcat + 64, Nn * 128, 128, 448, Nn * 256);
    dense_mma_kernel<128, 128, false, 1><<<dim3(gx, 4), blk, SMD>>>(hcat + 64, 448, whn3, wln3, b3a, 256, AB, 512, Nn);
    edge_mma_kernel<256, 128, 2, 1><<<dim3(egx, 2), blk, SM2>>>(AB, wh3, wl3, agg, E, 256);
    decode_clear_kernel<<<(Nn * 256 + TB - 1) / TB, blk>>>(agg, b3b, hcat + 192, Nn * 256, 256, 448, 0);

    // ---- MLP head ----
    prep_wb_kernel<<<(448 * 512 + TB - 1) / TB, blk>>>(wm1, whm1, wlm1, 448, 512, 128);
    dense_mma_kernel<448, 128, true, 1><<<dim3(gx, 4), blk, SMD>>>(hcat, 448, whm1, wlm1, bm1, 512, m1, 512, Nn);
    prep_wb_kernel<<<(512 * 256 + TB - 1) / TB, blk>>>(wm2, whm2, wlm2, 512, 256, 128);
    dense_mma_kernel<512, 128, true, 1><<<dim3(gx, 2), blk, SMD>>>(m1, 512, whm2, wlm2, bm2, 256, m2, 256, Nn);
    mlp3_kernel<<<(Nn * 32 + TB - 1) / TB, blk>>>(m2, wm3, bm3, out, Nn);
}

// round 15
// speedup vs baseline: 1.0818x; 1.0095x over previous
#include <cuda_runtime.h>
#include <cuda_bf16.h>
#include <cstdint>

// ---------------------------------------------------------------------------
// DGCNN segmentation. ALL GEMMs on tensor cores via mma.sync bf16x3 split
// precision (ldmatrix frags, cp.async.cg W streaming, 64-wide K chunks).
// Edges counting-sorted by dst. Bias applied after segment-max (exact).
// Launch-compressed: single prep_all kernel (all weights + bin zeroing),
// hist fused into convert, fused decode+clear, inline node-weight combine.
// ---------------------------------------------------------------------------

#define NMAX 30016
#define EMAX 480256
#define NBIN 30720   // 1024 * 30

__device__ float    g_AB[NMAX * 512];
__device__ unsigned g_agg[NMAX * 256];
__device__ float    g_hcat[NMAX * 448];
__device__ float    g_m1[NMAX * 512];
__device__ float    g_m2[NMAX * 256];
__device__ uint4    g_wh1[64 * 72 / 8],       g_wl1[64 * 72 / 8];
__device__ uint4    g_wh2[2 * 128 * 72 / 8],  g_wl2[2 * 128 * 72 / 8];
__device__ uint4    g_wh3[8 * 128 * 72 / 8],  g_wl3[8 * 128 * 72 / 8];
__device__ uint4    g_whn2[2304],  g_wln2[2304];
__device__ uint4    g_whn3[9216],  g_wln3[9216];
__device__ uint4    g_whm1[32256], g_wlm1[32256];
__device__ uint4    g_whm2[18432], g_wlm2[18432];
__device__ int      g_src[EMAX];
__device__ int      g_dst[EMAX];
__device__ int      g_srcS[EMAX];   // sorted by dst
__device__ int      g_dstS[EMAX];
__device__ int      g_cnt[NBIN];
__device__ int      g_c2[NBIN];
__device__ int      g_start[NBIN];

// ---- ordered-uint encoding for float max ------------------------------------
__device__ __forceinline__ unsigned f2ord(float f) {
    int i = __float_as_int(f);
    return (i >= 0) ? ((unsigned)i | 0x80000000u) : ~(unsigned)i;
}
__device__ __forceinline__ float ord2f(unsigned u) {
    int i = (u & 0x80000000u) ? (int)(u & 0x7fffffffu) : (int)(~u);
    return __int_as_float(i);
}

// ---- PTX helpers --------------------------------------------------------------
__device__ __forceinline__ uint32_t smem_u32(const void* p) {
    uint32_t a;
    asm("{ .reg .u64 t; cvta.to.shared.u64 t, %1; cvt.u32.u64 %0, t; }" : "=r"(a) : "l"(p));
    return a;
}
__device__ __forceinline__ void mma_bf16(float* d, const uint32_t* a,
                                         uint32_t b0, uint32_t b1) {
    asm volatile(
        "mma.sync.aligned.m16n8k16.row.col.f32.bf16.bf16.f32 "
        "{%0,%1,%2,%3},{%4,%5,%6,%7},{%8,%9},{%0,%1,%2,%3};"
        : "+f"(d[0]), "+f"(d[1]), "+f"(d[2]), "+f"(d[3])
        : "r"(a[0]), "r"(a[1]), "r"(a[2]), "r"(a[3]), "r"(b0), "r"(b1));
}
__device__ __forceinline__ void ldsm_x4(uint32_t* r, uint32_t addr) {
    asm volatile("ldmatrix.sync.aligned.m8n8.x4.shared.b16 {%0,%1,%2,%3},[%4];"
                 : "=r"(r[0]), "=r"(r[1]), "=r"(r[2]), "=r"(r[3]) : "r"(addr));
}
__device__ __forceinline__ void cp16(uint32_t s, const void* g) {
    asm volatile("cp.async.cg.shared.global [%0],[%1],16;" :: "r"(s), "l"(g));
}
__device__ __forceinline__ void split2(float m0, float m1, uint32_t& hi2, uint32_t& lo2) {
    asm("cvt.rn.bf16x2.f32 %0, %1, %2;" : "=r"(hi2) : "f"(m1), "f"(m0));
    float h0 = __uint_as_float(hi2 << 16);
    float h1 = __uint_as_float(hi2 & 0xffff0000u);
    float l0 = m0 - h0, l1 = m1 - h1;
    asm("cvt.rn.bf16x2.f32 %0, %1, %2;" : "=r"(lo2) : "f"(l1), "f"(l0));
}

// ---- weight conversion helpers -------------------------------------------------
__device__ __forceinline__ void store_wb(float val, int k, int n, int NCH, int BN,
                                         uint4* Whi, uint4* Wlo) {
    __nv_bfloat16 hb = __float2bfloat16(val);
    __nv_bfloat16 lb = __float2bfloat16(val - __bfloat162float(hb));
    int tile = n / BN, nl = n % BN, c = k >> 6, kl = k & 63;
    size_t off = ((size_t)(tile * NCH + c) * BN + nl) * 72 + kl;
    ((unsigned short*)Whi)[off] = __bfloat16_as_ushort(hb);
    ((unsigned short*)Wlo)[off] = __bfloat16_as_ushort(lb);
}
__device__ __forceinline__ void prep_std(const float* W, int idx, int COUT, int H,
                                         int BN, uint4* Whi, uint4* Wlo) {
    int k = idx / COUT, n = idx % COUT;
    store_wb(W[idx], k, n, H >> 6, BN, Whi, Wlo);
}
__device__ __forceinline__ void prep_node(const float* w, int idx, int C, int H,
                                          int BN, uint4* Whi, uint4* Wlo) {
    int COUT = 2 * H;
    int k = idx / COUT, n = idx % COUT;
    float val = (n < H) ? (w[k * H + n] - w[(k + C) * H + n])
                        : w[(k + C) * H + (n - H)];
    store_wb(val, k, n, C >> 6, BN, Whi, Wlo);
}

// ---- one-shot prep: all weight conversions + sort-bin zeroing ------------------
// segments (cumulative):  wb1 4096 | wbn2 16384 | wb2 16384 | wbn3 65536 |
//                         wb3 65536 | wbm1 229376 | wbm2 131072   = 528384
__global__ void prep_all_kernel(const float* __restrict__ w1b,
                                const float* __restrict__ w2a,
                                const float* __restrict__ w2b,
                                const float* __restrict__ w3a,
                                const float* __restrict__ w3b,
                                const float* __restrict__ wm1,
                                const float* __restrict__ wm2) {
    int i = blockIdx.x * blockDim.x + threadIdx.x;
    if (i < NBIN) { g_cnt[i] = 0; g_c2[i] = 0; }
    int j = i;
    if (j < 4096)            { prep_std (w1b, j, 64, 64, 64, g_wh1, g_wl1); return; }
    j -= 4096;
    if (j < 16384)           { prep_node(w2a, j, 64, 128, 128, g_whn2, g_wln2); return; }
    j -= 16384;
    if (j < 16384)           { prep_std (w2b, j, 128, 128, 128, g_wh2, g_wl2); return; }
    j -= 16384;
    if (j < 65536)           { prep_node(w3a, j, 128, 256, 128, g_whn3, g_wln3); return; }
    j -= 65536;
    if (j < 65536)           { prep_std (w3b, j, 256, 256, 128, g_wh3, g_wl3); return; }
    j -= 65536;
    if (j < 229376)          { prep_std (wm1, j, 512, 448, 128, g_whm1, g_wlm1); return; }
    j -= 229376;
    if (j < 131072)          { prep_std (wm2, j, 256, 512, 128, g_whm2, g_wlm2); return; }
}

// ---- edge index convert + histogram (bins pre-zeroed by prep_all) --------------
__global__ void convert_idx_kernel(const unsigned* __restrict__ raw, int E) {
    int n = (E < 256) ? E : 256;
    int is64 = 1;
    for (int i = 0; i < n; i++)
        if (raw[2 * i + 1] != 0u) { is64 = 0; break; }
    int i = blockIdx.x * blockDim.x + threadIdx.x;
    if (i >= E) return;
    int s, d;
    if (is64) {
        const long long* p = (const long long*)raw;
        s = (int)p[i]; d = (int)p[E + i];
    } else {
        const int* p = (const int*)raw;
        s = p[i]; d = p[E + i];
    }
    g_src[i] = s;
    g_dst[i] = d;
    atomicAdd(&g_cnt[d], 1);
}
__global__ void scan_kernel() {   // 1 block, 1024 threads, 30 bins each
    __shared__ int part[1024];
    int t = threadIdx.x;
    int base = t * 30;
    int s = 0;
#pragma unroll
    for (int j = 0; j < 30; j++) s += g_cnt[base + j];
    part[t] = s;
    __syncthreads();
    for (int off = 1; off < 1024; off <<= 1) {
        int v = (t >= off) ? part[t - off] : 0;
        __syncthreads();
        part[t] += v;
        __syncthreads();
    }
    int run = part[t] - s;
#pragma unroll
    for (int j = 0; j < 30; j++) {
        g_start[base + j] = run;
        run += g_cnt[base + j];
    }
}
__global__ void scatter_kernel(int E) {
    int i = blockIdx.x * blockDim.x + threadIdx.x;
    if (i >= E) return;
    int d = g_dst[i];
    int pos = g_start[d] + atomicAdd(&g_c2[d], 1);
    g_srcS[pos] = g_src[i];
    g_dstS[pos] = d;
}

// ---- layer-1 node precompute fused with wc1 prep + agg clear ------------------
__global__ void node1_fused_kernel(const float* __restrict__ x,
                                   const float* __restrict__ w1a,
                                   const float* __restrict__ b1a,
                                   float* __restrict__ AB,
                                   unsigned* __restrict__ agg, int M) {
    int idx = blockIdx.x * blockDim.x + threadIdx.x;
    if (idx >= M * 128) return;
    if (idx < M * 64) agg[idx] = 0u;
    int n = idx >> 7, j = idx & 127;
    float wk0, wk1, wk2, bb;
    if (j < 64) {
        wk0 = w1a[0 * 64 + j] - w1a[3 * 64 + j];
        wk1 = w1a[1 * 64 + j] - w1a[4 * 64 + j];
        wk2 = w1a[2 * 64 + j] - w1a[5 * 64 + j];
        bb  = b1a[j];
    } else {
        int jj = j - 64;
        wk0 = w1a[3 * 64 + jj];
        wk1 = w1a[4 * 64 + jj];
        wk2 = w1a[5 * 64 + jj];
        bb  = 0.f;
    }
    float x0 = x[n * 3 + 0], x1 = x[n * 3 + 1], x2 = x[n * 3 + 2];
    AB[idx] = fmaf(x0, wk0, fmaf(x1, wk1, fmaf(x2, wk2, bb)));
}

// ---- dense bf16x3 mma GEMM: C = act(A @ W + [bias|0]) --------------------------
template <int K, int BN, bool RELU, int MT>
__global__ void __launch_bounds__(256, 2)
dense_mma_kernel(const float* __restrict__ A, int lda,
                 const uint4* __restrict__ Whi_g, const uint4* __restrict__ Wlo_g,
                 const float* __restrict__ bias, int HB,
                 float* __restrict__ C, int ldc, int M) {
    constexpr int NCH = K / 64;
    static_assert(MT == 1 || NCH == 1, "MT>1 requires single-chunk K");
    constexpr int NA  = BN / 16;
    constexpr int WSZ = BN * 144;
    constexpr int ASZ = 128 * 144;
    constexpr int OA  = 2 * WSZ;
    constexpr int WCNT = BN * 9;

    extern __shared__ char sm[];
    const uint32_t smb = smem_u32(sm);

    const int tid = threadIdx.x;
    const int wid = tid >> 5, lane = tid & 31;
    const int g = lane >> 2, tig = lane & 3;
    const int bmb = blockIdx.x * (128 * MT);
    const int bn = blockIdx.y * BN;

    const int r  = tid >> 1;
    const int hf = tid & 1;

    const int wm = wid >> 1, wn = wid & 1;
    const int m0 = wm * 32, n0 = wn * (BN / 2);

    const int lr = lane & 7;
    const uint32_t a_off =
        (uint32_t)(m0 + lr + ((lane >> 3) & 1) * 8) * 144u + (uint32_t)(lane >> 4) * 16u;
    const uint32_t w_off =
        (uint32_t)(n0 + lr + ((lane >> 4) & 1) * 8) * 144u + (uint32_t)((lane >> 3) & 1) * 16u;

    const uint32_t WhU = smb;
    const uint32_t WlU = WhU + WSZ;
    const uint32_t AhU = smb + OA;
    const uint32_t AlU = AhU + ASZ;
    char* Ah = sm + OA;
    char* Al = sm + OA + ASZ;

    for (int mt = 0; mt < MT; mt++) {
        const int bm = bmb + mt * 128;
        const bool rv = (bm + r) < M;
        const float* Arow = A + (size_t)(bm + r) * lda + hf * 32;

        float acc[2][NA][4];
#pragma unroll
        for (int ma = 0; ma < 2; ma++)
#pragma unroll
            for (int na = 0; na < NA; na++)
#pragma unroll
                for (int q = 0; q < 4; q++) acc[ma][na][q] = 0.f;

        for (int c = 0; c < NCH; c++) {
            if (c || mt) __syncthreads();
            if (mt == 0) {
                const char* shp = (const char*)(Whi_g + (size_t)(blockIdx.y * NCH + c) * WCNT);
                const char* slp = (const char*)(Wlo_g + (size_t)(blockIdx.y * NCH + c) * WCNT);
                for (int i = tid; i < WCNT; i += 256) {
                    cp16(WhU + i * 16, shp + i * 16);
                    cp16(WlU + i * 16, slp + i * 16);
                }
                asm volatile("cp.async.commit_group;" ::: "memory");
            }
            {
                const float4* Ap = (const float4*)(Arow + c * 64);
                float v[32];
                if (rv) {
#pragma unroll
                    for (int q = 0; q < 8; q++) {
                        float4 a = Ap[q];
                        v[q * 4 + 0] = a.x; v[q * 4 + 1] = a.y;
                        v[q * 4 + 2] = a.z; v[q * 4 + 3] = a.w;
                    }
                } else {
#pragma unroll
                    for (int q = 0; q < 32; q++) v[q] = 0.f;
                }
                char* ah = Ah + r * 144 + hf * 64;
                char* al = Al + r * 144 + hf * 64;
#pragma unroll
                for (int q8 = 0; q8 < 4; q8++) {
                    uint32_t uh[4], ul[4];
#pragma unroll
                    for (int p = 0; p < 4; p++)
                        split2(v[q8 * 8 + p * 2], v[q8 * 8 + p * 2 + 1], uh[p], ul[p]);
                    *(uint4*)(ah + q8 * 16) = make_uint4(uh[0], uh[1], uh[2], uh[3]);
                    *(uint4*)(al + q8 * 16) = make_uint4(ul[0], ul[1], ul[2], ul[3]);
                }
            }
            asm volatile("cp.async.wait_group 0;" ::: "memory");
            __syncthreads();

#pragma unroll
            for (int kq = 0; kq < 4; kq++) {
                uint32_t ah[2][4], al[2][4];
#pragma unroll
                for (int ma = 0; ma < 2; ma++) {
                    ldsm_x4(ah[ma], AhU + a_off + (uint32_t)(ma * 16 * 144 + kq * 32));
                    ldsm_x4(al[ma], AlU + a_off + (uint32_t)(ma * 16 * 144 + kq * 32));
                }
#pragma unroll
                for (int n2 = 0; n2 < NA / 2; n2++) {
                    uint32_t wh[4], wl[4];
                    ldsm_x4(wh, WhU + w_off + (uint32_t)(n2 * 16 * 144 + kq * 32));
                    ldsm_x4(wl, WlU + w_off + (uint32_t)(n2 * 16 * 144 + kq * 32));
#pragma unroll
                    for (int j = 0; j < 2; j++) {
                        const int na = n2 * 2 + j;
                        mma_bf16(acc[0][na], ah[0], wh[2 * j], wh[2 * j + 1]);
                        mma_bf16(acc[1][na], ah[1], wh[2 * j], wh[2 * j + 1]);
                        mma_bf16(acc[0][na], al[0], wh[2 * j], wh[2 * j + 1]);
                        mma_bf16(acc[1][na], al[1], wh[2 * j], wh[2 * j + 1]);
                        mma_bf16(acc[0][na], ah[0], wl[2 * j], wl[2 * j + 1]);
                        mma_bf16(acc[1][na], ah[1], wl[2 * j], wl[2 * j + 1]);
                    }
                }
            }
        }

#pragma unroll
        for (int ma = 0; ma < 2; ma++) {
#pragma unroll
            for (int rr = 0; rr < 2; rr++) {
                const int rg = bm + m0 + ma * 16 + g + rr * 8;
                if (rg >= M) continue;
                float* crow = C + (size_t)rg * ldc + bn;
#pragma unroll
                for (int na = 0; na < NA; na++) {
                    const int j = n0 + na * 8 + 2 * tig;
                    float b0 = (bn + j     < HB) ? bias[bn + j]     : 0.f;
                    float b1 = (bn + j + 1 < HB) ? bias[bn + j + 1] : 0.f;
                    float v0 = acc[ma][na][rr * 2 + 0] + b0;
                    float v1 = acc[ma][na][rr * 2 + 1] + b1;
                    if (RELU) { v0 = fmaxf(v0, 0.f); v1 = fmaxf(v1, 0.f); }
                    *(float2*)(crow + j) = make_float2(v0, v1);
                }
            }
        }
    }
}

// ---- mma.sync edge kernel: sorted edges, MT m-tiles, bias post-max ------------
template <int H, int BN, int MINB, int MT>
__global__ void __launch_bounds__(256, MINB)
edge_mma_kernel(const float* __restrict__ AB,
                const uint4* __restrict__ Whi_g, const uint4* __restrict__ Wlo_g,
                unsigned* __restrict__ agg, int E, int COUT) {
    constexpr int NCH = H / 64;
    static_assert(MT == 1 || NCH == 1, "MT>1 requires single-chunk K");
    constexpr int NA  = BN / 16;
    constexpr int WSZ = BN * 144;
    constexpr int ASZ = 128 * 144;
    constexpr int OW  = 2048;
    constexpr int OA  = OW + 2 * WSZ;
    constexpr int WCNT = BN * 9;

    extern __shared__ char sm[];
    const uint32_t smb = smem_u32(sm);
    int* sdst = (int*)sm;            // MT*128 ints
    int* ssrc = (int*)(sm + 1024);   // MT*128 ints

    const int tid = threadIdx.x;
    const int wid = tid >> 5, lane = tid & 31;
    const int g = lane >> 2, tig = lane & 3;
    const int e0b = blockIdx.x * (128 * MT);
    const int bn = blockIdx.y * BN;

    for (int i = tid; i < 128 * MT; i += 256) {
        int e = e0b + i;
        ssrc[i] = (e < E) ? g_srcS[e] : 0;
        sdst[i] = (e < E) ? g_dstS[e] : 0;
    }
    __syncthreads();

    const int r  = tid >> 1;
    const int hf = tid & 1;

    const int wm = wid >> 1, wn = wid & 1;
    const int m0 = wm * 32, n0 = wn * (BN / 2);

    const int lr = lane & 7;
    const uint32_t a_off =
        (uint32_t)(m0 + lr + ((lane >> 3) & 1) * 8) * 144u + (uint32_t)(lane >> 4) * 16u;
    const uint32_t w_off =
        (uint32_t)(n0 + lr + ((lane >> 4) & 1) * 8) * 144u + (uint32_t)((lane >> 3) & 1) * 16u;

    const uint32_t WhU = smb + OW;
    const uint32_t WlU = WhU + WSZ;
    const uint32_t AhU = smb + OA;
    const uint32_t AlU = AhU + ASZ;
    char* Ah = sm + OA;
    char* Al = sm + OA + ASZ;

    for (int mt = 0; mt < MT; mt++) {
        const int rb = mt * 128;
        const float* Arow = AB + (size_t)sdst[rb + r] * (2 * H) + hf * 32;
        const float* Brow = AB + (size_t)ssrc[rb + r] * (2 * H) + H + hf * 32;

        float acc[2][NA][4];
#pragma unroll
        for (int ma = 0; ma < 2; ma++)
#pragma unroll
            for (int na = 0; na < NA; na++)
#pragma unroll
                for (int q = 0; q < 4; q++) acc[ma][na][q] = 0.f;

        float4 pre[4];
#pragma unroll
        for (int q = 0; q < 4; q++) pre[q] = ((const float4*)Brow)[q];

        for (int c = 0; c < NCH; c++) {
            if (c || mt) __syncthreads();
            if (mt == 0) {
                const char* shp = (const char*)(Whi_g + (size_t)(blockIdx.y * NCH + c) * WCNT);
                const char* slp = (const char*)(Wlo_g + (size_t)(blockIdx.y * NCH + c) * WCNT);
                for (int i = tid; i < WCNT; i += 256) {
                    cp16(WhU + i * 16, shp + i * 16);
                    cp16(WlU + i * 16, slp + i * 16);
                }
                asm volatile("cp.async.commit_group;" ::: "memory");
            }
            {
                const float4* Ap = (const float4*)(Arow + c * 64);
                const float4* Bp = (const float4*)(Brow + c * 64);
                float v[32];
#pragma unroll
                for (int q = 0; q < 4; q++) {
                    float4 a = Ap[q], b = pre[q];
                    v[q * 4 + 0] = fmaxf(a.x + b.x, 0.f);
                    v[q * 4 + 1] = fmaxf(a.y + b.y, 0.f);
                    v[q * 4 + 2] = fmaxf(a.z + b.z, 0.f);
                    v[q * 4 + 3] = fmaxf(a.w + b.w, 0.f);
                }
#pragma unroll
                for (int q = 4; q < 8; q++) {
                    float4 a = Ap[q], b = Bp[q];
                    v[q * 4 + 0] = fmaxf(a.x + b.x, 0.f);
                    v[q * 4 + 1] = fmaxf(a.y + b.y, 0.f);
                    v[q * 4 + 2] = fmaxf(a.z + b.z, 0.f);
                    v[q * 4 + 3] = fmaxf(a.w + b.w, 0.f);
                }
                if (c + 1 < NCH) {
                    const float4* Bn = (const float4*)(Brow + (c + 1) * 64);
#pragma unroll
                    for (int q = 0; q < 4; q++) pre[q] = Bn[q];
                }
                char* ah = Ah + r * 144 + hf * 64;
                char* al = Al + r * 144 + hf * 64;
#pragma unroll
                for (int q8 = 0; q8 < 4; q8++) {
                    uint32_t uh[4], ul[4];
#pragma unroll
                    for (int p = 0; p < 4; p++)
                        split2(v[q8 * 8 + p * 2], v[q8 * 8 + p * 2 + 1], uh[p], ul[p]);
                    *(uint4*)(ah + q8 * 16) = make_uint4(uh[0], uh[1], uh[2], uh[3]);
                    *(uint4*)(al + q8 * 16) = make_uint4(ul[0], ul[1], ul[2], ul[3]);
                }
            }
            asm volatile("cp.async.wait_group 0;" ::: "memory");
            __syncthreads();

#pragma unroll
            for (int kq = 0; kq < 4; kq++) {
                uint32_t ah[2][4], al[2][4];
#pragma unroll
                for (int ma = 0; ma < 2; ma++) {
                    ldsm_x4(ah[ma], AhU + a_off + (uint32_t)(ma * 16 * 144 + kq * 32));
                    ldsm_x4(al[ma], AlU + a_off + (uint32_t)(ma * 16 * 144 + kq * 32));
                }
#pragma unroll
                for (int n2 = 0; n2 < NA / 2; n2++) {
                    uint32_t wh[4], wl[4];
                    ldsm_x4(wh, WhU + w_off + (uint32_t)(n2 * 16 * 144 + kq * 32));
                    ldsm_x4(wl, WlU + w_off + (uint32_t)(n2 * 16 * 144 + kq * 32));
#pragma unroll
                    for (int j = 0; j < 2; j++) {
                        const int na = n2 * 2 + j;
                        mma_bf16(acc[0][na], ah[0], wh[2 * j], wh[2 * j + 1]);
                        mma_bf16(acc[1][na], ah[1], wh[2 * j], wh[2 * j + 1]);
                        mma_bf16(acc[0][na], al[0], wh[2 * j], wh[2 * j + 1]);
                        mma_bf16(acc[1][na], al[1], wh[2 * j], wh[2 * j + 1]);
                        mma_bf16(acc[0][na], ah[0], wl[2 * j], wl[2 * j + 1]);
                        mma_bf16(acc[1][na], ah[1], wl[2 * j], wl[2 * j + 1]);
                    }
                }
            }
        }

#pragma unroll
        for (int ma = 0; ma < 2; ma++) {
#pragma unroll
            for (int rr = 0; rr < 2; rr++) {
                const int rloc = m0 + ma * 16 + g + rr * 8;
                if (e0b + rb + rloc >= E) continue;
                const int d = sdst[rb + rloc];
                unsigned* arow = agg + (size_t)d * COUT + bn;
#pragma unroll
                for (int na = 0; na < NA; na++) {
                    const int j = n0 + na * 8 + 2 * tig;
                    unsigned k0 = f2ord(acc[ma][na][rr * 2 + 0]);
                    unsigned k1 = f2ord(acc[ma][na][rr * 2 + 1]);
                    uint2 cur = *(const uint2*)(arow + j);
                    if (k0 > cur.x) atomicMax(arow + j, k0);
                    if (k1 > cur.y) atomicMax(arow + j + 1, k1);
                }
            }
        }
    }
}

// ---- decode agg (+bias post-max) -> float, then clear agg in-place ------------
__global__ void decode_clear_kernel(unsigned* __restrict__ agg,
                                    const float* __restrict__ bias,
                                    float* __restrict__ dsth, int total, int C, int ldc,
                                    int clrN) {
    int i = blockIdx.x * blockDim.x + threadIdx.x;
    if (i < total) {
        int n = i / C, c = i % C;
        unsigned u = agg[i];
        dsth[(size_t)n * ldc + c] = (u == 0u) ? 0.f : (ord2f(u) + bias[c]);
    }
    if (i < clrN) agg[i] = 0u;
}

// ---- final 256 -> 4 linear ------------------------------------------------------
__global__ void mlp3_kernel(const float* __restrict__ A, const float* __restrict__ W,
                            const float* __restrict__ b, float* __restrict__ out, int M) {
    int gw = (blockIdx.x * blockDim.x + threadIdx.x) >> 5;
    int lane = threadIdx.x & 31;
    if (gw >= M) return;
    const float* a = A + (size_t)gw * 256;
    float acc0 = 0.f, acc1 = 0.f, acc2 = 0.f, acc3 = 0.f;
    for (int k = lane; k < 256; k += 32) {
        float av = a[k];
        const float* wr = W + k * 4;
        acc0 = fmaf(av, wr[0], acc0);
        acc1 = fmaf(av, wr[1], acc1);
        acc2 = fmaf(av, wr[2], acc2);
        acc3 = fmaf(av, wr[3], acc3);
    }
#pragma unroll
    for (int off = 16; off > 0; off >>= 1) {
        acc0 += __shfl_down_sync(0xffffffffu, acc0, off);
        acc1 += __shfl_down_sync(0xffffffffu, acc1, off);
        acc2 += __shfl_down_sync(0xffffffffu, acc2, off);
        acc3 += __shfl_down_sync(0xffffffffu, acc3, off);
    }
    if (lane == 0) {
        out[gw * 4 + 0] = acc0 + b[0];
        out[gw * 4 + 1] = acc1 + b[1];
        out[gw * 4 + 2] = acc2 + b[2];
        out[gw * 4 + 3] = acc3 + b[3];
    }
}

// ---------------------------------------------------------------------------
extern "C" void kernel_launch(void* const* d_in, const int* in_sizes, int n_in,
                              void* d_out, int out_size) {
    const float* x   = (const float*)d_in[0];
    const void*  ei  = d_in[1];
    const float* w1a = (const float*)d_in[3];
    const float* b1a = (const float*)d_in[4];
    const float* w1b = (const float*)d_in[5];
    const float* b1b = (const float*)d_in[6];
    const float* w2a = (const float*)d_in[7];
    const float* b2a = (const float*)d_in[8];
    const float* w2b = (const float*)d_in[9];
    const float* b2b = (const float*)d_in[10];
    const float* w3a = (const float*)d_in[11];
    const float* b3a = (const float*)d_in[12];
    const float* w3b = (const float*)d_in[13];
    const float* b3b = (const float*)d_in[14];
    const float* wm1 = (const float*)d_in[15];
    const float* bm1 = (const float*)d_in[16];
    const float* wm2 = (const float*)d_in[17];
    const float* bm2 = (const float*)d_in[18];
    const float* wm3 = (const float*)d_in[19];
    const float* bm3 = (const float*)d_in[20];

    const int Nn = in_sizes[0] / 3;
    const int E  = in_sizes[1] / 2;
    float* out = (float*)d_out;

    float *AB, *hcat, *m1, *m2;
    unsigned* agg;
    uint4 *wh1, *wl1, *wh2, *wl2, *wh3, *wl3;
    uint4 *whn2, *wln2, *whn3, *wln3, *whm1, *wlm1, *whm2, *wlm2;
    cudaGetSymbolAddress((void**)&AB,   g_AB);
    cudaGetSymbolAddress((void**)&agg,  g_agg);
    cudaGetSymbolAddress((void**)&hcat, g_hcat);
    cudaGetSymbolAddress((void**)&m1,   g_m1);
    cudaGetSymbolAddress((void**)&m2,   g_m2);
    cudaGetSymbolAddress((void**)&wh1,  g_wh1);
    cudaGetSymbolAddress((void**)&wl1,  g_wl1);
    cudaGetSymbolAddress((void**)&wh2,  g_wh2);
    cudaGetSymbolAddress((void**)&wl2,  g_wl2);
    cudaGetSymbolAddress((void**)&wh3,  g_wh3);
    cudaGetSymbolAddress((void**)&wl3,  g_wl3);
    cudaGetSymbolAddress((void**)&whn2, g_whn2);
    cudaGetSymbolAddress((void**)&wln2, g_wln2);
    cudaGetSymbolAddress((void**)&whn3, g_whn3);
    cudaGetSymbolAddress((void**)&wln3, g_wln3);
    cudaGetSymbolAddress((void**)&whm1, g_whm1);
    cudaGetSymbolAddress((void**)&wlm1, g_wlm1);
    cudaGetSymbolAddress((void**)&whm2, g_whm2);
    cudaGetSymbolAddress((void**)&wlm2, g_wlm2);

    const int SM1 = 2048 + 2 * (64  * 144) + 2 * 18432;  // 57344
    const int SM2 = 2048 + 2 * (128 * 144) + 2 * 18432;  // 75776
    const int SMD = 2 * (128 * 144) + 2 * 18432;         // 73728
    cudaFuncSetAttribute(edge_mma_kernel<64, 64, 3, 2>,   cudaFuncAttributeMaxDynamicSharedMemorySize, SM1);
    cudaFuncSetAttribute(edge_mma_kernel<128, 128, 2, 1>, cudaFuncAttributeMaxDynamicSharedMemorySize, SM2);
    cudaFuncSetAttribute(edge_mma_kernel<256, 128, 2, 1>, cudaFuncAttributeMaxDynamicSharedMemorySize, SM2);
    cudaFuncSetAttribute(dense_mma_kernel<64,  128, false, 2>, cudaFuncAttributeMaxDynamicSharedMemorySize, SMD);
    cudaFuncSetAttribute(dense_mma_kernel<128, 128, false, 1>, cudaFuncAttributeMaxDynamicSharedMemorySize, SMD);
    cudaFuncSetAttribute(dense_mma_kernel<448, 128, true, 1>,  cudaFuncAttributeMaxDynamicSharedMemorySize, SMD);
    cudaFuncSetAttribute(dense_mma_kernel<512, 128, true, 1>,  cudaFuncAttributeMaxDynamicSharedMemorySize, SMD);

    const int TB = 256;
    dim3 blk(TB);
    const int gx   = (Nn + 127) / 128;
    const int gx2  = (Nn + 255) / 256;
    const int egx  = (E + 127) / 128;
    const int egx2 = (E + 255) / 256;

    // ---- one-shot weight prep + bin zeroing (runs before convert's hist) ----
    prep_all_kernel<<<(528384 + TB - 1) / TB, blk>>>(w1b, w2a, w2b, w3a, w3b, wm1, wm2);

    // ---- edge sort by dst (counting sort; segment-max is order-invariant) ----
    convert_idx_kernel<<<(E + TB - 1) / TB, blk>>>((const unsigned*)ei, E);
    scan_kernel<<<1, 1024>>>();
    scatter_kernel<<<(E + TB - 1) / TB, blk>>>(E);

    // ---- EdgeConv 1: 3 -> 64 ----
    node1_fused_kernel<<<(Nn * 128 + TB - 1) / TB, blk>>>(x, w1a, b1a, AB, agg, Nn);
    edge_mma_kernel<64, 64, 3, 2><<<dim3(egx2, 1), blk, SM1>>>(AB, wh1, wl1, agg, E, 64);

    // ---- EdgeConv 2: 64 -> 128 ----
    decode_clear_kernel<<<(Nn * 128 + TB - 1) / TB, blk>>>(agg, b1b, hcat + 0, Nn * 64, 64, 448, Nn * 128);
    dense_mma_kernel<64, 128, false, 2><<<dim3(gx2, 2), blk, SMD>>>(hcat, 448, whn2, wln2, b2a, 128, AB, 256, Nn);
    edge_mma_kernel<128, 128, 2, 1><<<dim3(egx, 1), blk, SM2>>>(AB, wh2, wl2, agg, E, 128);

    // ---- EdgeConv 3: 128 -> 256 ----
    decode_clear_kernel<<<(Nn * 256 + TB - 1) / TB, blk>>>(agg, b2b, hcat + 64, Nn * 128, 128, 448, Nn * 256);
    dense_mma_kernel<128, 128, false, 1><<<dim3(gx, 4), blk, SMD>>>(hcat + 64, 448, whn3, wln3, b3a, 256, AB, 512, Nn);
    edge_mma_kernel<256, 128, 2, 1><<<dim3(egx, 2), blk, SM2>>>(AB, wh3, wl3, agg, E, 256);
    decode_clear_kernel<<<(Nn * 256 + TB - 1) / TB, blk>>>(agg, b3b, hcat + 192, Nn * 256, 256, 448, 0);

    // ---- MLP head ----
    dense_mma_kernel<448, 128, true, 1><<<dim3(gx, 4), blk, SMD>>>(hcat, 448, whm1, wlm1, bm1, 512, m1, 512, Nn);
    dense_mma_kernel<512, 128, true, 1><<<dim3(gx, 2), blk, SMD>>>(m1, 512, whm2, wlm2, bm2, 256, m2, 256, Nn);
    mlp3_kernel<<<(Nn * 32 + TB - 1) / TB, blk>>>(m2, wm3, bm3, out, Nn);
}

// round 16
// speedup vs baseline: 1.0841x; 1.0021x over previous
#include <cuda_runtime.h>
#include <cuda_bf16.h>
#include <cstdint>

// ---------------------------------------------------------------------------
// DGCNN segmentation. ALL GEMMs on tensor cores via mma.sync bf16x3 split
// precision (ldmatrix frags, cp.async.cg W streaming, 64-wide K chunks).
// Edges counting-sorted by dst. Bias applied after segment-max (exact).
// Launch-compressed: single prep_all (weights + bins), hist in convert,
// scatter+node1 fused, decode+clear fused, inline node-weight combine.
// ---------------------------------------------------------------------------

#define NMAX 30016
#define EMAX 480256
#define NBIN 30720   // 1024 * 30

__device__ float    g_AB[NMAX * 512];
__device__ unsigned g_agg[NMAX * 256];
__device__ float    g_hcat[NMAX * 448];
__device__ float    g_m1[NMAX * 512];
__device__ float    g_m2[NMAX * 256];
__device__ uint4    g_wh1[64 * 72 / 8],       g_wl1[64 * 72 / 8];
__device__ uint4    g_wh2[2 * 128 * 72 / 8],  g_wl2[2 * 128 * 72 / 8];
__device__ uint4    g_wh3[8 * 128 * 72 / 8],  g_wl3[8 * 128 * 72 / 8];
__device__ uint4    g_whn2[2304],  g_wln2[2304];
__device__ uint4    g_whn3[9216],  g_wln3[9216];
__device__ uint4    g_whm1[32256], g_wlm1[32256];
__device__ uint4    g_whm2[18432], g_wlm2[18432];
__device__ int      g_src[EMAX];
__device__ int      g_dst[EMAX];
__device__ int      g_srcS[EMAX];   // sorted by dst
__device__ int      g_dstS[EMAX];
__device__ int      g_cnt[NBIN];
__device__ int      g_c2[NBIN];
__device__ int      g_start[NBIN];

// ---- ordered-uint encoding for float max ------------------------------------
__device__ __forceinline__ unsigned f2ord(float f) {
    int i = __float_as_int(f);
    return (i >= 0) ? ((unsigned)i | 0x80000000u) : ~(unsigned)i;
}
__device__ __forceinline__ float ord2f(unsigned u) {
    int i = (u & 0x80000000u) ? (int)(u & 0x7fffffffu) : (int)(~u);
    return __int_as_float(i);
}

// ---- PTX helpers --------------------------------------------------------------
__device__ __forceinline__ uint32_t smem_u32(const void* p) {
    uint32_t a;
    asm("{ .reg .u64 t; cvta.to.shared.u64 t, %1; cvt.u32.u64 %0, t; }" : "=r"(a) : "l"(p));
    return a;
}
__device__ __forceinline__ void mma_bf16(float* d, const uint32_t* a,
                                         uint32_t b0, uint32_t b1) {
    asm volatile(
        "mma.sync.aligned.m16n8k16.row.col.f32.bf16.bf16.f32 "
        "{%0,%1,%2,%3},{%4,%5,%6,%7},{%8,%9},{%0,%1,%2,%3};"
        : "+f"(d[0]), "+f"(d[1]), "+f"(d[2]), "+f"(d[3])
        : "r"(a[0]), "r"(a[1]), "r"(a[2]), "r"(a[3]), "r"(b0), "r"(b1));
}
__device__ __forceinline__ void ldsm_x4(uint32_t* r, uint32_t addr) {
    asm volatile("ldmatrix.sync.aligned.m8n8.x4.shared.b16 {%0,%1,%2,%3},[%4];"
                 : "=r"(r[0]), "=r"(r[1]), "=r"(r[2]), "=r"(r[3]) : "r"(addr));
}
__device__ __forceinline__ void cp16(uint32_t s, const void* g) {
    asm volatile("cp.async.cg.shared.global [%0],[%1],16;" :: "r"(s), "l"(g));
}
__device__ __forceinline__ void split2(float m0, float m1, uint32_t& hi2, uint32_t& lo2) {
    asm("cvt.rn.bf16x2.f32 %0, %1, %2;" : "=r"(hi2) : "f"(m1), "f"(m0));
    float h0 = __uint_as_float(hi2 << 16);
    float h1 = __uint_as_float(hi2 & 0xffff0000u);
    float l0 = m0 - h0, l1 = m1 - h1;
    asm("cvt.rn.bf16x2.f32 %0, %1, %2;" : "=r"(lo2) : "f"(l1), "f"(l0));
}

// ---- weight conversion helpers -------------------------------------------------
__device__ __forceinline__ void store_wb(float val, int k, int n, int NCH, int BN,
                                         uint4* Whi, uint4* Wlo) {
    __nv_bfloat16 hb = __float2bfloat16(val);
    __nv_bfloat16 lb = __float2bfloat16(val - __bfloat162float(hb));
    int tile = n / BN, nl = n % BN, c = k >> 6, kl = k & 63;
    size_t off = ((size_t)(tile * NCH + c) * BN + nl) * 72 + kl;
    ((unsigned short*)Whi)[off] = __bfloat16_as_ushort(hb);
    ((unsigned short*)Wlo)[off] = __bfloat16_as_ushort(lb);
}
__device__ __forceinline__ void prep_std(const float* W, int idx, int COUT, int H,
                                         int BN, uint4* Whi, uint4* Wlo) {
    int k = idx / COUT, n = idx % COUT;
    store_wb(W[idx], k, n, H >> 6, BN, Whi, Wlo);
}
__device__ __forceinline__ void prep_node(const float* w, int idx, int C, int H,
                                          int BN, uint4* Whi, uint4* Wlo) {
    int COUT = 2 * H;
    int k = idx / COUT, n = idx % COUT;
    float val = (n < H) ? (w[k * H + n] - w[(k + C) * H + n])
                        : w[(k + C) * H + (n - H)];
    store_wb(val, k, n, C >> 6, BN, Whi, Wlo);
}

// ---- one-shot prep: all weight conversions + sort-bin zeroing ------------------
__global__ void prep_all_kernel(const float* __restrict__ w1b,
                                const float* __restrict__ w2a,
                                const float* __restrict__ w2b,
                                const float* __restrict__ w3a,
                                const float* __restrict__ w3b,
                                const float* __restrict__ wm1,
                                const float* __restrict__ wm2) {
    int i = blockIdx.x * blockDim.x + threadIdx.x;
    if (i < NBIN) { g_cnt[i] = 0; g_c2[i] = 0; }
    int j = i;
    if (j < 4096)            { prep_std (w1b, j, 64, 64, 64, g_wh1, g_wl1); return; }
    j -= 4096;
    if (j < 16384)           { prep_node(w2a, j, 64, 128, 128, g_whn2, g_wln2); return; }
    j -= 16384;
    if (j < 16384)           { prep_std (w2b, j, 128, 128, 128, g_wh2, g_wl2); return; }
    j -= 16384;
    if (j < 65536)           { prep_node(w3a, j, 128, 256, 128, g_whn3, g_wln3); return; }
    j -= 65536;
    if (j < 65536)           { prep_std (w3b, j, 256, 256, 128, g_wh3, g_wl3); return; }
    j -= 65536;
    if (j < 229376)          { prep_std (wm1, j, 512, 448, 128, g_whm1, g_wlm1); return; }
    j -= 229376;
    if (j < 131072)          { prep_std (wm2, j, 256, 512, 128, g_whm2, g_wlm2); return; }
}

// ---- edge index convert + histogram (bins pre-zeroed by prep_all) --------------
__global__ void convert_idx_kernel(const unsigned* __restrict__ raw, int E) {
    int n = (E < 256) ? E : 256;
    int is64 = 1;
    for (int i = 0; i < n; i++)
        if (raw[2 * i + 1] != 0u) { is64 = 0; break; }
    int i = blockIdx.x * blockDim.x + threadIdx.x;
    if (i >= E) return;
    int s, d;
    if (is64) {
        const long long* p = (const long long*)raw;
        s = (int)p[i]; d = (int)p[E + i];
    } else {
        const int* p = (const int*)raw;
        s = p[i]; d = p[E + i];
    }
    g_src[i] = s;
    g_dst[i] = d;
    atomicAdd(&g_cnt[d], 1);
}
__global__ void scan_kernel() {   // 1 block, 1024 threads, 30 bins each
    __shared__ int part[1024];
    int t = threadIdx.x;
    int base = t * 30;
    int s = 0;
#pragma unroll
    for (int j = 0; j < 30; j++) s += g_cnt[base + j];
    part[t] = s;
    __syncthreads();
    for (int off = 1; off < 1024; off <<= 1) {
        int v = (t >= off) ? part[t - off] : 0;
        __syncthreads();
        part[t] += v;
        __syncthreads();
    }
    int run = part[t] - s;
#pragma unroll
    for (int j = 0; j < 30; j++) {
        g_start[base + j] = run;
        run += g_cnt[base + j];
    }
}

// ---- fused scatter (edge reorder) + layer-1 node precompute + agg clear --------
// Disjoint outputs (srcS/dstS vs AB/agg); both ready after scan.
__global__ void scatter_node1_kernel(const float* __restrict__ x,
                                     const float* __restrict__ w1a,
                                     const float* __restrict__ b1a,
                                     float* __restrict__ AB,
                                     unsigned* __restrict__ agg, int M, int E) {
    int idx = blockIdx.x * blockDim.x + threadIdx.x;
    if (idx < E) {
        int d = g_dst[idx];
        int pos = g_start[d] + atomicAdd(&g_c2[d], 1);
        g_srcS[pos] = g_src[idx];
        g_dstS[pos] = d;
    }
    if (idx >= M * 128) return;
    if (idx < M * 64) agg[idx] = 0u;
    int n = idx >> 7, j = idx & 127;
    float wk0, wk1, wk2, bb;
    if (j < 64) {
        wk0 = w1a[0 * 64 + j] - w1a[3 * 64 + j];
        wk1 = w1a[1 * 64 + j] - w1a[4 * 64 + j];
        wk2 = w1a[2 * 64 + j] - w1a[5 * 64 + j];
        bb  = b1a[j];
    } else {
        int jj = j - 64;
        wk0 = w1a[3 * 64 + jj];
        wk1 = w1a[4 * 64 + jj];
        wk2 = w1a[5 * 64 + jj];
        bb  = 0.f;
    }
    float x0 = x[n * 3 + 0], x1 = x[n * 3 + 1], x2 = x[n * 3 + 2];
    AB[idx] = fmaf(x0, wk0, fmaf(x1, wk1, fmaf(x2, wk2, bb)));
}

// ---- dense bf16x3 mma GEMM: C = act(A @ W + [bias|0]) --------------------------
template <int K, int BN, bool RELU, int MT>
__global__ void __launch_bounds__(256, 2)
dense_mma_kernel(const float* __restrict__ A, int lda,
                 const uint4* __restrict__ Whi_g, const uint4* __restrict__ Wlo_g,
                 const float* __restrict__ bias, int HB,
                 float* __restrict__ C, int ldc, int M) {
    constexpr int NCH = K / 64;
    static_assert(MT == 1 || NCH == 1, "MT>1 requires single-chunk K");
    constexpr int NA  = BN / 16;
    constexpr int WSZ = BN * 144;
    constexpr int ASZ = 128 * 144;
    constexpr int OA  = 2 * WSZ;
    constexpr int WCNT = BN * 9;

    extern __shared__ char sm[];
    const uint32_t smb = smem_u32(sm);

    const int tid = threadIdx.x;
    const int wid = tid >> 5, lane = tid & 31;
    const int g = lane >> 2, tig = lane & 3;
    const int bmb = blockIdx.x * (128 * MT);
    const int bn = blockIdx.y * BN;

    const int r  = tid >> 1;
    const int hf = tid & 1;

    const int wm = wid >> 1, wn = wid & 1;
    const int m0 = wm * 32, n0 = wn * (BN / 2);

    const int lr = lane & 7;
    const uint32_t a_off =
        (uint32_t)(m0 + lr + ((lane >> 3) & 1) * 8) * 144u + (uint32_t)(lane >> 4) * 16u;
    const uint32_t w_off =
        (uint32_t)(n0 + lr + ((lane >> 4) & 1) * 8) * 144u + (uint32_t)((lane >> 3) & 1) * 16u;

    const uint32_t WhU = smb;
    const uint32_t WlU = WhU + WSZ;
    const uint32_t AhU = smb + OA;
    const uint32_t AlU = AhU + ASZ;
    char* Ah = sm + OA;
    char* Al = sm + OA + ASZ;

    for (int mt = 0; mt < MT; mt++) {
        const int bm = bmb + mt * 128;
        const bool rv = (bm + r) < M;
        const float* Arow = A + (size_t)(bm + r) * lda + hf * 32;

        float acc[2][NA][4];
#pragma unroll
        for (int ma = 0; ma < 2; ma++)
#pragma unroll
            for (int na = 0; na < NA; na++)
#pragma unroll
                for (int q = 0; q < 4; q++) acc[ma][na][q] = 0.f;

        for (int c = 0; c < NCH; c++) {
            if (c || mt) __syncthreads();
            if (mt == 0) {
                const char* shp = (const char*)(Whi_g + (size_t)(blockIdx.y * NCH + c) * WCNT);
                const char* slp = (const char*)(Wlo_g + (size_t)(blockIdx.y * NCH + c) * WCNT);
                for (int i = tid; i < WCNT; i += 256) {
                    cp16(WhU + i * 16, shp + i * 16);
                    cp16(WlU + i * 16, slp + i * 16);
                }
                asm volatile("cp.async.commit_group;" ::: "memory");
            }
            {
                const float4* Ap = (const float4*)(Arow + c * 64);
                float v[32];
                if (rv) {
#pragma unroll
                    for (int q = 0; q < 8; q++) {
                        float4 a = Ap[q];
                        v[q * 4 + 0] = a.x; v[q * 4 + 1] = a.y;
                        v[q * 4 + 2] = a.z; v[q * 4 + 3] = a.w;
                    }
                } else {
#pragma unroll
                    for (int q = 0; q < 32; q++) v[q] = 0.f;
                }
                char* ah = Ah + r * 144 + hf * 64;
                char* al = Al + r * 144 + hf * 64;
#pragma unroll
                for (int q8 = 0; q8 < 4; q8++) {
                    uint32_t uh[4], ul[4];
#pragma unroll
                    for (int p = 0; p < 4; p++)
                        split2(v[q8 * 8 + p * 2], v[q8 * 8 + p * 2 + 1], uh[p], ul[p]);
                    *(uint4*)(ah + q8 * 16) = make_uint4(uh[0], uh[1], uh[2], uh[3]);
                    *(uint4*)(al + q8 * 16) = make_uint4(ul[0], ul[1], ul[2], ul[3]);
                }
            }
            asm volatile("cp.async.wait_group 0;" ::: "memory");
            __syncthreads();

#pragma unroll
            for (int kq = 0; kq < 4; kq++) {
                uint32_t ah[2][4], al[2][4];
#pragma unroll
                for (int ma = 0; ma < 2; ma++) {
                    ldsm_x4(ah[ma], AhU + a_off + (uint32_t)(ma * 16 * 144 + kq * 32));
                    ldsm_x4(al[ma], AlU + a_off + (uint32_t)(ma * 16 * 144 + kq * 32));
                }
#pragma unroll
                for (int n2 = 0; n2 < NA / 2; n2++) {
                    uint32_t wh[4], wl[4];
                    ldsm_x4(wh, WhU + w_off + (uint32_t)(n2 * 16 * 144 + kq * 32));
                    ldsm_x4(wl, WlU + w_off + (uint32_t)(n2 * 16 * 144 + kq * 32));
#pragma unroll
                    for (int j = 0; j < 2; j++) {
                        const int na = n2 * 2 + j;
                        mma_bf16(acc[0][na], ah[0], wh[2 * j], wh[2 * j + 1]);
                        mma_bf16(acc[1][na], ah[1], wh[2 * j], wh[2 * j + 1]);
                        mma_bf16(acc[0][na], al[0], wh[2 * j], wh[2 * j + 1]);
                        mma_bf16(acc[1][na], al[1], wh[2 * j], wh[2 * j + 1]);
                        mma_bf16(acc[0][na], ah[0], wl[2 * j], wl[2 * j + 1]);
                        mma_bf16(acc[1][na], ah[1], wl[2 * j], wl[2 * j + 1]);
                    }
                }
            }
        }

#pragma unroll
        for (int ma = 0; ma < 2; ma++) {
#pragma unroll
            for (int rr = 0; rr < 2; rr++) {
                const int rg = bm + m0 + ma * 16 + g + rr * 8;
                if (rg >= M) continue;
                float* crow = C + (size_t)rg * ldc + bn;
#pragma unroll
                for (int na = 0; na < NA; na++) {
                    const int j = n0 + na * 8 + 2 * tig;
                    float b0 = (bn + j     < HB) ? bias[bn + j]     : 0.f;
                    float b1 = (bn + j + 1 < HB) ? bias[bn + j + 1] : 0.f;
                    float v0 = acc[ma][na][rr * 2 + 0] + b0;
                    float v1 = acc[ma][na][rr * 2 + 1] + b1;
                    if (RELU) { v0 = fmaxf(v0, 0.f); v1 = fmaxf(v1, 0.f); }
                    *(float2*)(crow + j) = make_float2(v0, v1);
                }
            }
        }
    }
}

// ---- mma.sync edge kernel: sorted edges, MT m-tiles, bias post-max ------------
template <int H, int BN, int MINB, int MT>
__global__ void __launch_bounds__(256, MINB)
edge_mma_kernel(const float* __restrict__ AB,
                const uint4* __restrict__ Whi_g, const uint4* __restrict__ Wlo_g,
                unsigned* __restrict__ agg, int E, int COUT) {
    constexpr int NCH = H / 64;
    static_assert(MT == 1 || NCH == 1, "MT>1 requires single-chunk K");
    constexpr int NA  = BN / 16;
    constexpr int WSZ = BN * 144;
    constexpr int ASZ = 128 * 144;
    constexpr int OW  = 2048;
    constexpr int OA  = OW + 2 * WSZ;
    constexpr int WCNT = BN * 9;

    extern __shared__ char sm[];
    const uint32_t smb = smem_u32(sm);
    int* sdst = (int*)sm;            // MT*128 ints
    int* ssrc = (int*)(sm + 1024);   // MT*128 ints

    const int tid = threadIdx.x;
    const int wid = tid >> 5, lane = tid & 31;
    const int g = lane >> 2, tig = lane & 3;
    const int e0b = blockIdx.x * (128 * MT);
    const int bn = blockIdx.y * BN;

    for (int i = tid; i < 128 * MT; i += 256) {
        int e = e0b + i;
        ssrc[i] = (e < E) ? g_srcS[e] : 0;
        sdst[i] = (e < E) ? g_dstS[e] : 0;
    }
    __syncthreads();

    const int r  = tid >> 1;
    const int hf = tid & 1;

    const int wm = wid >> 1, wn = wid & 1;
    const int m0 = wm * 32, n0 = wn * (BN / 2);

    const int lr = lane & 7;
    const uint32_t a_off =
        (uint32_t)(m0 + lr + ((lane >> 3) & 1) * 8) * 144u + (uint32_t)(lane >> 4) * 16u;
    const uint32_t w_off =
        (uint32_t)(n0 + lr + ((lane >> 4) & 1) * 8) * 144u + (uint32_t)((lane >> 3) & 1) * 16u;

    const uint32_t WhU = smb + OW;
    const uint32_t WlU = WhU + WSZ;
    const uint32_t AhU = smb + OA;
    const uint32_t AlU = AhU + ASZ;
    char* Ah = sm + OA;
    char* Al = sm + OA + ASZ;

    for (int mt = 0; mt < MT; mt++) {
        const int rb = mt * 128;
        const float* Arow = AB + (size_t)sdst[rb + r] * (2 * H) + hf * 32;
        const float* Brow = AB + (size_t)ssrc[rb + r] * (2 * H) + H + hf * 32;

        float acc[2][NA][4];
#pragma unroll
        for (int ma = 0; ma < 2; ma++)
#pragma unroll
            for (int na = 0; na < NA; na++)
#pragma unroll
                for (int q = 0; q < 4; q++) acc[ma][na][q] = 0.f;

        float4 pre[4];
#pragma unroll
        for (int q = 0; q < 4; q++) pre[q] = ((const float4*)Brow)[q];

        for (int c = 0; c < NCH; c++) {
            if (c || mt) __syncthreads();
            if (mt == 0) {
                const char* shp = (const char*)(Whi_g + (size_t)(blockIdx.y * NCH + c) * WCNT);
                const char* slp = (const char*)(Wlo_g + (size_t)(blockIdx.y * NCH + c) * WCNT);
                for (int i = tid; i < WCNT; i += 256) {
                    cp16(WhU + i * 16, shp + i * 16);
                    cp16(WlU + i * 16, slp + i * 16);
                }
                asm volatile("cp.async.commit_group;" ::: "memory");
            }
            {
                const float4* Ap = (const float4*)(Arow + c * 64);
                const float4* Bp = (const float4*)(Brow + c * 64);
                float v[32];
#pragma unroll
                for (int q = 0; q < 4; q++) {
                    float4 a = Ap[q], b = pre[q];
                    v[q * 4 + 0] = fmaxf(a.x + b.x, 0.f);
                    v[q * 4 + 1] = fmaxf(a.y + b.y, 0.f);
                    v[q * 4 + 2] = fmaxf(a.z + b.z, 0.f);
                    v[q * 4 + 3] = fmaxf(a.w + b.w, 0.f);
                }
#pragma unroll
                for (int q = 4; q < 8; q++) {
                    float4 a = Ap[q], b = Bp[q];
                    v[q * 4 + 0] = fmaxf(a.x + b.x, 0.f);
                    v[q * 4 + 1] = fmaxf(a.y + b.y, 0.f);
                    v[q * 4 + 2] = fmaxf(a.z + b.z, 0.f);
                    v[q * 4 + 3] = fmaxf(a.w + b.w, 0.f);
                }
                if (c + 1 < NCH) {
                    const float4* Bn = (const float4*)(Brow + (c + 1) * 64);
#pragma unroll
                    for (int q = 0; q < 4; q++) pre[q] = Bn[q];
                }
                char* ah = Ah + r * 144 + hf * 64;
                char* al = Al + r * 144 + hf * 64;
#pragma unroll
                for (int q8 = 0; q8 < 4; q8++) {
                    uint32_t uh[4], ul[4];
#pragma unroll
                    for (int p = 0; p < 4; p++)
                        split2(v[q8 * 8 + p * 2], v[q8 * 8 + p * 2 + 1], uh[p], ul[p]);
                    *(uint4*)(ah + q8 * 16) = make_uint4(uh[0], uh[1], uh[2], uh[3]);
                    *(uint4*)(al + q8 * 16) = make_uint4(ul[0], ul[1], ul[2], ul[3]);
                }
            }
            asm volatile("cp.async.wait_group 0;" ::: "memory");
            __syncthreads();

#pragma unroll
            for (int kq = 0; kq < 4; kq++) {
                uint32_t ah[2][4], al[2][4];
#pragma unroll
                for (int ma = 0; ma < 2; ma++) {
                    ldsm_x4(ah[ma], AhU + a_off + (uint32_t)(ma * 16 * 144 + kq * 32));
                    ldsm_x4(al[ma], AlU + a_off + (uint32_t)(ma * 16 * 144 + kq * 32));
                }
#pragma unroll
                for (int n2 = 0; n2 < NA / 2; n2++) {
                    uint32_t wh[4], wl[4];
                    ldsm_x4(wh, WhU + w_off + (uint32_t)(n2 * 16 * 144 + kq * 32));
                    ldsm_x4(wl, WlU + w_off + (uint32_t)(n2 * 16 * 144 + kq * 32));
#pragma unroll
                    for (int j = 0; j < 2; j++) {
                        const int na = n2 * 2 + j;
                        mma_bf16(acc[0][na], ah[0], wh[2 * j], wh[2 * j + 1]);
                        mma_bf16(acc[1][na], ah[1], wh[2 * j], wh[2 * j + 1]);
                        mma_bf16(acc[0][na], al[0], wh[2 * j], wh[2 * j + 1]);
                        mma_bf16(acc[1][na], al[1], wh[2 * j], wh[2 * j + 1]);
                        mma_bf16(acc[0][na], ah[0], wl[2 * j], wl[2 * j + 1]);
                        mma_bf16(acc[1][na], ah[1], wl[2 * j], wl[2 * j + 1]);
                    }
                }
            }
        }

#pragma unroll
        for (int ma = 0; ma < 2; ma++) {
#pragma unroll
            for (int rr = 0; rr < 2; rr++) {
                const int rloc = m0 + ma * 16 + g + rr * 8;
                if (e0b + rb + rloc >= E) continue;
                const int d = sdst[rb + rloc];
                unsigned* arow = agg + (size_t)d * COUT + bn;
#pragma unroll
                for (int na = 0; na < NA; na++) {
                    const int j = n0 + na * 8 + 2 * tig;
                    unsigned k0 = f2ord(acc[ma][na][rr * 2 + 0]);
                    unsigned k1 = f2ord(acc[ma][na][rr * 2 + 1]);
                    uint2 cur = *(const uint2*)(arow + j);
                    if (k0 > cur.x) atomicMax(arow + j, k0);
                    if (k1 > cur.y) atomicMax(arow + j + 1, k1);
                }
            }
        }
    }
}

// ---- decode agg (+bias post-max) -> float, then clear agg in-place ------------
__global__ void decode_clear_kernel(unsigned* __restrict__ agg,
                                    const float* __restrict__ bias,
                                    float* __restrict__ dsth, int total, int C, int ldc,
                                    int clrN) {
    int i = blockIdx.x * blockDim.x + threadIdx.x;
    if (i < total) {
        int n = i / C, c = i % C;
        unsigned u = agg[i];
        dsth[(size_t)n * ldc + c] = (u == 0u) ? 0.f : (ord2f(u) + bias[c]);
    }
    if (i < clrN) agg[i] = 0u;
}

// ---- final 256 -> 4 linear ------------------------------------------------------
__global__ void mlp3_kernel(const float* __restrict__ A, const float* __restrict__ W,
                            const float* __restrict__ b, float* __restrict__ out, int M) {
    int gw = (blockIdx.x * blockDim.x + threadIdx.x) >> 5;
    int lane = threadIdx.x & 31;
    if (gw >= M) return;
    const float* a = A + (size_t)gw * 256;
    float acc0 = 0.f, acc1 = 0.f, acc2 = 0.f, acc3 = 0.f;
    for (int k = lane; k < 256; k += 32) {
        float av = a[k];
        const float* wr = W + k * 4;
        acc0 = fmaf(av, wr[0], acc0);
        acc1 = fmaf(av, wr[1], acc1);
        acc2 = fmaf(av, wr[2], acc2);
        acc3 = fmaf(av, wr[3], acc3);
    }
#pragma unroll
    for (int off = 16; off > 0; off >>= 1) {
        acc0 += __shfl_down_sync(0xffffffffu, acc0, off);
        acc1 += __shfl_down_sync(0xffffffffu, acc1, off);
        acc2 += __shfl_down_sync(0xffffffffu, acc2, off);
        acc3 += __shfl_down_sync(0xffffffffu, acc3, off);
    }
    if (lane == 0) {
        out[gw * 4 + 0] = acc0 + b[0];
        out[gw * 4 + 1] = acc1 + b[1];
        out[gw * 4 + 2] = acc2 + b[2];
        out[gw * 4 + 3] = acc3 + b[3];
    }
}

// ---------------------------------------------------------------------------
extern "C" void kernel_launch(void* const* d_in, const int* in_sizes, int n_in,
                              void* d_out, int out_size) {
    const float* x   = (const float*)d_in[0];
    const void*  ei  = d_in[1];
    const float* w1a = (const float*)d_in[3];
    const float* b1a = (const float*)d_in[4];
    const float* w1b = (const float*)d_in[5];
    const float* b1b = (const float*)d_in[6];
    const float* w2a = (const float*)d_in[7];
    const float* b2a = (const float*)d_in[8];
    const float* w2b = (const float*)d_in[9];
    const float* b2b = (const float*)d_in[10];
    const float* w3a = (const float*)d_in[11];
    const float* b3a = (const float*)d_in[12];
    const float* w3b = (const float*)d_in[13];
    const float* b3b = (const float*)d_in[14];
    const float* wm1 = (const float*)d_in[15];
    const float* bm1 = (const float*)d_in[16];
    const float* wm2 = (const float*)d_in[17];
    const float* bm2 = (const float*)d_in[18];
    const float* wm3 = (const float*)d_in[19];
    const float* bm3 = (const float*)d_in[20];

    const int Nn = in_sizes[0] / 3;
    const int E  = in_sizes[1] / 2;
    float* out = (float*)d_out;

    float *AB, *hcat, *m1, *m2;
    unsigned* agg;
    uint4 *wh1, *wl1, *wh2, *wl2, *wh3, *wl3;
    uint4 *whn2, *wln2, *whn3, *wln3, *whm1, *wlm1, *whm2, *wlm2;
    cudaGetSymbolAddress((void**)&AB,   g_AB);
    cudaGetSymbolAddress((void**)&agg,  g_agg);
    cudaGetSymbolAddress((void**)&hcat, g_hcat);
    cudaGetSymbolAddress((void**)&m1,   g_m1);
    cudaGetSymbolAddress((void**)&m2,   g_m2);
    cudaGetSymbolAddress((void**)&wh1,  g_wh1);
    cudaGetSymbolAddress((void**)&wl1,  g_wl1);
    cudaGetSymbolAddress((void**)&wh2,  g_wh2);
    cudaGetSymbolAddress((void**)&wl2,  g_wl2);
    cudaGetSymbolAddress((void**)&wh3,  g_wh3);
    cudaGetSymbolAddress((void**)&wl3,  g_wl3);
    cudaGetSymbolAddress((void**)&whn2, g_whn2);
    cudaGetSymbolAddress((void**)&wln2, g_wln2);
    cudaGetSymbolAddress((void**)&whn3, g_whn3);
    cudaGetSymbolAddress((void**)&wln3, g_wln3);
    cudaGetSymbolAddress((void**)&whm1, g_whm1);
    cudaGetSymbolAddress((void**)&wlm1, g_wlm1);
    cudaGetSymbolAddress((void**)&whm2, g_whm2);
    cudaGetSymbolAddress((void**)&wlm2, g_wlm2);

    const int SM1 = 2048 + 2 * (64  * 144) + 2 * 18432;  // 57344
    const int SM2 = 2048 + 2 * (128 * 144) + 2 * 18432;  // 75776
    const int SMD = 2 * (128 * 144) + 2 * 18432;         // 73728
    cudaFuncSetAttribute(edge_mma_kernel<64, 64, 3, 2>,   cudaFuncAttributeMaxDynamicSharedMemorySize, SM1);
    cudaFuncSetAttribute(edge_mma_kernel<128, 128, 2, 1>, cudaFuncAttributeMaxDynamicSharedMemorySize, SM2);
    cudaFuncSetAttribute(edge_mma_kernel<256, 128, 2, 1>, cudaFuncAttributeMaxDynamicSharedMemorySize, SM2);
    cudaFuncSetAttribute(dense_mma_kernel<64,  128, false, 2>, cudaFuncAttributeMaxDynamicSharedMemorySize, SMD);
    cudaFuncSetAttribute(dense_mma_kernel<128, 128, false, 1>, cudaFuncAttributeMaxDynamicSharedMemorySize, SMD);
    cudaFuncSetAttribute(dense_mma_kernel<448, 128, true, 1>,  cudaFuncAttributeMaxDynamicSharedMemorySize, SMD);
    cudaFuncSetAttribute(dense_mma_kernel<512, 128, true, 1>,  cudaFuncAttributeMaxDynamicSharedMemorySize, SMD);

    const int TB = 256;
    dim3 blk(TB);
    const int gx   = (Nn + 127) / 128;
    const int gx2  = (Nn + 255) / 256;
    const int egx  = (E + 127) / 128;
    const int egx2 = (E + 255) / 256;

    // ---- one-shot weight prep + bin zeroing (before convert's hist) ----
    prep_all_kernel<<<(528384 + TB - 1) / TB, blk>>>(w1b, w2a, w2b, w3a, w3b, wm1, wm2);

    // ---- edge sort by dst (counting sort; segment-max is order-invariant) ----
    convert_idx_kernel<<<(E + TB - 1) / TB, blk>>>((const unsigned*)ei, E);
    scan_kernel<<<1, 1024>>>();

    // ---- fused scatter + layer-1 node precompute ----
    {
        int tot = (Nn * 128 > E) ? Nn * 128 : E;
        scatter_node1_kernel<<<(tot + TB - 1) / TB, blk>>>(x, w1a, b1a, AB, agg, Nn, E);
    }

    // ---- EdgeConv 1: 3 -> 64 ----
    edge_mma_kernel<64, 64, 3, 2><<<dim3(egx2, 1), blk, SM1>>>(AB, wh1, wl1, agg, E, 64);

    // ---- EdgeConv 2: 64 -> 128 ----
    decode_clear_kernel<<<(Nn * 128 + TB - 1) / TB, blk>>>(agg, b1b, hcat + 0, Nn * 64, 64, 448, Nn * 128);
    dense_mma_kernel<64, 128, false, 2><<<dim3(gx2, 2), blk, SMD>>>(hcat, 448, whn2, wln2, b2a, 128, AB, 256, Nn);
    edge_mma_kernel<128, 128, 2, 1><<<dim3(egx, 1), blk, SM2>>>(AB, wh2, wl2, agg, E, 128);

    // ---- EdgeConv 3: 128 -> 256 ----
    decode_clear_kernel<<<(Nn * 256 + TB - 1) / TB, blk>>>(agg, b2b, hcat + 64, Nn * 128, 128, 448, Nn * 256);
    dense_mma_kernel<128, 128, false, 1><<<dim3(gx, 4), blk, SMD>>>(hcat + 64, 448, whn3, wln3, b3a, 256, AB, 512, Nn);
    edge_mma_kernel<256, 128, 2, 1><<<dim3(egx, 2), blk, SM2>>>(AB, wh3, wl3, agg, E, 256);
    decode_clear_kernel<<<(Nn * 256 + TB - 1) / TB, blk>>>(agg, b3b, hcat + 192, Nn * 256, 256, 448, 0);

    // ---- MLP head ----
    dense_mma_kernel<448, 128, true, 1><<<dim3(gx, 4), blk, SMD>>>(hcat, 448, whm1, wlm1, bm1, 512, m1, 512, Nn);
    dense_mma_kernel<512, 128, true, 1><<<dim3(gx, 2), blk, SMD>>>(m1, 512, whm2, wlm2, bm2, 256, m2, 256, Nn);
    mlp3_kernel<<<(Nn * 32 + TB - 1) / TB, blk>>>(m2, wm3, bm3, out, Nn);
}

// round 17
// speedup vs baseline: 1.1015x; 1.0161x over previous
#include <cuda_runtime.h>
#include <cuda_bf16.h>
#include <cstdint>

// ---------------------------------------------------------------------------
// DGCNN segmentation. ALL GEMMs on tensor cores via mma.sync bf16x3 split
// precision (ldmatrix frags, cp.async.cg W streaming, 64-wide K chunks).
// Edges counting-sorted by dst. Bias applied after segment-max (exact).
// Launch-compressed; decode/clear passes vectorized 4-wide.
// ---------------------------------------------------------------------------

#define NMAX 30016
#define EMAX 480256
#define NBIN 30720   // 1024 * 30

__device__ float    g_AB[NMAX * 512];
__device__ unsigned g_agg[NMAX * 256];
__device__ float    g_hcat[NMAX * 448];
__device__ float    g_m1[NMAX * 512];
__device__ float    g_m2[NMAX * 256];
__device__ uint4    g_wh1[64 * 72 / 8],       g_wl1[64 * 72 / 8];
__device__ uint4    g_wh2[2 * 128 * 72 / 8],  g_wl2[2 * 128 * 72 / 8];
__device__ uint4    g_wh3[8 * 128 * 72 / 8],  g_wl3[8 * 128 * 72 / 8];
__device__ uint4    g_whn2[2304],  g_wln2[2304];
__device__ uint4    g_whn3[9216],  g_wln3[9216];
__device__ uint4    g_whm1[32256], g_wlm1[32256];
__device__ uint4    g_whm2[18432], g_wlm2[18432];
__device__ int      g_src[EMAX];
__device__ int      g_dst[EMAX];
__device__ int      g_srcS[EMAX];   // sorted by dst
__device__ int      g_dstS[EMAX];
__device__ int      g_cnt[NBIN];
__device__ int      g_c2[NBIN];
__device__ int      g_start[NBIN];

// ---- ordered-uint encoding for float max ------------------------------------
__device__ __forceinline__ unsigned f2ord(float f) {
    int i = __float_as_int(f);
    return (i >= 0) ? ((unsigned)i | 0x80000000u) : ~(unsigned)i;
}
__device__ __forceinline__ float ord2f(unsigned u) {
    int i = (u & 0x80000000u) ? (int)(u & 0x7fffffffu) : (int)(~u);
    return __int_as_float(i);
}

// ---- PTX helpers --------------------------------------------------------------
__device__ __forceinline__ uint32_t smem_u32(const void* p) {
    uint32_t a;
    asm("{ .reg .u64 t; cvta.to.shared.u64 t, %1; cvt.u32.u64 %0, t; }" : "=r"(a) : "l"(p));
    return a;
}
__device__ __forceinline__ void mma_bf16(float* d, const uint32_t* a,
                                         uint32_t b0, uint32_t b1) {
    asm volatile(
        "mma.sync.aligned.m16n8k16.row.col.f32.bf16.bf16.f32 "
        "{%0,%1,%2,%3},{%4,%5,%6,%7},{%8,%9},{%0,%1,%2,%3};"
        : "+f"(d[0]), "+f"(d[1]), "+f"(d[2]), "+f"(d[3])
        : "r"(a[0]), "r"(a[1]), "r"(a[2]), "r"(a[3]), "r"(b0), "r"(b1));
}
__device__ __forceinline__ void ldsm_x4(uint32_t* r, uint32_t addr) {
    asm volatile("ldmatrix.sync.aligned.m8n8.x4.shared.b16 {%0,%1,%2,%3},[%4];"
                 : "=r"(r[0]), "=r"(r[1]), "=r"(r[2]), "=r"(r[3]) : "r"(addr));
}
__device__ __forceinline__ void cp16(uint32_t s, const void* g) {
    asm volatile("cp.async.cg.shared.global [%0],[%1],16;" :: "r"(s), "l"(g));
}
__device__ __forceinline__ void split2(float m0, float m1, uint32_t& hi2, uint32_t& lo2) {
    asm("cvt.rn.bf16x2.f32 %0, %1, %2;" : "=r"(hi2) : "f"(m1), "f"(m0));
    float h0 = __uint_as_float(hi2 << 16);
    float h1 = __uint_as_float(hi2 & 0xffff0000u);
    float l0 = m0 - h0, l1 = m1 - h1;
    asm("cvt.rn.bf16x2.f32 %0, %1, %2;" : "=r"(lo2) : "f"(l1), "f"(l0));
}

// ---- weight conversion helpers -------------------------------------------------
__device__ __forceinline__ void store_wb(float val, int k, int n, int NCH, int BN,
                                         uint4* Whi, uint4* Wlo) {
    __nv_bfloat16 hb = __float2bfloat16(val);
    __nv_bfloat16 lb = __float2bfloat16(val - __bfloat162float(hb));
    int tile = n / BN, nl = n % BN, c = k >> 6, kl = k & 63;
    size_t off = ((size_t)(tile * NCH + c) * BN + nl) * 72 + kl;
    ((unsigned short*)Whi)[off] = __bfloat16_as_ushort(hb);
    ((unsigned short*)Wlo)[off] = __bfloat16_as_ushort(lb);
}
__device__ __forceinline__ void prep_std(const float* W, int idx, int COUT, int H,
                                         int BN, uint4* Whi, uint4* Wlo) {
    int k = idx / COUT, n = idx % COUT;
    store_wb(W[idx], k, n, H >> 6, BN, Whi, Wlo);
}
__device__ __forceinline__ void prep_node(const float* w, int idx, int C, int H,
                                          int BN, uint4* Whi, uint4* Wlo) {
    int COUT = 2 * H;
    int k = idx / COUT, n = idx % COUT;
    float val = (n < H) ? (w[k * H + n] - w[(k + C) * H + n])
                        : w[(k + C) * H + (n - H)];
    store_wb(val, k, n, C >> 6, BN, Whi, Wlo);
}

// ---- one-shot prep: all weight conversions + sort-bin zeroing ------------------
__global__ void prep_all_kernel(const float* __restrict__ w1b,
                                const float* __restrict__ w2a,
                                const float* __restrict__ w2b,
                                const float* __restrict__ w3a,
                                const float* __restrict__ w3b,
                                const float* __restrict__ wm1,
                                const float* __restrict__ wm2) {
    int i = blockIdx.x * blockDim.x + threadIdx.x;
    if (i < NBIN) { g_cnt[i] = 0; g_c2[i] = 0; }
    int j = i;
    if (j < 4096)            { prep_std (w1b, j, 64, 64, 64, g_wh1, g_wl1); return; }
    j -= 4096;
    if (j < 16384)           { prep_node(w2a, j, 64, 128, 128, g_whn2, g_wln2); return; }
    j -= 16384;
    if (j < 16384)           { prep_std (w2b, j, 128, 128, 128, g_wh2, g_wl2); return; }
    j -= 16384;
    if (j < 65536)           { prep_node(w3a, j, 128, 256, 128, g_whn3, g_wln3); return; }
    j -= 65536;
    if (j < 65536)           { prep_std (w3b, j, 256, 256, 128, g_wh3, g_wl3); return; }
    j -= 65536;
    if (j < 229376)          { prep_std (wm1, j, 512, 448, 128, g_whm1, g_wlm1); return; }
    j -= 229376;
    if (j < 131072)          { prep_std (wm2, j, 256, 512, 128, g_whm2, g_wlm2); return; }
}

// ---- edge index convert + histogram (bins pre-zeroed by prep_all) --------------
__global__ void convert_idx_kernel(const unsigned* __restrict__ raw, int E) {
    int n = (E < 256) ? E : 256;
    int is64 = 1;
    for (int i = 0; i < n; i++)
        if (raw[2 * i + 1] != 0u) { is64 = 0; break; }
    int i = blockIdx.x * blockDim.x + threadIdx.x;
    if (i >= E) return;
    int s, d;
    if (is64) {
        const long long* p = (const long long*)raw;
        s = (int)p[i]; d = (int)p[E + i];
    } else {
        const int* p = (const int*)raw;
        s = p[i]; d = p[E + i];
    }
    g_src[i] = s;
    g_dst[i] = d;
    atomicAdd(&g_cnt[d], 1);
}
__global__ void scan_kernel() {   // 1 block, 1024 threads, 30 bins each
    __shared__ int part[1024];
    int t = threadIdx.x;
    int base = t * 30;
    int s = 0;
#pragma unroll
    for (int j = 0; j < 30; j++) s += g_cnt[base + j];
    part[t] = s;
    __syncthreads();
    for (int off = 1; off < 1024; off <<= 1) {
        int v = (t >= off) ? part[t - off] : 0;
        __syncthreads();
        part[t] += v;
        __syncthreads();
    }
    int run = part[t] - s;
#pragma unroll
    for (int j = 0; j < 30; j++) {
        g_start[base + j] = run;
        run += g_cnt[base + j];
    }
}

// ---- fused scatter (edge reorder) + layer-1 node precompute + agg clear --------
__global__ void scatter_node1_kernel(const float* __restrict__ x,
                                     const float* __restrict__ w1a,
                                     const float* __restrict__ b1a,
                                     float* __restrict__ AB,
                                     unsigned* __restrict__ agg, int M, int E) {
    int idx = blockIdx.x * blockDim.x + threadIdx.x;
    if (idx < E) {
        int d = g_dst[idx];
        int pos = g_start[d] + atomicAdd(&g_c2[d], 1);
        g_srcS[pos] = g_src[idx];
        g_dstS[pos] = d;
    }
    if (idx >= M * 128) return;
    if (idx < M * 64) agg[idx] = 0u;
    int n = idx >> 7, j = idx & 127;
    float wk0, wk1, wk2, bb;
    if (j < 64) {
        wk0 = w1a[0 * 64 + j] - w1a[3 * 64 + j];
        wk1 = w1a[1 * 64 + j] - w1a[4 * 64 + j];
        wk2 = w1a[2 * 64 + j] - w1a[5 * 64 + j];
        bb  = b1a[j];
    } else {
        int jj = j - 64;
        wk0 = w1a[3 * 64 + jj];
        wk1 = w1a[4 * 64 + jj];
        wk2 = w1a[5 * 64 + jj];
        bb  = 0.f;
    }
    float x0 = x[n * 3 + 0], x1 = x[n * 3 + 1], x2 = x[n * 3 + 2];
    AB[idx] = fmaf(x0, wk0, fmaf(x1, wk1, fmaf(x2, wk2, bb)));
}

// ---- dense bf16x3 mma GEMM: C = act(A @ W + [bias|0]) --------------------------
template <int K, int BN, bool RELU, int MT>
__global__ void __launch_bounds__(256, 2)
dense_mma_kernel(const float* __restrict__ A, int lda,
                 const uint4* __restrict__ Whi_g, const uint4* __restrict__ Wlo_g,
                 const float* __restrict__ bias, int HB,
                 float* __restrict__ C, int ldc, int M) {
    constexpr int NCH = K / 64;
    static_assert(MT == 1 || NCH == 1, "MT>1 requires single-chunk K");
    constexpr int NA  = BN / 16;
    constexpr int WSZ = BN * 144;
    constexpr int ASZ = 128 * 144;
    constexpr int OA  = 2 * WSZ;
    constexpr int WCNT = BN * 9;

    extern __shared__ char sm[];
    const uint32_t smb = smem_u32(sm);

    const int tid = threadIdx.x;
    const int wid = tid >> 5, lane = tid & 31;
    const int g = lane >> 2, tig = lane & 3;
    const int bmb = blockIdx.x * (128 * MT);
    const int bn = blockIdx.y * BN;

    const int r  = tid >> 1;
    const int hf = tid & 1;

    const int wm = wid >> 1, wn = wid & 1;
    const int m0 = wm * 32, n0 = wn * (BN / 2);

    const int lr = lane & 7;
    const uint32_t a_off =
        (uint32_t)(m0 + lr + ((lane >> 3) & 1) * 8) * 144u + (uint32_t)(lane >> 4) * 16u;
    const uint32_t w_off =
        (uint32_t)(n0 + lr + ((lane >> 4) & 1) * 8) * 144u + (uint32_t)((lane >> 3) & 1) * 16u;

    const uint32_t WhU = smb;
    const uint32_t WlU = WhU + WSZ;
    const uint32_t AhU = smb + OA;
    const uint32_t AlU = AhU + ASZ;
    char* Ah = sm + OA;
    char* Al = sm + OA + ASZ;

    for (int mt = 0; mt < MT; mt++) {
        const int bm = bmb + mt * 128;
        const bool rv = (bm + r) < M;
        const float* Arow = A + (size_t)(bm + r) * lda + hf * 32;

        float acc[2][NA][4];
#pragma unroll
        for (int ma = 0; ma < 2; ma++)
#pragma unroll
            for (int na = 0; na < NA; na++)
#pragma unroll
                for (int q = 0; q < 4; q++) acc[ma][na][q] = 0.f;

        for (int c = 0; c < NCH; c++) {
            if (c || mt) __syncthreads();
            if (mt == 0) {
                const char* shp = (const char*)(Whi_g + (size_t)(blockIdx.y * NCH + c) * WCNT);
                const char* slp = (const char*)(Wlo_g + (size_t)(blockIdx.y * NCH + c) * WCNT);
                for (int i = tid; i < WCNT; i += 256) {
                    cp16(WhU + i * 16, shp + i * 16);
                    cp16(WlU + i * 16, slp + i * 16);
                }
                asm volatile("cp.async.commit_group;" ::: "memory");
            }
            {
                const float4* Ap = (const float4*)(Arow + c * 64);
                float v[32];
                if (rv) {
#pragma unroll
                    for (int q = 0; q < 8; q++) {
                        float4 a = Ap[q];
                        v[q * 4 + 0] = a.x; v[q * 4 + 1] = a.y;
                        v[q * 4 + 2] = a.z; v[q * 4 + 3] = a.w;
                    }
                } else {
#pragma unroll
                    for (int q = 0; q < 32; q++) v[q] = 0.f;
                }
                char* ah = Ah + r * 144 + hf * 64;
                char* al = Al + r * 144 + hf * 64;
#pragma unroll
                for (int q8 = 0; q8 < 4; q8++) {
                    uint32_t uh[4], ul[4];
#pragma unroll
                    for (int p = 0; p < 4; p++)
                        split2(v[q8 * 8 + p * 2], v[q8 * 8 + p * 2 + 1], uh[p], ul[p]);
                    *(uint4*)(ah + q8 * 16) = make_uint4(uh[0], uh[1], uh[2], uh[3]);
                    *(uint4*)(al + q8 * 16) = make_uint4(ul[0], ul[1], ul[2], ul[3]);
                }
            }
            asm volatile("cp.async.wait_group 0;" ::: "memory");
            __syncthreads();

#pragma unroll
            for (int kq = 0; kq < 4; kq++) {
                uint32_t ah[2][4], al[2][4];
#pragma unroll
                for (int ma = 0; ma < 2; ma++) {
                    ldsm_x4(ah[ma], AhU + a_off + (uint32_t)(ma * 16 * 144 + kq * 32));
                    ldsm_x4(al[ma], AlU + a_off + (uint32_t)(ma * 16 * 144 + kq * 32));
                }
#pragma unroll
                for (int n2 = 0; n2 < NA / 2; n2++) {
                    uint32_t wh[4], wl[4];
                    ldsm_x4(wh, WhU + w_off + (uint32_t)(n2 * 16 * 144 + kq * 32));
                    ldsm_x4(wl, WlU + w_off + (uint32_t)(n2 * 16 * 144 + kq * 32));
#pragma unroll
                    for (int j = 0; j < 2; j++) {
                        const int na = n2 * 2 + j;
                        mma_bf16(acc[0][na], ah[0], wh[2 * j], wh[2 * j + 1]);
                        mma_bf16(acc[1][na], ah[1], wh[2 * j], wh[2 * j + 1]);
                        mma_bf16(acc[0][na], al[0], wh[2 * j], wh[2 * j + 1]);
                        mma_bf16(acc[1][na], al[1], wh[2 * j], wh[2 * j + 1]);
                        mma_bf16(acc[0][na], ah[0], wl[2 * j], wl[2 * j + 1]);
                        mma_bf16(acc[1][na], ah[1], wl[2 * j], wl[2 * j + 1]);
                    }
                }
            }
        }

#pragma unroll
        for (int ma = 0; ma < 2; ma++) {
#pragma unroll
            for (int rr = 0; rr < 2; rr++) {
                const int rg = bm + m0 + ma * 16 + g + rr * 8;
                if (rg >= M) continue;
                float* crow = C + (size_t)rg * ldc + bn;
#pragma unroll
                for (int na = 0; na < NA; na++) {
                    const int j = n0 + na * 8 + 2 * tig;
                    float b0 = (bn + j     < HB) ? bias[bn + j]     : 0.f;
                    float b1 = (bn + j + 1 < HB) ? bias[bn + j + 1] : 0.f;
                    float v0 = acc[ma][na][rr * 2 + 0] + b0;
                    float v1 = acc[ma][na][rr * 2 + 1] + b1;
                    if (RELU) { v0 = fmaxf(v0, 0.f); v1 = fmaxf(v1, 0.f); }
                    *(float2*)(crow + j) = make_float2(v0, v1);
                }
            }
        }
    }
}

// ---- mma.sync edge kernel: sorted edges, MT m-tiles, bias post-max ------------
template <int H, int BN, int MINB, int MT>
__global__ void __launch_bounds__(256, MINB)
edge_mma_kernel(const float* __restrict__ AB,
                const uint4* __restrict__ Whi_g, const uint4* __restrict__ Wlo_g,
                unsigned* __restrict__ agg, int E, int COUT) {
    constexpr int NCH = H / 64;
    static_assert(MT == 1 || NCH == 1, "MT>1 requires single-chunk K");
    constexpr int NA  = BN / 16;
    constexpr int WSZ = BN * 144;
    constexpr int ASZ = 128 * 144;
    constexpr int OW  = 2048;
    constexpr int OA  = OW + 2 * WSZ;
    constexpr int WCNT = BN * 9;

    extern __shared__ char sm[];
    const uint32_t smb = smem_u32(sm);
    int* sdst = (int*)sm;            // MT*128 ints
    int* ssrc = (int*)(sm + 1024);   // MT*128 ints

    const int tid = threadIdx.x;
    const int wid = tid >> 5, lane = tid & 31;
    const int g = lane >> 2, tig = lane & 3;
    const int e0b = blockIdx.x * (128 * MT);
    const int bn = blockIdx.y * BN;

    for (int i = tid; i < 128 * MT; i += 256) {
        int e = e0b + i;
        ssrc[i] = (e < E) ? g_srcS[e] : 0;
        sdst[i] = (e < E) ? g_dstS[e] : 0;
    }
    __syncthreads();

    const int r  = tid >> 1;
    const int hf = tid & 1;

    const int wm = wid >> 1, wn = wid & 1;
    const int m0 = wm * 32, n0 = wn * (BN / 2);

    const int lr = lane & 7;
    const uint32_t a_off =
        (uint32_t)(m0 + lr + ((lane >> 3) & 1) * 8) * 144u + (uint32_t)(lane >> 4) * 16u;
    const uint32_t w_off =
        (uint32_t)(n0 + lr + ((lane >> 4) & 1) * 8) * 144u + (uint32_t)((lane >> 3) & 1) * 16u;

    const uint32_t WhU = smb + OW;
    const uint32_t WlU = WhU + WSZ;
    const uint32_t AhU = smb + OA;
    const uint32_t AlU = AhU + ASZ;
    char* Ah = sm + OA;
    char* Al = sm + OA + ASZ;

    for (int mt = 0; mt < MT; mt++) {
        const int rb = mt * 128;
        const float* Arow = AB + (size_t)sdst[rb + r] * (2 * H) + hf * 32;
        const float* Brow = AB + (size_t)ssrc[rb + r] * (2 * H) + H + hf * 32;

        float acc[2][NA][4];
#pragma unroll
        for (int ma = 0; ma < 2; ma++)
#pragma unroll
            for (int na = 0; na < NA; na++)
#pragma unroll
                for (int q = 0; q < 4; q++) acc[ma][na][q] = 0.f;

        float4 pre[4];
#pragma unroll
        for (int q = 0; q < 4; q++) pre[q] = ((const float4*)Brow)[q];

        for (int c = 0; c < NCH; c++) {
            if (c || mt) __syncthreads();
            if (mt == 0) {
                const char* shp = (const char*)(Whi_g + (size_t)(blockIdx.y * NCH + c) * WCNT);
                const char* slp = (const char*)(Wlo_g + (size_t)(blockIdx.y * NCH + c) * WCNT);
                for (int i = tid; i < WCNT; i += 256) {
                    cp16(WhU + i * 16, shp + i * 16);
                    cp16(WlU + i * 16, slp + i * 16);
                }
                asm volatile("cp.async.commit_group;" ::: "memory");
            }
            {
                const float4* Ap = (const float4*)(Arow + c * 64);
                const float4* Bp = (const float4*)(Brow + c * 64);
                float v[32];
#pragma unroll
                for (int q = 0; q < 4; q++) {
                    float4 a = Ap[q], b = pre[q];
                    v[q * 4 + 0] = fmaxf(a.x + b.x, 0.f);
                    v[q * 4 + 1] = fmaxf(a.y + b.y, 0.f);
                    v[q * 4 + 2] = fmaxf(a.z + b.z, 0.f);
                    v[q * 4 + 3] = fmaxf(a.w + b.w, 0.f);
                }
#pragma unroll
                for (int q = 4; q < 8; q++) {
                    float4 a = Ap[q], b = Bp[q];
                    v[q * 4 + 0] = fmaxf(a.x + b.x, 0.f);
                    v[q * 4 + 1] = fmaxf(a.y + b.y, 0.f);
                    v[q * 4 + 2] = fmaxf(a.z + b.z, 0.f);
                    v[q * 4 + 3] = fmaxf(a.w + b.w, 0.f);
                }
                if (c + 1 < NCH) {
                    const float4* Bn = (const float4*)(Brow + (c + 1) * 64);
#pragma unroll
                    for (int q = 0; q < 4; q++) pre[q] = Bn[q];
                }
                char* ah = Ah + r * 144 + hf * 64;
                char* al = Al + r * 144 + hf * 64;
#pragma unroll
                for (int q8 = 0; q8 < 4; q8++) {
                    uint32_t uh[4], ul[4];
#pragma unroll
                    for (int p = 0; p < 4; p++)
                        split2(v[q8 * 8 + p * 2], v[q8 * 8 + p * 2 + 1], uh[p], ul[p]);
                    *(uint4*)(ah + q8 * 16) = make_uint4(uh[0], uh[1], uh[2], uh[3]);
                    *(uint4*)(al + q8 * 16) = make_uint4(ul[0], ul[1], ul[2], ul[3]);
                }
            }
            asm volatile("cp.async.wait_group 0;" ::: "memory");
            __syncthreads();

#pragma unroll
            for (int kq = 0; kq < 4; kq++) {
                uint32_t ah[2][4], al[2][4];
#pragma unroll
                for (int ma = 0; ma < 2; ma++) {
                    ldsm_x4(ah[ma], AhU + a_off + (uint32_t)(ma * 16 * 144 + kq * 32));
                    ldsm_x4(al[ma], AlU + a_off + (uint32_t)(ma * 16 * 144 + kq * 32));
                }
#pragma unroll
                for (int n2 = 0; n2 < NA / 2; n2++) {
                    uint32_t wh[4], wl[4];
                    ldsm_x4(wh, WhU + w_off + (uint32_t)(n2 * 16 * 144 + kq * 32));
                    ldsm_x4(wl, WlU + w_off + (uint32_t)(n2 * 16 * 144 + kq * 32));
#pragma unroll
                    for (int j = 0; j < 2; j++) {
                        const int na = n2 * 2 + j;
                        mma_bf16(acc[0][na], ah[0], wh[2 * j], wh[2 * j + 1]);
                        mma_bf16(acc[1][na], ah[1], wh[2 * j], wh[2 * j + 1]);
                        mma_bf16(acc[0][na], al[0], wh[2 * j], wh[2 * j + 1]);
                        mma_bf16(acc[1][na], al[1], wh[2 * j], wh[2 * j + 1]);
                        mma_bf16(acc[0][na], ah[0], wl[2 * j], wl[2 * j + 1]);
                        mma_bf16(acc[1][na], ah[1], wl[2 * j], wl[2 * j + 1]);
                    }
                }
            }
        }

#pragma unroll
        for (int ma = 0; ma < 2; ma++) {
#pragma unroll
            for (int rr = 0; rr < 2; rr++) {
                const int rloc = m0 + ma * 16 + g + rr * 8;
                if (e0b + rb + rloc >= E) continue;
                const int d = sdst[rb + rloc];
                unsigned* arow = agg + (size_t)d * COUT + bn;
#pragma unroll
                for (int na = 0; na < NA; na++) {
                    const int j = n0 + na * 8 + 2 * tig;
                    unsigned k0 = f2ord(acc[ma][na][rr * 2 + 0]);
                    unsigned k1 = f2ord(acc[ma][na][rr * 2 + 1]);
                    uint2 cur = *(const uint2*)(arow + j);
                    if (k0 > cur.x) atomicMax(arow + j, k0);
                    if (k1 > cur.y) atomicMax(arow + j + 1, k1);
                }
            }
        }
    }
}

// ---- decode agg (+bias post-max) -> float + clear, 4-wide vectorized -----------
// total, clrN, C multiples of 4; hcat row bases 16B-aligned (ldc=448, off 0/64/192).
__global__ void decode_clear_kernel(unsigned* __restrict__ agg,
                                    const float* __restrict__ bias,
                                    float* __restrict__ dsth, int total, int C, int ldc,
                                    int clrN) {
    int i = (blockIdx.x * blockDim.x + threadIdx.x) * 4;
    if (i < total) {
        int n = i / C, c = i % C;
        uint4 u = *(const uint4*)(agg + i);
        float4 o;
        o.x = (u.x == 0u) ? 0.f : (ord2f(u.x) + bias[c + 0]);
        o.y = (u.y == 0u) ? 0.f : (ord2f(u.y) + bias[c + 1]);
        o.z = (u.z == 0u) ? 0.f : (ord2f(u.z) + bias[c + 2]);
        o.w = (u.w == 0u) ? 0.f : (ord2f(u.w) + bias[c + 3]);
        *(float4*)(dsth + (size_t)n * ldc + c) = o;
    }
    if (i < clrN) *(uint4*)(agg + i) = make_uint4(0u, 0u, 0u, 0u);
}

// ---- final 256 -> 4 linear ------------------------------------------------------
__global__ void mlp3_kernel(const float* __restrict__ A, const float* __restrict__ W,
                            const float* __restrict__ b, float* __restrict__ out, int M) {
    int gw = (blockIdx.x * blockDim.x + threadIdx.x) >> 5;
    int lane = threadIdx.x & 31;
    if (gw >= M) return;
    const float* a = A + (size_t)gw * 256;
    float acc0 = 0.f, acc1 = 0.f, acc2 = 0.f, acc3 = 0.f;
    for (int k = lane; k < 256; k += 32) {
        float av = a[k];
        const float* wr = W + k * 4;
        acc0 = fmaf(av, wr[0], acc0);
        acc1 = fmaf(av, wr[1], acc1);
        acc2 = fmaf(av, wr[2], acc2);
        acc3 = fmaf(av, wr[3], acc3);
    }
#pragma unroll
    for (int off = 16; off > 0; off >>= 1) {
        acc0 += __shfl_down_sync(0xffffffffu, acc0, off);
        acc1 += __shfl_down_sync(0xffffffffu, acc1, off);
        acc2 += __shfl_down_sync(0xffffffffu, acc2, off);
        acc3 += __shfl_down_sync(0xffffffffu, acc3, off);
    }
    if (lane == 0) {
        out[gw * 4 + 0] = acc0 + b[0];
        out[gw * 4 + 1] = acc1 + b[1];
        out[gw * 4 + 2] = acc2 + b[2];
        out[gw * 4 + 3] = acc3 + b[3];
    }
}

// ---------------------------------------------------------------------------
extern "C" void kernel_launch(void* const* d_in, const int* in_sizes, int n_in,
                              void* d_out, int out_size) {
    const float* x   = (const float*)d_in[0];
    const void*  ei  = d_in[1];
    const float* w1a = (const float*)d_in[3];
    const float* b1a = (const float*)d_in[4];
    const float* w1b = (const float*)d_in[5];
    const float* b1b = (const float*)d_in[6];
    const float* w2a = (const float*)d_in[7];
    const float* b2a = (const float*)d_in[8];
    const float* w2b = (const float*)d_in[9];
    const float* b2b = (const float*)d_in[10];
    const float* w3a = (const float*)d_in[11];
    const float* b3a = (const float*)d_in[12];
    const float* w3b = (const float*)d_in[13];
    const float* b3b = (const float*)d_in[14];
    const float* wm1 = (const float*)d_in[15];
    const float* bm1 = (const float*)d_in[16];
    const float* wm2 = (const float*)d_in[17];
    const float* bm2 = (const float*)d_in[18];
    const float* wm3 = (const float*)d_in[19];
    const float* bm3 = (const float*)d_in[20];

    const int Nn = in_sizes[0] / 3;
    const int E  = in_sizes[1] / 2;
    float* out = (float*)d_out;

    float *AB, *hcat, *m1, *m2;
    unsigned* agg;
    uint4 *wh1, *wl1, *wh2, *wl2, *wh3, *wl3;
    uint4 *whn2, *wln2, *whn3, *wln3, *whm1, *wlm1, *whm2, *wlm2;
    cudaGetSymbolAddress((void**)&AB,   g_AB);
    cudaGetSymbolAddress((void**)&agg,  g_agg);
    cudaGetSymbolAddress((void**)&hcat, g_hcat);
    cudaGetSymbolAddress((void**)&m1,   g_m1);
    cudaGetSymbolAddress((void**)&m2,   g_m2);
    cudaGetSymbolAddress((void**)&wh1,  g_wh1);
    cudaGetSymbolAddress((void**)&wl1,  g_wl1);
    cudaGetSymbolAddress((void**)&wh2,  g_wh2);
    cudaGetSymbolAddress((void**)&wl2,  g_wl2);
    cudaGetSymbolAddress((void**)&wh3,  g_wh3);
    cudaGetSymbolAddress((void**)&wl3,  g_wl3);
    cudaGetSymbolAddress((void**)&whn2, g_whn2);
    cudaGetSymbolAddress((void**)&wln2, g_wln2);
    cudaGetSymbolAddress((void**)&whn3, g_whn3);
    cudaGetSymbolAddress((void**)&wln3, g_wln3);
    cudaGetSymbolAddress((void**)&whm1, g_whm1);
    cudaGetSymbolAddress((void**)&wlm1, g_wlm1);
    cudaGetSymbolAddress((void**)&whm2, g_whm2);
    cudaGetSymbolAddress((void**)&wlm2, g_wlm2);

    const int SM1 = 2048 + 2 * (64  * 144) + 2 * 18432;  // 57344
    const int SM2 = 2048 + 2 * (128 * 144) + 2 * 18432;  // 75776
    const int SMD = 2 * (128 * 144) + 2 * 18432;         // 73728
    cudaFuncSetAttribute(edge_mma_kernel<64, 64, 3, 2>,   cudaFuncAttributeMaxDynamicSharedMemorySize, SM1);
    cudaFuncSetAttribute(edge_mma_kernel<128, 128, 2, 1>, cudaFuncAttributeMaxDynamicSharedMemorySize, SM2);
    cudaFuncSetAttribute(edge_mma_kernel<256, 128, 2, 1>, cudaFuncAttributeMaxDynamicSharedMemorySize, SM2);
    cudaFuncSetAttribute(dense_mma_kernel<64,  128, false, 2>, cudaFuncAttributeMaxDynamicSharedMemorySize, SMD);
    cudaFuncSetAttribute(dense_mma_kernel<128, 128, false, 1>, cudaFuncAttributeMaxDynamicSharedMemorySize, SMD);
    cudaFuncSetAttribute(dense_mma_kernel<448, 128, true, 1>,  cudaFuncAttributeMaxDynamicSharedMemorySize, SMD);
    cudaFuncSetAttribute(dense_mma_kernel<512, 128, true, 1>,  cudaFuncAttributeMaxDynamicSharedMemorySize, SMD);

    const int TB = 256;
    dim3 blk(TB);
    const int gx   = (Nn + 127) / 128;
    const int gx2  = (Nn + 255) / 256;
    const int egx  = (E + 127) / 128;
    const int egx2 = (E + 255) / 256;

    // ---- one-shot weight prep + bin zeroing (before convert's hist) ----
    prep_all_kernel<<<(528384 + TB - 1) / TB, blk>>>(w1b, w2a, w2b, w3a, w3b, wm1, wm2);

    // ---- edge sort by dst (counting sort; segment-max is order-invariant) ----
    convert_idx_kernel<<<(E + TB - 1) / TB, blk>>>((const unsigned*)ei, E);
    scan_kernel<<<1, 1024>>>();

    // ---- fused scatter + layer-1 node precompute ----
    {
        int tot = (Nn * 128 > E) ? Nn * 128 : E;
        scatter_node1_kernel<<<(tot + TB - 1) / TB, blk>>>(x, w1a, b1a, AB, agg, Nn, E);
    }

    // ---- EdgeConv 1: 3 -> 64 ----
    edge_mma_kernel<64, 64, 3, 2><<<dim3(egx2, 1), blk, SM1>>>(AB, wh1, wl1, agg, E, 64);

    // ---- EdgeConv 2: 64 -> 128 ----
    decode_clear_kernel<<<(Nn * 128 / 4 + TB - 1) / TB, blk>>>(agg, b1b, hcat + 0, Nn * 64, 64, 448, Nn * 128);
    dense_mma_kernel<64, 128, false, 2><<<dim3(gx2, 2), blk, SMD>>>(hcat, 448, whn2, wln2, b2a, 128, AB, 256, Nn);
    edge_mma_kernel<128, 128, 2, 1><<<dim3(egx, 1), blk, SM2>>>(AB, wh2, wl2, agg, E, 128);

    // ---- EdgeConv 3: 128 -> 256 ----
    decode_clear_kernel<<<(Nn * 256 / 4 + TB - 1) / TB, blk>>>(agg, b2b, hcat + 64, Nn * 128, 128, 448, Nn * 256);
    dense_mma_kernel<128, 128, false, 1><<<dim3(gx, 4), blk, SMD>>>(hcat + 64, 448, whn3, wln3, b3a, 256, AB, 512, Nn);
    edge_mma_kernel<256, 128, 2, 1><<<dim3(egx, 2), blk, SM2>>>(AB, wh3, wl3, agg, E, 256);
    decode_clear_kernel<<<(Nn * 256 / 4 + TB - 1) / TB, blk>>>(agg, b3b, hcat + 192, Nn * 256, 256, 448, 0);

    // ---- MLP head ----
    dense_mma_kernel<448, 128, true, 1><<<dim3(gx, 4), blk, SMD>>>(hcat, 448, whm1, wlm1, bm1, 512, m1, 512, Nn);
    dense_mma_kernel<512, 128, true, 1><<<dim3(gx, 2), blk, SMD>>>(m1, 512, whm2, wlm2, bm2, 256, m2, 256, Nn);
    mlp3_kernel<<<(Nn * 32 + TB - 1) / TB, blk>>>(m2, wm3, bm3, out, Nn);
}